// round 3
// baseline (speedup 1.0000x reference)
#include <cuda_runtime.h>
#include <cstdint>

#define NGG 6
#define NN 6000
#define EE 96000
#define CC 128
#define NGI 24      // NGG * 4 layers
#define NPAIR 21
#define SP 132      // padded row stride for sim tiles

// ---------------- device scratch (no allocations allowed) ----------------
__device__ float g_deg[NGI * NN];                       // deg -> dis (in place)
__device__ float g_H[(size_t)NGI * NN * CC];            // x @ W per (graph,layer)
__device__ float g_O[(size_t)NGI * NN * CC];            // scattered GCN output
__device__ float g_feats[(size_t)NGG * NN * CC];        // acc per graph
__device__ float g_xn[(size_t)NGG * NN * CC];           // normalized feats
__device__ unsigned int g_cnt[NPAIR];

__constant__ int cP1[NPAIR] = {0,0,0,0,0,0, 1,1,1,1,1, 2,2,2,2, 3,3,3, 4,4, 5};
__constant__ int cP2[NPAIR] = {0,1,2,3,4,5, 1,2,3,4,5, 2,3,4,5, 3,4,5, 4,5, 5};

// ---------------- setup ----------------
__global__ void k_init() {
    int i = blockIdx.x * blockDim.x + threadIdx.x;
    if (i < NGI * NN) g_deg[i] = 1.0f;     // self-loop weight
    if (i < NPAIR) g_cnt[i] = 0u;
}

__global__ void k_deg(const int* __restrict__ ei, const float* __restrict__ ea) {
    int i = blockIdx.x * blockDim.x + threadIdx.x;
    if (i >= NGG * EE) return;
    int g = i / EE, e = i - g * EE;
    int c = ei[(size_t)g * 2 * EE + EE + e];
    const float* w = ea + ((size_t)g * EE + e) * 6;
#pragma unroll
    for (int l = 0; l < 4; l++)
        atomicAdd(&g_deg[(g * 4 + l) * NN + c], w[2 + l]);
}

__global__ void k_dis() {
    int i = blockIdx.x * blockDim.x + threadIdx.x;
    if (i < NGI * NN) g_deg[i] = rsqrtf(g_deg[i]);   // deg >= 1 always
}

// ---------------- H[gi] = x[g] @ gcn_W[layer]  (M=6000, N=128, K=128) ----------
__global__ void __launch_bounds__(256) k_gemm_h(const float* __restrict__ x,
                                                const float* __restrict__ gW) {
    __shared__ float sA[64 * 32];
    __shared__ float sB[32 * 128];
    int gi = blockIdx.y, g = gi >> 2, l = gi & 3;
    int row0 = blockIdx.x * 64;
    int tx = threadIdx.x, ty = threadIdx.y;
    int tid = ty * 32 + tx;
    const float4* Av = (const float4*)(x + (size_t)g * NN * CC);
    const float4* Bv = (const float4*)(gW + (size_t)l * CC * CC);
    float acc[8][4];
#pragma unroll
    for (int j = 0; j < 8; j++) { acc[j][0]=0;acc[j][1]=0;acc[j][2]=0;acc[j][3]=0; }
    for (int kc = 0; kc < 4; kc++) {
        __syncthreads();
#pragma unroll
        for (int it = 0; it < 4; it++)
            ((float4*)sB)[it * 256 + tid] = Bv[kc * 1024 + it * 256 + tid];
#pragma unroll
        for (int it = 0; it < 2; it++) {
            int idx = it * 256 + tid;
            int m = idx >> 3, kq = idx & 7;
            int gm = row0 + m;
            float4 v = make_float4(0.f, 0.f, 0.f, 0.f);
            if (gm < NN) v = Av[(size_t)gm * 32 + kc * 8 + kq];
            ((float4*)sA)[idx] = v;
        }
        __syncthreads();
#pragma unroll
        for (int k = 0; k < 32; k++) {
            float4 b = ((float4*)sB)[k * 32 + tx];
#pragma unroll
            for (int j = 0; j < 8; j++) {
                float a = sA[(ty * 8 + j) * 32 + k];
                acc[j][0] += a * b.x; acc[j][1] += a * b.y;
                acc[j][2] += a * b.z; acc[j][3] += a * b.w;
            }
        }
    }
#pragma unroll
    for (int j = 0; j < 8; j++) {
        int gm = row0 + ty * 8 + j;
        if (gm < NN)
            ((float4*)(g_H + ((size_t)gi * NN + gm) * CC))[tx] =
                make_float4(acc[j][0], acc[j][1], acc[j][2], acc[j][3]);
    }
}

// ---------------- O init with self-loop:  O = dis^2 * H ----------------
__global__ void k_initO() {
    size_t i = (size_t)blockIdx.x * 256 + threadIdx.x;   // float4 index
    if (i >= (size_t)NGI * NN * 32) return;
    int rowid = (int)(i >> 5);
    int gi = rowid / NN, node = rowid - gi * NN;
    float d = g_deg[gi * NN + node];
    float s = d * d;
    float4 h = ((const float4*)g_H)[i];
    ((float4*)g_O)[i] = make_float4(h.x * s, h.y * s, h.z * s, h.w * s);
}

// ---------------- edge scatter: O[c] += dis[r]*w*dis[c] * H[r] ----------------
__global__ void k_scatter(const int* __restrict__ ei, const float* __restrict__ ea) {
    int w = (blockIdx.x * 256 + threadIdx.x) >> 5;
    int lane = threadIdx.x & 31;
    if (w >= NGG * EE) return;
    int g = w / EE, e = w - g * EE;
    int r = ei[(size_t)g * 2 * EE + e];
    int c = ei[(size_t)g * 2 * EE + EE + e];
    const float* wp = ea + ((size_t)g * EE + e) * 6;
#pragma unroll
    for (int l = 0; l < 4; l++) {
        int gi = g * 4 + l;
        float nrm = g_deg[gi * NN + r] * wp[2 + l] * g_deg[gi * NN + c];
        float4 h = ((const float4*)(g_H + ((size_t)gi * NN + r) * CC))[lane];
        float* o = g_O + ((size_t)gi * NN + c) * CC + lane * 4;
        atomicAdd(o + 0, h.x * nrm);
        atomicAdd(o + 1, h.y * nrm);
        atomicAdd(o + 2, h.z * nrm);
        atomicAdd(o + 3, h.w * nrm);
    }
}

// ---------------- feats[g] = sum_l relu(O[g,l]+b[l]) @ Ws[l] ----------------
__global__ void __launch_bounds__(256) k_feats(const float* __restrict__ Wsm,
                                               const float* __restrict__ gb) {
    __shared__ float sA[64 * 32];
    __shared__ float sB[32 * 128];
    int g = blockIdx.y;
    int row0 = blockIdx.x * 64;
    int tx = threadIdx.x, ty = threadIdx.y;
    int tid = ty * 32 + tx;
    float acc[8][4];
#pragma unroll
    for (int j = 0; j < 8; j++) { acc[j][0]=0;acc[j][1]=0;acc[j][2]=0;acc[j][3]=0; }
    for (int l = 0; l < 4; l++) {
        const float4* Bv = (const float4*)(Wsm + (size_t)l * CC * CC);
        const float4* bb = (const float4*)(gb + l * CC);
        const float4* Ov = (const float4*)(g_O + (size_t)(g * 4 + l) * NN * CC);
        for (int kc = 0; kc < 4; kc++) {
            __syncthreads();
#pragma unroll
            for (int it = 0; it < 4; it++)
                ((float4*)sB)[it * 256 + tid] = Bv[kc * 1024 + it * 256 + tid];
#pragma unroll
            for (int it = 0; it < 2; it++) {
                int idx = it * 256 + tid;
                int m = idx >> 3, kq = idx & 7;
                int gm = row0 + m;
                float4 v = make_float4(0.f, 0.f, 0.f, 0.f);
                if (gm < NN) {
                    float4 o = Ov[(size_t)gm * 32 + kc * 8 + kq];
                    float4 b = bb[kc * 8 + kq];
                    v = make_float4(fmaxf(o.x + b.x, 0.f), fmaxf(o.y + b.y, 0.f),
                                    fmaxf(o.z + b.z, 0.f), fmaxf(o.w + b.w, 0.f));
                }
                ((float4*)sA)[idx] = v;
            }
            __syncthreads();
#pragma unroll
            for (int k = 0; k < 32; k++) {
                float4 b = ((float4*)sB)[k * 32 + tx];
#pragma unroll
                for (int j = 0; j < 8; j++) {
                    float a = sA[(ty * 8 + j) * 32 + k];
                    acc[j][0] += a * b.x; acc[j][1] += a * b.y;
                    acc[j][2] += a * b.z; acc[j][3] += a * b.w;
                }
            }
        }
    }
#pragma unroll
    for (int j = 0; j < 8; j++) {
        int gm = row0 + ty * 8 + j;
        if (gm < NN)
            ((float4*)(g_feats + ((size_t)g * NN + gm) * CC))[tx] =
                make_float4(acc[j][0], acc[j][1], acc[j][2], acc[j][3]);
    }
}

// ---------------- g_matrix: per-graph per-channel mean ----------------
__global__ void k_gmatrix(float* __restrict__ out) {
    int g = blockIdx.x, c = threadIdx.x;   // 128 threads
    const float* p = g_feats + (size_t)g * NN * CC + c;
    float s0 = 0.f, s1 = 0.f, s2 = 0.f, s3 = 0.f;
    for (int n = 0; n < NN; n += 4) {
        s0 += p[(size_t)(n + 0) * CC];
        s1 += p[(size_t)(n + 1) * CC];
        s2 += p[(size_t)(n + 2) * CC];
        s3 += p[(size_t)(n + 3) * CC];
    }
    out[g * CC + c] = (s0 + s1 + s2 + s3) / (float)NN;
}

// ---------------- row L2 normalize ----------------
__global__ void k_norm() {
    int w = (blockIdx.x * 256 + threadIdx.x) >> 5;
    int lane = threadIdx.x & 31;
    if (w >= NGG * NN) return;
    float4 v = ((const float4*)g_feats)[(size_t)w * 32 + lane];
    float ss = v.x * v.x + v.y * v.y + v.z * v.z + v.w * v.w;
#pragma unroll
    for (int o = 16; o; o >>= 1) ss += __shfl_xor_sync(0xffffffffu, ss, o);
    float inv = 1.0f / fmaxf(sqrtf(ss), 1e-12f);
    ((float4*)g_xn)[(size_t)w * 32 + lane] =
        make_float4(v.x * inv, v.y * inv, v.z * inv, v.w * inv);
}

// ---------------- sim: counts of (dot >= atanh(boundary)) per pair -------------
// value = -0.8 + 0.1 * count / N^2, where count sums over 16 interior
// thresholds atanh(k/10.5 - 1), k = 3..18 (k<=2 always true, k>=19 never).
__global__ void __launch_bounds__(256) k_sim() {
    __shared__ float sA[32 * SP];   // [k][m], k-chunk of 32, padded stride
    __shared__ float sB[32 * SP];
    int p = blockIdx.z;
    const float* A = g_xn + (size_t)cP1[p] * NN * CC;
    const float* B = g_xn + (size_t)cP2[p] * NN * CC;
    int row0 = blockIdx.x * 128, col0 = blockIdx.y * 128;
    int tid = threadIdx.x;
    int tx = tid & 15, ty = tid >> 4;

    float acc[8][8];
#pragma unroll
    for (int i = 0; i < 8; i++)
#pragma unroll
        for (int j = 0; j < 8; j++) acc[i][j] = 0.f;

    for (int kc = 0; kc < 4; kc++) {
        __syncthreads();
#pragma unroll
        for (int it = 0; it < 4; it++) {
            int idx = it * 256 + tid;       // 0..1023
            int kv = idx & 7, m = idx >> 3; // kv: float4 within chunk, m: 0..127
            {
                int gm = row0 + m;
                float4 v = make_float4(0.f, 0.f, 0.f, 0.f);
                if (gm < NN) v = ((const float4*)A)[(size_t)gm * 32 + kc * 8 + kv];
                sA[(4 * kv + 0) * SP + m] = v.x;
                sA[(4 * kv + 1) * SP + m] = v.y;
                sA[(4 * kv + 2) * SP + m] = v.z;
                sA[(4 * kv + 3) * SP + m] = v.w;
            }
            {
                int gn = col0 + m;
                float4 v = make_float4(0.f, 0.f, 0.f, 0.f);
                if (gn < NN) v = ((const float4*)B)[(size_t)gn * 32 + kc * 8 + kv];
                sB[(4 * kv + 0) * SP + m] = v.x;
                sB[(4 * kv + 1) * SP + m] = v.y;
                sB[(4 * kv + 2) * SP + m] = v.z;
                sB[(4 * kv + 3) * SP + m] = v.w;
            }
        }
        __syncthreads();
#pragma unroll 4
        for (int k = 0; k < 32; k++) {
            float4 a0 = *(const float4*)&sA[k * SP + 4 * ty];
            float4 a1 = *(const float4*)&sA[k * SP + 64 + 4 * ty];
            float4 b0 = *(const float4*)&sB[k * SP + 4 * tx];
            float4 b1 = *(const float4*)&sB[k * SP + 64 + 4 * tx];
            float am[8] = {a0.x, a0.y, a0.z, a0.w, a1.x, a1.y, a1.z, a1.w};
            float bn[8] = {b0.x, b0.y, b0.z, b0.w, b1.x, b1.y, b1.z, b1.w};
#pragma unroll
            for (int i = 0; i < 8; i++)
#pragma unroll
                for (int j = 0; j < 8; j++) acc[i][j] += am[i] * bn[j];
        }
    }

    const float THR[16] = {
        -0.8958797f, -0.7234595f, -0.5815754f, -0.4581454f,
        -0.3465736f, -0.2427540f, -0.1438410f, -0.0476551f,
         0.0476551f,  0.1438410f,  0.2427540f,  0.3465736f,
         0.4581454f,  0.5815754f,  0.7234595f,  0.8958797f};
    int cnt = 0;
#pragma unroll
    for (int mi = 0; mi < 8; mi++) {
        int gm = row0 + ((mi < 4) ? (4 * ty + mi) : (64 + 4 * ty + mi - 4));
        if (gm >= NN) continue;
#pragma unroll
        for (int ni = 0; ni < 8; ni++) {
            int gn = col0 + ((ni < 4) ? (4 * tx + ni) : (64 + 4 * tx + ni - 4));
            if (gn >= NN) continue;
            float s = acc[mi][ni];
#pragma unroll
            for (int j = 0; j < 16; j++) cnt += (s >= THR[j]) ? 1 : 0;
        }
    }
#pragma unroll
    for (int o = 16; o; o >>= 1) cnt += __shfl_xor_sync(0xffffffffu, cnt, o);
    if ((tid & 31) == 0) atomicAdd(&g_cnt[p], (unsigned)cnt);
}

// ---------------- finalize sim values ----------------
__global__ void k_final(float* __restrict__ out) {
    int p = threadIdx.x;
    if (p < NPAIR) {
        double v = -0.8 + 0.1 * (double)g_cnt[p] / ((double)NN * (double)NN);
        out[NGG * CC + cP1[p] * NGG + cP2[p]] = (float)v;
        out[NGG * CC + cP2[p] * NGG + cP1[p]] = (float)v;
    }
}

// ---------------- launch ----------------
extern "C" void kernel_launch(void* const* d_in, const int* in_sizes, int n_in,
                              void* d_out, int out_size) {
    const float* x   = (const float*)d_in[0];
    const int* ei    = (const int*)d_in[1];     // edge_index materializes as int32
    const float* ea  = (const float*)d_in[2];
    const float* gW  = (const float*)d_in[3];
    const float* gb  = (const float*)d_in[4];
    const float* Wsm = (const float*)d_in[5];
    float* out = (float*)d_out;

    k_init<<<(NGI * NN + 255) / 256, 256>>>();
    k_deg<<<(NGG * EE + 255) / 256, 256>>>(ei, ea);
    k_dis<<<(NGI * NN + 255) / 256, 256>>>();
    k_gemm_h<<<dim3(94, NGI), dim3(32, 8)>>>(x, gW);
    k_initO<<<18000, 256>>>();
    k_scatter<<<72000, 256>>>(ei, ea);
    k_feats<<<dim3(94, NGG), dim3(32, 8)>>>(Wsm, gb);
    k_gmatrix<<<NGG, 128>>>(out);
    k_norm<<<(NGG * NN) / 8, 256>>>();
    k_sim<<<dim3(47, 47, NPAIR), 256>>>();
    k_final<<<1, 32>>>(out);
}

// round 5
// speedup vs baseline: 3.6801x; 3.6801x over previous
#include <cuda_runtime.h>
#include <cuda_bf16.h>
#include <cstdint>

#define NGG 6
#define NN 6000
#define EE 96000
#define CC 128
#define NGI 24       // NGG * 4 layers
#define NPAIR 21
#define NROWP 6016   // NN padded to multiple of 128

// ---------------- device scratch ----------------
__device__ float g_deg[NGI * NN];
__device__ float g_H[(size_t)NGI * NN * CC];
__device__ float g_O[(size_t)NGI * NN * CC];
__device__ float g_feats[(size_t)NGG * NN * CC];
__device__ __nv_bfloat16 g_xnb[(size_t)NGG * NROWP * CC];   // normalized, bf16, padded
__device__ unsigned int g_cnt[NPAIR];

__constant__ int cP1[NPAIR] = {0,0,0,0,0,0, 1,1,1,1,1, 2,2,2,2, 3,3,3, 4,4, 5};
__constant__ int cP2[NPAIR] = {0,1,2,3,4,5, 1,2,3,4,5, 2,3,4,5, 3,4,5, 4,5, 5};

// s-space bin boundaries: bnd[k] = atanh(k/10.5 - 1), k=1..20; sentinels at ends
__constant__ float c_bnd[22] = {
    -3e38f,
    -1.49786614f, -1.12564590f, -0.89587974f, -0.72345949f, -0.58157540f,
    -0.45814537f, -0.34657359f, -0.24275391f, -0.14384104f, -0.04765509f,
     0.04765509f,  0.14384104f,  0.24275391f,  0.34657359f,  0.45814537f,
     0.58157540f,  0.72345949f,  0.89587974f,  1.12564590f,  1.49786614f,
     3e38f };

__device__ __forceinline__ uint32_t smem_u32(const void* p) {
    uint32_t a;
    asm("{ .reg .u64 t; cvta.to.shared.u64 t, %1; cvt.u32.u64 %0, t; }"
        : "=r"(a) : "l"(p));
    return a;
}
#define SWZ128(off) ((off) ^ (((off) >> 3) & 0x70))

// ---------------- setup ----------------
__global__ void k_init() {
    int i = blockIdx.x * blockDim.x + threadIdx.x;
    if (i < NGI * NN) g_deg[i] = 1.0f;
    if (i < NPAIR) g_cnt[i] = 0u;
}

__global__ void k_padzero() {
    int i = blockIdx.x * blockDim.x + threadIdx.x;   // over NGG*16*CC
    if (i < NGG * 16 * CC) {
        int g = i / (16 * CC), rem = i - g * (16 * CC);
        g_xnb[((size_t)g * NROWP + NN) * CC + rem] = __float2bfloat16(0.f);
    }
}

__global__ void k_deg(const int* __restrict__ ei, const float* __restrict__ ea) {
    int i = blockIdx.x * blockDim.x + threadIdx.x;
    if (i >= NGG * EE) return;
    int g = i / EE, e = i - g * EE;
    int c = ei[(size_t)g * 2 * EE + EE + e];
    const float* w = ea + ((size_t)g * EE + e) * 6;
#pragma unroll
    for (int l = 0; l < 4; l++)
        atomicAdd(&g_deg[(g * 4 + l) * NN + c], w[2 + l]);
}

__global__ void k_dis() {
    int i = blockIdx.x * blockDim.x + threadIdx.x;
    if (i < NGI * NN) g_deg[i] = rsqrtf(g_deg[i]);
}

// ---------------- H[gi] = x[g] @ gcn_W[layer] ----------------
__global__ void __launch_bounds__(256) k_gemm_h(const float* __restrict__ x,
                                                const float* __restrict__ gW) {
    __shared__ float sA[64 * 32];
    __shared__ float sB[32 * 128];
    int gi = blockIdx.y, g = gi >> 2, l = gi & 3;
    int row0 = blockIdx.x * 64;
    int tx = threadIdx.x, ty = threadIdx.y;
    int tid = ty * 32 + tx;
    const float4* Av = (const float4*)(x + (size_t)g * NN * CC);
    const float4* Bv = (const float4*)(gW + (size_t)l * CC * CC);
    float acc[8][4];
#pragma unroll
    for (int j = 0; j < 8; j++) { acc[j][0]=0;acc[j][1]=0;acc[j][2]=0;acc[j][3]=0; }
    for (int kc = 0; kc < 4; kc++) {
        __syncthreads();
#pragma unroll
        for (int it = 0; it < 4; it++)
            ((float4*)sB)[it * 256 + tid] = Bv[kc * 1024 + it * 256 + tid];
#pragma unroll
        for (int it = 0; it < 2; it++) {
            int idx = it * 256 + tid;
            int m = idx >> 3, kq = idx & 7;
            int gm = row0 + m;
            float4 v = make_float4(0.f, 0.f, 0.f, 0.f);
            if (gm < NN) v = Av[(size_t)gm * 32 + kc * 8 + kq];
            ((float4*)sA)[idx] = v;
        }
        __syncthreads();
#pragma unroll
        for (int k = 0; k < 32; k++) {
            float4 b = ((float4*)sB)[k * 32 + tx];
#pragma unroll
            for (int j = 0; j < 8; j++) {
                float a = sA[(ty * 8 + j) * 32 + k];
                acc[j][0] += a * b.x; acc[j][1] += a * b.y;
                acc[j][2] += a * b.z; acc[j][3] += a * b.w;
            }
        }
    }
#pragma unroll
    for (int j = 0; j < 8; j++) {
        int gm = row0 + ty * 8 + j;
        if (gm < NN)
            ((float4*)(g_H + ((size_t)gi * NN + gm) * CC))[tx] =
                make_float4(acc[j][0], acc[j][1], acc[j][2], acc[j][3]);
    }
}

// ---------------- O = dis^2 * H (self-loop term) ----------------
__global__ void k_initO() {
    size_t i = (size_t)blockIdx.x * 256 + threadIdx.x;
    if (i >= (size_t)NGI * NN * 32) return;
    int rowid = (int)(i >> 5);
    int gi = rowid / NN, node = rowid - gi * NN;
    float d = g_deg[gi * NN + node];
    float s = d * d;
    float4 h = ((const float4*)g_H)[i];
    ((float4*)g_O)[i] = make_float4(h.x * s, h.y * s, h.z * s, h.w * s);
}

// ---------------- edge scatter with vector reductions ----------------
__global__ void k_scatter(const int* __restrict__ ei, const float* __restrict__ ea) {
    int w = (blockIdx.x * 256 + threadIdx.x) >> 5;
    int lane = threadIdx.x & 31;
    if (w >= NGG * EE) return;
    int g = w / EE, e = w - g * EE;
    int r = ei[(size_t)g * 2 * EE + e];
    int c = ei[(size_t)g * 2 * EE + EE + e];
    const float* wp = ea + ((size_t)g * EE + e) * 6;
#pragma unroll
    for (int l = 0; l < 4; l++) {
        int gi = g * 4 + l;
        float nrm = g_deg[gi * NN + r] * wp[2 + l] * g_deg[gi * NN + c];
        float4 h = ((const float4*)(g_H + ((size_t)gi * NN + r) * CC))[lane];
        float* o = g_O + ((size_t)gi * NN + c) * CC + lane * 4;
        asm volatile("red.global.add.v4.f32 [%0], {%1, %2, %3, %4};"
                     :: "l"(o), "f"(h.x * nrm), "f"(h.y * nrm),
                        "f"(h.z * nrm), "f"(h.w * nrm) : "memory");
    }
}

// ---------------- feats[g] = sum_l relu(O[g,l]+b[l]) @ Ws[l] ----------------
__global__ void __launch_bounds__(256) k_feats(const float* __restrict__ Wsm,
                                               const float* __restrict__ gb) {
    __shared__ float sA[64 * 32];
    __shared__ float sB[32 * 128];
    int g = blockIdx.y;
    int row0 = blockIdx.x * 64;
    int tx = threadIdx.x, ty = threadIdx.y;
    int tid = ty * 32 + tx;
    float acc[8][4];
#pragma unroll
    for (int j = 0; j < 8; j++) { acc[j][0]=0;acc[j][1]=0;acc[j][2]=0;acc[j][3]=0; }
    for (int l = 0; l < 4; l++) {
        const float4* Bv = (const float4*)(Wsm + (size_t)l * CC * CC);
        const float4* bb = (const float4*)(gb + l * CC);
        const float4* Ov = (const float4*)(g_O + (size_t)(g * 4 + l) * NN * CC);
        for (int kc = 0; kc < 4; kc++) {
            __syncthreads();
#pragma unroll
            for (int it = 0; it < 4; it++)
                ((float4*)sB)[it * 256 + tid] = Bv[kc * 1024 + it * 256 + tid];
#pragma unroll
            for (int it = 0; it < 2; it++) {
                int idx = it * 256 + tid;
                int m = idx >> 3, kq = idx & 7;
                int gm = row0 + m;
                float4 v = make_float4(0.f, 0.f, 0.f, 0.f);
                if (gm < NN) {
                    float4 o = Ov[(size_t)gm * 32 + kc * 8 + kq];
                    float4 b = bb[kc * 8 + kq];
                    v = make_float4(fmaxf(o.x + b.x, 0.f), fmaxf(o.y + b.y, 0.f),
                                    fmaxf(o.z + b.z, 0.f), fmaxf(o.w + b.w, 0.f));
                }
                ((float4*)sA)[idx] = v;
            }
            __syncthreads();
#pragma unroll
            for (int k = 0; k < 32; k++) {
                float4 b = ((float4*)sB)[k * 32 + tx];
#pragma unroll
                for (int j = 0; j < 8; j++) {
                    float a = sA[(ty * 8 + j) * 32 + k];
                    acc[j][0] += a * b.x; acc[j][1] += a * b.y;
                    acc[j][2] += a * b.z; acc[j][3] += a * b.w;
                }
            }
        }
    }
#pragma unroll
    for (int j = 0; j < 8; j++) {
        int gm = row0 + ty * 8 + j;
        if (gm < NN)
            ((float4*)(g_feats + ((size_t)g * NN + gm) * CC))[tx] =
                make_float4(acc[j][0], acc[j][1], acc[j][2], acc[j][3]);
    }
}

// ---------------- g_matrix ----------------
__global__ void k_gmatrix(float* __restrict__ out) {
    int g = blockIdx.x, c = threadIdx.x;
    const float* p = g_feats + (size_t)g * NN * CC + c;
    float s0 = 0.f, s1 = 0.f, s2 = 0.f, s3 = 0.f;
    for (int n = 0; n < NN; n += 4) {
        s0 += p[(size_t)(n + 0) * CC];
        s1 += p[(size_t)(n + 1) * CC];
        s2 += p[(size_t)(n + 2) * CC];
        s3 += p[(size_t)(n + 3) * CC];
    }
    out[g * CC + c] = (s0 + s1 + s2 + s3) / (float)NN;
}

// ---------------- normalize rows -> bf16 (padded layout) ----------------
__global__ void k_norm() {
    int w = (blockIdx.x * 256 + threadIdx.x) >> 5;
    int lane = threadIdx.x & 31;
    if (w >= NGG * NN) return;
    int g = w / NN, node = w - g * NN;
    float4 v = ((const float4*)g_feats)[(size_t)w * 32 + lane];
    float ss = v.x * v.x + v.y * v.y + v.z * v.z + v.w * v.w;
#pragma unroll
    for (int o = 16; o; o >>= 1) ss += __shfl_xor_sync(0xffffffffu, ss, o);
    float inv = 1.0f / fmaxf(sqrtf(ss), 1e-12f);
    __nv_bfloat162 b0 = __floats2bfloat162_rn(v.x * inv, v.y * inv);
    __nv_bfloat162 b1 = __floats2bfloat162_rn(v.z * inv, v.w * inv);
    uint2 pk;
    pk.x = *(uint32_t*)&b0;
    pk.y = *(uint32_t*)&b1;
    ((uint2*)(g_xnb + ((size_t)g * NROWP + node) * CC))[lane] = pk;
}

// ---------------- sim via mma.sync bf16 + tanh-binned epilogue ----------------
// Each block: 128x128 tile of the pair dot-product matrix. 8 warps, each 32x64.
__global__ void __launch_bounds__(256, 2) k_sim() {
    __shared__ __nv_bfloat16 sA[128 * 64];   // K-chunk tile, SW128-swizzled
    __shared__ __nv_bfloat16 sB[128 * 64];
    __shared__ float s_bnd[22];

    int p = blockIdx.z;
    int i1 = cP1[p], i2 = cP2[p];
    int bx = blockIdx.x, by = blockIdx.y;
    bool diag = (i1 == i2);
    if (diag && bx > by) return;
    unsigned wgt = (diag && bx < by) ? 2u : 1u;

    int tid = threadIdx.x;
    int lane = tid & 31, wid = tid >> 5;
    int wm = wid & 3, wn = wid >> 2;          // warp tile: rows wm*32, cols wn*64
    if (tid < 22) s_bnd[tid] = c_bnd[tid];

    int row0 = bx * 128, col0 = by * 128;
    const __nv_bfloat16* A = g_xnb + (size_t)i1 * NROWP * CC;
    const __nv_bfloat16* B = g_xnb + (size_t)i2 * NROWP * CC;
    uint32_t baseA = smem_u32(sA), baseB = smem_u32(sB);

    float acc[2][8][4];
#pragma unroll
    for (int mt = 0; mt < 2; mt++)
#pragma unroll
        for (int nt = 0; nt < 8; nt++) {
            acc[mt][nt][0] = 0.f; acc[mt][nt][1] = 0.f;
            acc[mt][nt][2] = 0.f; acc[mt][nt][3] = 0.f;
        }

    for (int kc = 0; kc < 2; kc++) {
        __syncthreads();
#pragma unroll
        for (int it = 0; it < 4; it++) {
            int idx = it * 256 + tid;          // 0..1023 uint4 slots
            int r = idx >> 3, q = idx & 7;
            uint32_t sw = SWZ128((uint32_t)(r * 128 + q * 16));
            *(uint4*)((uint8_t*)sA + sw) =
                *(const uint4*)(A + (size_t)(row0 + r) * CC + kc * 64 + q * 8);
            *(uint4*)((uint8_t*)sB + sw) =
                *(const uint4*)(B + (size_t)(col0 + r) * CC + kc * 64 + q * 8);
        }
        __syncthreads();
#pragma unroll
        for (int ks = 0; ks < 4; ks++) {
            int kb = ks * 32;                  // byte offset of k-step within row
            uint32_t a[2][4];
#pragma unroll
            for (int mt = 0; mt < 2; mt++) {
                int r = wm * 32 + mt * 16 + (lane & 15);
                uint32_t ad = baseA + SWZ128((uint32_t)(r * 128 + kb + (lane >> 4) * 16));
                asm volatile("ldmatrix.sync.aligned.m8n8.x4.shared.b16 {%0,%1,%2,%3}, [%4];"
                    : "=r"(a[mt][0]), "=r"(a[mt][1]), "=r"(a[mt][2]), "=r"(a[mt][3])
                    : "r"(ad));
            }
            uint32_t b[4][4];
#pragma unroll
            for (int np = 0; np < 4; np++) {
                int r = wn * 64 + np * 16 + (lane & 7) + ((lane >> 4) << 3);
                uint32_t bd = baseB + SWZ128((uint32_t)(r * 128 + kb + ((lane >> 3) & 1) * 16));
                asm volatile("ldmatrix.sync.aligned.m8n8.x4.shared.b16 {%0,%1,%2,%3}, [%4];"
                    : "=r"(b[np][0]), "=r"(b[np][1]), "=r"(b[np][2]), "=r"(b[np][3])
                    : "r"(bd));
            }
#pragma unroll
            for (int mt = 0; mt < 2; mt++)
#pragma unroll
                for (int nt = 0; nt < 8; nt++) {
                    asm volatile(
                        "mma.sync.aligned.m16n8k16.row.col.f32.bf16.bf16.f32 "
                        "{%0,%1,%2,%3}, {%4,%5,%6,%7}, {%8,%9}, {%0,%1,%2,%3};"
                        : "+f"(acc[mt][nt][0]), "+f"(acc[mt][nt][1]),
                          "+f"(acc[mt][nt][2]), "+f"(acc[mt][nt][3])
                        : "r"(a[mt][0]), "r"(a[mt][1]), "r"(a[mt][2]), "r"(a[mt][3]),
                          "r"(b[nt >> 1][(nt & 1) * 2]), "r"(b[nt >> 1][(nt & 1) * 2 + 1]));
                }
        }
    }

    // epilogue: bin every accumulator value (position-independent)
    int sum = 0;
#pragma unroll
    for (int mt = 0; mt < 2; mt++)
#pragma unroll
        for (int nt = 0; nt < 8; nt++)
#pragma unroll
            for (int v = 0; v < 4; v++) {
                float s = acc[mt][nt][v];
                float t;
                asm("tanh.approx.f32 %0, %1;" : "=f"(t) : "f"(s));
                int idx = __float2int_rd(fmaf(t, 10.5f, 10.5f));
                idx = max(0, min(20, idx));
                idx += (s >= s_bnd[idx + 1]) ? 1 : 0;
                idx -= (s <  s_bnd[idx]) ? 1 : 0;
                idx += (s >= s_bnd[idx + 1]) ? 1 : 0;
                idx -= (s <  s_bnd[idx]) ? 1 : 0;
                sum += idx;
            }
#pragma unroll
    for (int o = 16; o; o >>= 1) sum += __shfl_xor_sync(0xffffffffu, sum, o);
    if ((tid & 31) == 0) atomicAdd(&g_cnt[p], wgt * (unsigned)sum);
}

// ---------------- finalize ----------------
__global__ void k_final(float* __restrict__ out) {
    int p = threadIdx.x;
    if (p < NPAIR) {
        // pads: 6016^2 - 6000^2 = 192256 zero-dots, each binned at idx=10 (center 0)
        double cnt = (double)g_cnt[p] - 10.0 * 192256.0;
        double v = -1.0 + 0.1 * cnt / ((double)NN * (double)NN);
        out[NGG * CC + cP1[p] * NGG + cP2[p]] = (float)v;
        out[NGG * CC + cP2[p] * NGG + cP1[p]] = (float)v;
    }
}

// ---------------- launch ----------------
extern "C" void kernel_launch(void* const* d_in, const int* in_sizes, int n_in,
                              void* d_out, int out_size) {
    const float* x   = (const float*)d_in[0];
    const int* ei    = (const int*)d_in[1];
    const float* ea  = (const float*)d_in[2];
    const float* gW  = (const float*)d_in[3];
    const float* gb  = (const float*)d_in[4];
    const float* Wsm = (const float*)d_in[5];
    float* out = (float*)d_out;

    k_init<<<(NGI * NN + 255) / 256, 256>>>();
    k_padzero<<<48, 256>>>();
    k_deg<<<(NGG * EE + 255) / 256, 256>>>(ei, ea);
    k_dis<<<(NGI * NN + 255) / 256, 256>>>();
    k_gemm_h<<<dim3(94, NGI), dim3(32, 8)>>>(x, gW);
    k_initO<<<18000, 256>>>();
    k_scatter<<<72000, 256>>>(ei, ea);
    k_feats<<<dim3(94, NGG), dim3(32, 8)>>>(Wsm, gb);
    k_gmatrix<<<NGG, 128>>>(out);
    k_norm<<<(NGG * NN) / 8, 256>>>();
    k_sim<<<dim3(47, 47, NPAIR), 256>>>();
    k_final<<<1, 32>>>(out);
}

// round 6
// speedup vs baseline: 4.5423x; 1.2343x over previous
#include <cuda_runtime.h>
#include <cuda_bf16.h>
#include <cstdint>

#define NGG 6
#define NN 6000
#define EE 96000
#define CC 128
#define NGI 24       // NGG * 4 layers
#define NPAIR 21
#define NROWP 6016   // NN padded to multiple of 128

// ---------------- device scratch ----------------
__device__ float g_deg[NGI * NN];                 // weighted deg -> dis (in place)
__device__ int   g_cntn[NGG * NN];                // in-edge count per node
__device__ int   g_off[NGG * NN];                 // CSR start offsets
__device__ int   g_cur[NGG * NN];                 // fill cursors
__device__ int   g_csr[NGG * EE];                 // source node per CSR slot
__device__ float g_enorm[(size_t)NGG * EE * 4];   // per-edge per-layer norm coeff
__device__ float g_H[(size_t)NGI * NN * CC];
__device__ float g_O[(size_t)NGI * NN * CC];
__device__ float g_feats[(size_t)NGG * NN * CC];
__device__ __nv_bfloat16 g_xnb[(size_t)NGG * NROWP * CC];
__device__ unsigned int g_cnt[NPAIR];

__constant__ int cP1[NPAIR] = {0,0,0,0,0,0, 1,1,1,1,1, 2,2,2,2, 3,3,3, 4,4, 5};
__constant__ int cP2[NPAIR] = {0,1,2,3,4,5, 1,2,3,4,5, 2,3,4,5, 3,4,5, 4,5, 5};

// s-space bin boundaries: bnd[k] = atanh(k/10.5 - 1), k=1..20; sentinels at ends
__constant__ float c_bnd[22] = {
    -3e38f,
    -1.49786614f, -1.12564590f, -0.89587974f, -0.72345949f, -0.58157540f,
    -0.45814537f, -0.34657359f, -0.24275391f, -0.14384104f, -0.04765509f,
     0.04765509f,  0.14384104f,  0.24275391f,  0.34657359f,  0.45814537f,
     0.58157540f,  0.72345949f,  0.89587974f,  1.12564590f,  1.49786614f,
     3e38f };

__device__ __forceinline__ uint32_t smem_u32(const void* p) {
    uint32_t a;
    asm("{ .reg .u64 t; cvta.to.shared.u64 t, %1; cvt.u32.u64 %0, t; }"
        : "=r"(a) : "l"(p));
    return a;
}
#define SWZ128(off) ((off) ^ (((off) >> 3) & 0x70))

// ---------------- setup: init deg/counters + bf16 pad rows ----------------
__global__ void k_setup() {
    int i = blockIdx.x * blockDim.x + threadIdx.x;
    if (i < NGI * NN) g_deg[i] = 1.0f;          // self-loop weight
    if (i < NGG * NN) g_cntn[i] = 0;
    if (i < NPAIR) g_cnt[i] = 0u;
    if (i < NGG * 16 * CC) {
        int g = i / (16 * CC), rem = i - g * (16 * CC);
        g_xnb[((size_t)g * NROWP + NN) * CC + rem] = __float2bfloat16(0.f);
    }
}

// ---------------- per-node in-degree count + weighted degree ----------------
__global__ void k_deg(const int* __restrict__ ei, const float* __restrict__ ea) {
    int i = blockIdx.x * blockDim.x + threadIdx.x;
    if (i >= NGG * EE) return;
    int g = i / EE, e = i - g * EE;
    int c = ei[(size_t)g * 2 * EE + EE + e];
    const float* w = ea + ((size_t)g * EE + e) * 6;
    atomicAdd(&g_cntn[g * NN + c], 1);
#pragma unroll
    for (int l = 0; l < 4; l++)
        atomicAdd(&g_deg[(g * 4 + l) * NN + c], w[2 + l]);
}

__global__ void k_dis() {
    int i = blockIdx.x * blockDim.x + threadIdx.x;
    if (i < NGI * NN) g_deg[i] = rsqrtf(g_deg[i]);
}

// ---------------- CSR offsets: block per graph, scan 6000 counts ----------------
__global__ void __launch_bounds__(256) k_scan() {
    __shared__ int ps[256];
    int g = blockIdx.x, t = threadIdx.x;
    const int PT = 24;                    // 250 threads * 24 = 6000
    int loc[PT];
    int s = 0;
    if (t < 250) {
        int base = g * NN + t * PT;
#pragma unroll
        for (int i = 0; i < PT; i++) { loc[i] = g_cntn[base + i]; s += loc[i]; }
    }
    ps[t] = s;
    __syncthreads();
    for (int o = 1; o < 256; o <<= 1) {
        int v = (t >= o) ? ps[t - o] : 0;
        __syncthreads();
        ps[t] += v;
        __syncthreads();
    }
    if (t < 250) {
        int run = ps[t] - s;              // exclusive prefix
        int base = g * NN + t * PT;
#pragma unroll
        for (int i = 0; i < PT; i++) {
            g_off[base + i] = run;
            g_cur[base + i] = run;
            run += loc[i];
        }
    }
}

// ---------------- CSR fill + per-edge norm coefficients ----------------
__global__ void k_fill(const int* __restrict__ ei, const float* __restrict__ ea) {
    int i = blockIdx.x * blockDim.x + threadIdx.x;
    if (i >= NGG * EE) return;
    int g = i / EE, e = i - g * EE;
    int r = ei[(size_t)g * 2 * EE + e];
    int c = ei[(size_t)g * 2 * EE + EE + e];
    int pos = atomicAdd(&g_cur[g * NN + c], 1);
    g_csr[g * EE + pos] = r;
    const float* w = ea + ((size_t)g * EE + e) * 6;
    float4 nm;
    nm.x = g_deg[(g * 4 + 0) * NN + r] * w[2] * g_deg[(g * 4 + 0) * NN + c];
    nm.y = g_deg[(g * 4 + 1) * NN + r] * w[3] * g_deg[(g * 4 + 1) * NN + c];
    nm.z = g_deg[(g * 4 + 2) * NN + r] * w[4] * g_deg[(g * 4 + 2) * NN + c];
    nm.w = g_deg[(g * 4 + 3) * NN + r] * w[5] * g_deg[(g * 4 + 3) * NN + c];
    *(float4*)&g_enorm[((size_t)g * EE + pos) * 4] = nm;
}

// ---------------- H[gi] = x[g] @ gcn_W[layer] ----------------
__global__ void __launch_bounds__(256) k_gemm_h(const float* __restrict__ x,
                                                const float* __restrict__ gW) {
    __shared__ float sA[64 * 32];
    __shared__ float sB[32 * 128];
    int gi = blockIdx.y, g = gi >> 2, l = gi & 3;
    int row0 = blockIdx.x * 64;
    int tx = threadIdx.x, ty = threadIdx.y;
    int tid = ty * 32 + tx;
    const float4* Av = (const float4*)(x + (size_t)g * NN * CC);
    const float4* Bv = (const float4*)(gW + (size_t)l * CC * CC);
    float acc[8][4];
#pragma unroll
    for (int j = 0; j < 8; j++) { acc[j][0]=0;acc[j][1]=0;acc[j][2]=0;acc[j][3]=0; }
    for (int kc = 0; kc < 4; kc++) {
        __syncthreads();
#pragma unroll
        for (int it = 0; it < 4; it++)
            ((float4*)sB)[it * 256 + tid] = Bv[kc * 1024 + it * 256 + tid];
#pragma unroll
        for (int it = 0; it < 2; it++) {
            int idx = it * 256 + tid;
            int m = idx >> 3, kq = idx & 7;
            int gm = row0 + m;
            float4 v = make_float4(0.f, 0.f, 0.f, 0.f);
            if (gm < NN) v = Av[(size_t)gm * 32 + kc * 8 + kq];
            ((float4*)sA)[idx] = v;
        }
        __syncthreads();
#pragma unroll
        for (int k = 0; k < 32; k++) {
            float4 b = ((float4*)sB)[k * 32 + tx];
#pragma unroll
            for (int j = 0; j < 8; j++) {
                float a = sA[(ty * 8 + j) * 32 + k];
                acc[j][0] += a * b.x; acc[j][1] += a * b.y;
                acc[j][2] += a * b.z; acc[j][3] += a * b.w;
            }
        }
    }
#pragma unroll
    for (int j = 0; j < 8; j++) {
        int gm = row0 + ty * 8 + j;
        if (gm < NN)
            ((float4*)(g_H + ((size_t)gi * NN + gm) * CC))[tx] =
                make_float4(acc[j][0], acc[j][1], acc[j][2], acc[j][3]);
    }
}

// ---------------- gather: O[c] = dis[c]^2*H[c] + sum_in csr nrm*H[r] ----------
__global__ void __launch_bounds__(256) k_gather() {
    int w = (blockIdx.x * 256 + threadIdx.x) >> 5;
    int lane = threadIdx.x & 31;
    if (w >= NGG * NN) return;
    int g = w / NN, c = w - g * NN;

    float4 acc[4];
#pragma unroll
    for (int l = 0; l < 4; l++) {
        int gi = g * 4 + l;
        float d = g_deg[gi * NN + c];
        float s = d * d;
        float4 h = ((const float4*)(g_H + ((size_t)gi * NN + c) * CC))[lane];
        acc[l] = make_float4(h.x * s, h.y * s, h.z * s, h.w * s);
    }
    int start = g_off[g * NN + c];
    int cnt = g_cntn[g * NN + c];
    const int* csr = g_csr + (size_t)g * EE;
    const float4* en = (const float4*)(g_enorm + (size_t)g * EE * 4);
    for (int j = 0; j < cnt; j++) {
        int r = csr[start + j];
        float4 nm = en[start + j];
#pragma unroll
        for (int l = 0; l < 4; l++) {
            float nl = (l == 0) ? nm.x : (l == 1) ? nm.y : (l == 2) ? nm.z : nm.w;
            float4 h = ((const float4*)(g_H + ((size_t)(g * 4 + l) * NN + r) * CC))[lane];
            acc[l].x += nl * h.x; acc[l].y += nl * h.y;
            acc[l].z += nl * h.z; acc[l].w += nl * h.w;
        }
    }
#pragma unroll
    for (int l = 0; l < 4; l++)
        ((float4*)(g_O + ((size_t)(g * 4 + l) * NN + c) * CC))[lane] = acc[l];
}

// ---------------- feats[g] = sum_l relu(O[g,l]+b[l]) @ Ws[l] ----------------
__global__ void __launch_bounds__(256) k_feats(const float* __restrict__ Wsm,
                                               const float* __restrict__ gb) {
    __shared__ float sA[64 * 32];
    __shared__ float sB[32 * 128];
    int g = blockIdx.y;
    int row0 = blockIdx.x * 64;
    int tx = threadIdx.x, ty = threadIdx.y;
    int tid = ty * 32 + tx;
    float acc[8][4];
#pragma unroll
    for (int j = 0; j < 8; j++) { acc[j][0]=0;acc[j][1]=0;acc[j][2]=0;acc[j][3]=0; }
    for (int l = 0; l < 4; l++) {
        const float4* Bv = (const float4*)(Wsm + (size_t)l * CC * CC);
        const float4* bb = (const float4*)(gb + l * CC);
        const float4* Ov = (const float4*)(g_O + (size_t)(g * 4 + l) * NN * CC);
        for (int kc = 0; kc < 4; kc++) {
            __syncthreads();
#pragma unroll
            for (int it = 0; it < 4; it++)
                ((float4*)sB)[it * 256 + tid] = Bv[kc * 1024 + it * 256 + tid];
#pragma unroll
            for (int it = 0; it < 2; it++) {
                int idx = it * 256 + tid;
                int m = idx >> 3, kq = idx & 7;
                int gm = row0 + m;
                float4 v = make_float4(0.f, 0.f, 0.f, 0.f);
                if (gm < NN) {
                    float4 o = Ov[(size_t)gm * 32 + kc * 8 + kq];
                    float4 b = bb[kc * 8 + kq];
                    v = make_float4(fmaxf(o.x + b.x, 0.f), fmaxf(o.y + b.y, 0.f),
                                    fmaxf(o.z + b.z, 0.f), fmaxf(o.w + b.w, 0.f));
                }
                ((float4*)sA)[idx] = v;
            }
            __syncthreads();
#pragma unroll
            for (int k = 0; k < 32; k++) {
                float4 b = ((float4*)sB)[k * 32 + tx];
#pragma unroll
                for (int j = 0; j < 8; j++) {
                    float a = sA[(ty * 8 + j) * 32 + k];
                    acc[j][0] += a * b.x; acc[j][1] += a * b.y;
                    acc[j][2] += a * b.z; acc[j][3] += a * b.w;
                }
            }
        }
    }
#pragma unroll
    for (int j = 0; j < 8; j++) {
        int gm = row0 + ty * 8 + j;
        if (gm < NN)
            ((float4*)(g_feats + ((size_t)g * NN + gm) * CC))[tx] =
                make_float4(acc[j][0], acc[j][1], acc[j][2], acc[j][3]);
    }
}

// ---------------- g_matrix ----------------
__global__ void k_gmatrix(float* __restrict__ out) {
    int g = blockIdx.x, c = threadIdx.x;
    const float* p = g_feats + (size_t)g * NN * CC + c;
    float s0 = 0.f, s1 = 0.f, s2 = 0.f, s3 = 0.f;
    for (int n = 0; n < NN; n += 4) {
        s0 += p[(size_t)(n + 0) * CC];
        s1 += p[(size_t)(n + 1) * CC];
        s2 += p[(size_t)(n + 2) * CC];
        s3 += p[(size_t)(n + 3) * CC];
    }
    out[g * CC + c] = (s0 + s1 + s2 + s3) / (float)NN;
}

// ---------------- normalize rows -> bf16 (padded layout) ----------------
__global__ void k_norm() {
    int w = (blockIdx.x * 256 + threadIdx.x) >> 5;
    int lane = threadIdx.x & 31;
    if (w >= NGG * NN) return;
    int g = w / NN, node = w - g * NN;
    float4 v = ((const float4*)g_feats)[(size_t)w * 32 + lane];
    float ss = v.x * v.x + v.y * v.y + v.z * v.z + v.w * v.w;
#pragma unroll
    for (int o = 16; o; o >>= 1) ss += __shfl_xor_sync(0xffffffffu, ss, o);
    float inv = 1.0f / fmaxf(sqrtf(ss), 1e-12f);
    __nv_bfloat162 b0 = __floats2bfloat162_rn(v.x * inv, v.y * inv);
    __nv_bfloat162 b1 = __floats2bfloat162_rn(v.z * inv, v.w * inv);
    uint2 pk;
    pk.x = *(uint32_t*)&b0;
    pk.y = *(uint32_t*)&b1;
    ((uint2*)(g_xnb + ((size_t)g * NROWP + node) * CC))[lane] = pk;
}

// ---------------- sim via mma.sync bf16 + tanh-binned epilogue ----------------
__global__ void __launch_bounds__(256, 2) k_sim() {
    __shared__ __nv_bfloat16 sA[128 * 64];   // K-chunk tile, SW128-swizzled
    __shared__ __nv_bfloat16 sB[128 * 64];
    __shared__ float s_bnd[22];
    __shared__ unsigned s_part[8];

    int p = blockIdx.z;
    int i1 = cP1[p], i2 = cP2[p];
    int bx = blockIdx.x, by = blockIdx.y;
    bool diag = (i1 == i2);
    if (diag && bx > by) return;
    unsigned wgt = (diag && bx < by) ? 2u : 1u;

    int tid = threadIdx.x;
    int lane = tid & 31, wid = tid >> 5;
    int wm = wid & 3, wn = wid >> 2;          // warp tile: rows wm*32, cols wn*64
    if (tid < 22) s_bnd[tid] = c_bnd[tid];

    int row0 = bx * 128, col0 = by * 128;
    const __nv_bfloat16* A = g_xnb + (size_t)i1 * NROWP * CC;
    const __nv_bfloat16* B = g_xnb + (size_t)i2 * NROWP * CC;
    uint32_t baseA = smem_u32(sA), baseB = smem_u32(sB);

    float acc[2][8][4];
#pragma unroll
    for (int mt = 0; mt < 2; mt++)
#pragma unroll
        for (int nt = 0; nt < 8; nt++) {
            acc[mt][nt][0] = 0.f; acc[mt][nt][1] = 0.f;
            acc[mt][nt][2] = 0.f; acc[mt][nt][3] = 0.f;
        }

    for (int kc = 0; kc < 2; kc++) {
        __syncthreads();
#pragma unroll
        for (int it = 0; it < 4; it++) {
            int idx = it * 256 + tid;          // 0..1023 uint4 slots
            int r = idx >> 3, q = idx & 7;
            uint32_t sw = SWZ128((uint32_t)(r * 128 + q * 16));
            *(uint4*)((uint8_t*)sA + sw) =
                *(const uint4*)(A + (size_t)(row0 + r) * CC + kc * 64 + q * 8);
            *(uint4*)((uint8_t*)sB + sw) =
                *(const uint4*)(B + (size_t)(col0 + r) * CC + kc * 64 + q * 8);
        }
        __syncthreads();
#pragma unroll
        for (int ks = 0; ks < 4; ks++) {
            int kb = ks * 32;                  // byte offset of k-step within row
            uint32_t a[2][4];
#pragma unroll
            for (int mt = 0; mt < 2; mt++) {
                int r = wm * 32 + mt * 16 + (lane & 15);
                uint32_t ad = baseA + SWZ128((uint32_t)(r * 128 + kb + (lane >> 4) * 16));
                asm volatile("ldmatrix.sync.aligned.m8n8.x4.shared.b16 {%0,%1,%2,%3}, [%4];"
                    : "=r"(a[mt][0]), "=r"(a[mt][1]), "=r"(a[mt][2]), "=r"(a[mt][3])
                    : "r"(ad));
            }
            uint32_t b[4][4];
#pragma unroll
            for (int np = 0; np < 4; np++) {
                int r = wn * 64 + np * 16 + (lane & 7) + ((lane >> 4) << 3);
                uint32_t bd = baseB + SWZ128((uint32_t)(r * 128 + kb + ((lane >> 3) & 1) * 16));
                asm volatile("ldmatrix.sync.aligned.m8n8.x4.shared.b16 {%0,%1,%2,%3}, [%4];"
                    : "=r"(b[np][0]), "=r"(b[np][1]), "=r"(b[np][2]), "=r"(b[np][3])
                    : "r"(bd));
            }
#pragma unroll
            for (int mt = 0; mt < 2; mt++)
#pragma unroll
                for (int nt = 0; nt < 8; nt++) {
                    asm volatile(
                        "mma.sync.aligned.m16n8k16.row.col.f32.bf16.bf16.f32 "
                        "{%0,%1,%2,%3}, {%4,%5,%6,%7}, {%8,%9}, {%0,%1,%2,%3};"
                        : "+f"(acc[mt][nt][0]), "+f"(acc[mt][nt][1]),
                          "+f"(acc[mt][nt][2]), "+f"(acc[mt][nt][3])
                        : "r"(a[mt][0]), "r"(a[mt][1]), "r"(a[mt][2]), "r"(a[mt][3]),
                          "r"(b[nt >> 1][(nt & 1) * 2]), "r"(b[nt >> 1][(nt & 1) * 2 + 1]));
                }
        }
    }

    // epilogue: bin every accumulator value (position-independent).
    // tanh.approx err (~5e-4) << bin width (0.095) -> idx off by at most 1,
    // so a single up + single down exact-boundary correction suffices.
    int sum = 0;
#pragma unroll
    for (int mt = 0; mt < 2; mt++)
#pragma unroll
        for (int nt = 0; nt < 8; nt++)
#pragma unroll
            for (int v = 0; v < 4; v++) {
                float s = acc[mt][nt][v];
                float t;
                asm("tanh.approx.f32 %0, %1;" : "=f"(t) : "f"(s));
                int idx = __float2int_rd(fmaf(t, 10.5f, 10.5f));
                idx = max(0, min(20, idx));
                idx += (s >= s_bnd[idx + 1]) ? 1 : 0;
                idx -= (s <  s_bnd[idx]) ? 1 : 0;
                sum += idx;
            }
#pragma unroll
    for (int o = 16; o; o >>= 1) sum += __shfl_xor_sync(0xffffffffu, sum, o);
    if (lane == 0) s_part[wid] = (unsigned)sum;
    __syncthreads();
    if (tid == 0) {
        unsigned tot = 0;
#pragma unroll
        for (int i = 0; i < 8; i++) tot += s_part[i];
        atomicAdd(&g_cnt[p], wgt * tot);
    }
}

// ---------------- finalize ----------------
__global__ void k_final(float* __restrict__ out) {
    int p = threadIdx.x;
    if (p < NPAIR) {
        // pads: 6016^2 - 6000^2 = 192256 zero-dots, each binned at idx=10
        double cnt = (double)g_cnt[p] - 10.0 * 192256.0;
        double v = -1.0 + 0.1 * cnt / ((double)NN * (double)NN);
        out[NGG * CC + cP1[p] * NGG + cP2[p]] = (float)v;
        out[NGG * CC + cP2[p] * NGG + cP1[p]] = (float)v;
    }
}

// ---------------- launch ----------------
extern "C" void kernel_launch(void* const* d_in, const int* in_sizes, int n_in,
                              void* d_out, int out_size) {
    const float* x   = (const float*)d_in[0];
    const int* ei    = (const int*)d_in[1];
    const float* ea  = (const float*)d_in[2];
    const float* gW  = (const float*)d_in[3];
    const float* gb  = (const float*)d_in[4];
    const float* Wsm = (const float*)d_in[5];
    float* out = (float*)d_out;

    k_setup<<<(NGI * NN + 255) / 256, 256>>>();
    k_deg<<<(NGG * EE + 255) / 256, 256>>>(ei, ea);
    k_dis<<<(NGI * NN + 255) / 256, 256>>>();
    k_scan<<<NGG, 256>>>();
    k_fill<<<(NGG * EE + 255) / 256, 256>>>(ei, ea);
    k_gemm_h<<<dim3(94, NGI), dim3(32, 8)>>>(x, gW);
    k_gather<<<(NGG * NN + 7) / 8, 256>>>();
    k_feats<<<dim3(94, NGG), dim3(32, 8)>>>(Wsm, gb);
    k_gmatrix<<<NGG, 128>>>(out);
    k_norm<<<(NGG * NN) / 8, 256>>>();
    k_sim<<<dim3(47, 47, NPAIR), 256>>>();
    k_final<<<1, 32>>>(out);
}

// round 7
// speedup vs baseline: 4.5703x; 1.0062x over previous
#include <cuda_runtime.h>
#include <cuda_bf16.h>
#include <cstdint>

#define NGG 6
#define NN 6000
#define EE 96000
#define CC 128
#define NGI 24       // NGG * 4 layers
#define NPAIR 21
#define NROWP 6016   // NN padded to multiple of 128

// ---------------- device scratch ----------------
__device__ float g_deg[NGI * NN];                 // weighted deg -> dis (in place)
__device__ int   g_cntn[NGG * NN];                // in-edge count per node
__device__ int   g_off[NGG * NN];                 // CSR start offsets
__device__ int   g_cur[NGG * NN];                 // fill cursors
__device__ int   g_csr[NGG * EE];                 // source node per CSR slot
__device__ float g_enorm[(size_t)NGG * EE * 4];   // per-edge per-layer norm coeff
__device__ float g_Z[(size_t)NGI * NN * CC];      // gathered x (pre-GEMM), per (g,l)
__device__ float g_O[(size_t)NGI * NN * CC];      // Z @ W per (g,l)
__device__ float g_feats[(size_t)NGG * NN * CC];
__device__ __nv_bfloat16 g_xnb[(size_t)NGG * NROWP * CC];
__device__ unsigned int g_cnt[NPAIR];

__constant__ int cP1[NPAIR] = {0,0,0,0,0,0, 1,1,1,1,1, 2,2,2,2, 3,3,3, 4,4, 5};
__constant__ int cP2[NPAIR] = {0,1,2,3,4,5, 1,2,3,4,5, 2,3,4,5, 3,4,5, 4,5, 5};

// s-space bin boundaries: bnd[k] = atanh(k/10.5 - 1), k=1..20; sentinels at ends
__constant__ float c_bnd[22] = {
    -3e38f,
    -1.49786614f, -1.12564590f, -0.89587974f, -0.72345949f, -0.58157540f,
    -0.45814537f, -0.34657359f, -0.24275391f, -0.14384104f, -0.04765509f,
     0.04765509f,  0.14384104f,  0.24275391f,  0.34657359f,  0.45814537f,
     0.58157540f,  0.72345949f,  0.89587974f,  1.12564590f,  1.49786614f,
     3e38f };

__device__ __forceinline__ uint32_t smem_u32(const void* p) {
    uint32_t a;
    asm("{ .reg .u64 t; cvta.to.shared.u64 t, %1; cvt.u32.u64 %0, t; }"
        : "=r"(a) : "l"(p));
    return a;
}
#define SWZ128(off) ((off) ^ (((off) >> 3) & 0x70))

// ---------------- setup ----------------
__global__ void k_setup() {
    int i = blockIdx.x * blockDim.x + threadIdx.x;
    if (i < NGI * NN) g_deg[i] = 1.0f;          // self-loop weight
    if (i < NGG * NN) g_cntn[i] = 0;
    if (i < NPAIR) g_cnt[i] = 0u;
    if (i < NGG * 16 * CC) {
        int g = i / (16 * CC), rem = i - g * (16 * CC);
        g_xnb[((size_t)g * NROWP + NN) * CC + rem] = __float2bfloat16(0.f);
    }
}

// ---------------- per-node in-degree count + weighted degree ----------------
__global__ void k_deg(const int* __restrict__ ei, const float* __restrict__ ea) {
    int i = blockIdx.x * blockDim.x + threadIdx.x;
    if (i >= NGG * EE) return;
    int g = i / EE, e = i - g * EE;
    int c = ei[(size_t)g * 2 * EE + EE + e];
    const float* w = ea + ((size_t)g * EE + e) * 6;
    atomicAdd(&g_cntn[g * NN + c], 1);
#pragma unroll
    for (int l = 0; l < 4; l++)
        atomicAdd(&g_deg[(g * 4 + l) * NN + c], w[2 + l]);
}

__global__ void k_dis() {
    int i = blockIdx.x * blockDim.x + threadIdx.x;
    if (i < NGI * NN) g_deg[i] = rsqrtf(g_deg[i]);
}

// ---------------- CSR offsets: block per graph, scan 6000 counts ----------------
__global__ void __launch_bounds__(256) k_scan() {
    __shared__ int ps[256];
    int g = blockIdx.x, t = threadIdx.x;
    const int PT = 24;                    // 250 threads * 24 = 6000
    int loc[PT];
    int s = 0;
    if (t < 250) {
        int base = g * NN + t * PT;
#pragma unroll
        for (int i = 0; i < PT; i++) { loc[i] = g_cntn[base + i]; s += loc[i]; }
    }
    ps[t] = s;
    __syncthreads();
    for (int o = 1; o < 256; o <<= 1) {
        int v = (t >= o) ? ps[t - o] : 0;
        __syncthreads();
        ps[t] += v;
        __syncthreads();
    }
    if (t < 250) {
        int run = ps[t] - s;              // exclusive prefix
        int base = g * NN + t * PT;
#pragma unroll
        for (int i = 0; i < PT; i++) {
            g_off[base + i] = run;
            g_cur[base + i] = run;
            run += loc[i];
        }
    }
}

// ---------------- CSR fill + per-edge norm coefficients ----------------
__global__ void k_fill(const int* __restrict__ ei, const float* __restrict__ ea) {
    int i = blockIdx.x * blockDim.x + threadIdx.x;
    if (i >= NGG * EE) return;
    int g = i / EE, e = i - g * EE;
    int r = ei[(size_t)g * 2 * EE + e];
    int c = ei[(size_t)g * 2 * EE + EE + e];
    int pos = atomicAdd(&g_cur[g * NN + c], 1);
    g_csr[g * EE + pos] = r;
    const float* w = ea + ((size_t)g * EE + e) * 6;
    float4 nm;
    nm.x = g_deg[(g * 4 + 0) * NN + r] * w[2] * g_deg[(g * 4 + 0) * NN + c];
    nm.y = g_deg[(g * 4 + 1) * NN + r] * w[3] * g_deg[(g * 4 + 1) * NN + c];
    nm.z = g_deg[(g * 4 + 2) * NN + r] * w[4] * g_deg[(g * 4 + 2) * NN + c];
    nm.w = g_deg[(g * 4 + 3) * NN + r] * w[5] * g_deg[(g * 4 + 3) * NN + c];
    *(float4*)&g_enorm[((size_t)g * EE + pos) * 4] = nm;
}

// ---------------- gather raw x:  Z_l[c] = dis_l[c]^2 x[c] + sum_in nrm_l x[r] --
__global__ void __launch_bounds__(256) k_gather(const float* __restrict__ x) {
    int w = (blockIdx.x * 256 + threadIdx.x) >> 5;
    int lane = threadIdx.x & 31;
    if (w >= NGG * NN) return;
    int g = w / NN, c = w - g * NN;
    const float4* Xg = (const float4*)(x + (size_t)g * NN * CC);

    float4 xc = Xg[(size_t)c * 32 + lane];
    float4 acc[4];
#pragma unroll
    for (int l = 0; l < 4; l++) {
        float d = g_deg[(g * 4 + l) * NN + c];
        float s = d * d;
        acc[l] = make_float4(xc.x * s, xc.y * s, xc.z * s, xc.w * s);
    }
    int start = g_off[g * NN + c];
    int cnt = g_cntn[g * NN + c];
    const int* csr = g_csr + (size_t)g * EE;
    const float4* en = (const float4*)(g_enorm + (size_t)g * EE * 4);
    for (int j = 0; j < cnt; j++) {
        int r = csr[start + j];
        float4 nm = en[start + j];
        float4 h = Xg[(size_t)r * 32 + lane];
        acc[0].x += nm.x * h.x; acc[0].y += nm.x * h.y; acc[0].z += nm.x * h.z; acc[0].w += nm.x * h.w;
        acc[1].x += nm.y * h.x; acc[1].y += nm.y * h.y; acc[1].z += nm.y * h.z; acc[1].w += nm.y * h.w;
        acc[2].x += nm.z * h.x; acc[2].y += nm.z * h.y; acc[2].z += nm.z * h.z; acc[2].w += nm.z * h.w;
        acc[3].x += nm.w * h.x; acc[3].y += nm.w * h.y; acc[3].z += nm.w * h.z; acc[3].w += nm.w * h.w;
    }
#pragma unroll
    for (int l = 0; l < 4; l++)
        ((float4*)(g_Z + ((size_t)(g * 4 + l) * NN + c) * CC))[lane] = acc[l];
}

// ---------------- O[gi] = Z[gi] @ gcn_W[layer] ----------------
__global__ void __launch_bounds__(256) k_gemm_O(const float* __restrict__ gW) {
    __shared__ float sA[64 * 32];
    __shared__ float sB[32 * 128];
    int gi = blockIdx.y, l = gi & 3;
    int row0 = blockIdx.x * 64;
    int tx = threadIdx.x, ty = threadIdx.y;
    int tid = ty * 32 + tx;
    const float4* Av = (const float4*)(g_Z + (size_t)gi * NN * CC);
    const float4* Bv = (const float4*)(gW + (size_t)l * CC * CC);
    float acc[8][4];
#pragma unroll
    for (int j = 0; j < 8; j++) { acc[j][0]=0;acc[j][1]=0;acc[j][2]=0;acc[j][3]=0; }
    for (int kc = 0; kc < 4; kc++) {
        __syncthreads();
#pragma unroll
        for (int it = 0; it < 4; it++)
            ((float4*)sB)[it * 256 + tid] = Bv[kc * 1024 + it * 256 + tid];
#pragma unroll
        for (int it = 0; it < 2; it++) {
            int idx = it * 256 + tid;
            int m = idx >> 3, kq = idx & 7;
            int gm = row0 + m;
            float4 v = make_float4(0.f, 0.f, 0.f, 0.f);
            if (gm < NN) v = Av[(size_t)gm * 32 + kc * 8 + kq];
            ((float4*)sA)[idx] = v;
        }
        __syncthreads();
#pragma unroll
        for (int k = 0; k < 32; k++) {
            float4 b = ((float4*)sB)[k * 32 + tx];
#pragma unroll
            for (int j = 0; j < 8; j++) {
                float a = sA[(ty * 8 + j) * 32 + k];
                acc[j][0] += a * b.x; acc[j][1] += a * b.y;
                acc[j][2] += a * b.z; acc[j][3] += a * b.w;
            }
        }
    }
#pragma unroll
    for (int j = 0; j < 8; j++) {
        int gm = row0 + ty * 8 + j;
        if (gm < NN)
            ((float4*)(g_O + ((size_t)gi * NN + gm) * CC))[tx] =
                make_float4(acc[j][0], acc[j][1], acc[j][2], acc[j][3]);
    }
}

// ---------------- feats[g] = sum_l relu(O[g,l]+b[l]) @ Ws[l] ----------------
__global__ void __launch_bounds__(256) k_feats(const float* __restrict__ Wsm,
                                               const float* __restrict__ gb) {
    __shared__ float sA[64 * 32];
    __shared__ float sB[32 * 128];
    int g = blockIdx.y;
    int row0 = blockIdx.x * 64;
    int tx = threadIdx.x, ty = threadIdx.y;
    int tid = ty * 32 + tx;
    float acc[8][4];
#pragma unroll
    for (int j = 0; j < 8; j++) { acc[j][0]=0;acc[j][1]=0;acc[j][2]=0;acc[j][3]=0; }
    for (int l = 0; l < 4; l++) {
        const float4* Bv = (const float4*)(Wsm + (size_t)l * CC * CC);
        const float4* bb = (const float4*)(gb + l * CC);
        const float4* Ov = (const float4*)(g_O + (size_t)(g * 4 + l) * NN * CC);
        for (int kc = 0; kc < 4; kc++) {
            __syncthreads();
#pragma unroll
            for (int it = 0; it < 4; it++)
                ((float4*)sB)[it * 256 + tid] = Bv[kc * 1024 + it * 256 + tid];
#pragma unroll
            for (int it = 0; it < 2; it++) {
                int idx = it * 256 + tid;
                int m = idx >> 3, kq = idx & 7;
                int gm = row0 + m;
                float4 v = make_float4(0.f, 0.f, 0.f, 0.f);
                if (gm < NN) {
                    float4 o = Ov[(size_t)gm * 32 + kc * 8 + kq];
                    float4 b = bb[kc * 8 + kq];
                    v = make_float4(fmaxf(o.x + b.x, 0.f), fmaxf(o.y + b.y, 0.f),
                                    fmaxf(o.z + b.z, 0.f), fmaxf(o.w + b.w, 0.f));
                }
                ((float4*)sA)[idx] = v;
            }
            __syncthreads();
#pragma unroll
            for (int k = 0; k < 32; k++) {
                float4 b = ((float4*)sB)[k * 32 + tx];
#pragma unroll
                for (int j = 0; j < 8; j++) {
                    float a = sA[(ty * 8 + j) * 32 + k];
                    acc[j][0] += a * b.x; acc[j][1] += a * b.y;
                    acc[j][2] += a * b.z; acc[j][3] += a * b.w;
                }
            }
        }
    }
#pragma unroll
    for (int j = 0; j < 8; j++) {
        int gm = row0 + ty * 8 + j;
        if (gm < NN)
            ((float4*)(g_feats + ((size_t)g * NN + gm) * CC))[tx] =
                make_float4(acc[j][0], acc[j][1], acc[j][2], acc[j][3]);
    }
}

// ---------------- g_matrix ----------------
__global__ void k_gmatrix(float* __restrict__ out) {
    int g = blockIdx.x, c = threadIdx.x;
    const float* p = g_feats + (size_t)g * NN * CC + c;
    float s0 = 0.f, s1 = 0.f, s2 = 0.f, s3 = 0.f;
    for (int n = 0; n < NN; n += 4) {
        s0 += p[(size_t)(n + 0) * CC];
        s1 += p[(size_t)(n + 1) * CC];
        s2 += p[(size_t)(n + 2) * CC];
        s3 += p[(size_t)(n + 3) * CC];
    }
    out[g * CC + c] = (s0 + s1 + s2 + s3) / (float)NN;
}

// ---------------- normalize rows -> bf16 (padded layout) ----------------
__global__ void k_norm() {
    int w = (blockIdx.x * 256 + threadIdx.x) >> 5;
    int lane = threadIdx.x & 31;
    if (w >= NGG * NN) return;
    int g = w / NN, node = w - g * NN;
    float4 v = ((const float4*)g_feats)[(size_t)w * 32 + lane];
    float ss = v.x * v.x + v.y * v.y + v.z * v.z + v.w * v.w;
#pragma unroll
    for (int o = 16; o; o >>= 1) ss += __shfl_xor_sync(0xffffffffu, ss, o);
    float inv = 1.0f / fmaxf(sqrtf(ss), 1e-12f);
    __nv_bfloat162 b0 = __floats2bfloat162_rn(v.x * inv, v.y * inv);
    __nv_bfloat162 b1 = __floats2bfloat162_rn(v.z * inv, v.w * inv);
    uint2 pk;
    pk.x = *(uint32_t*)&b0;
    pk.y = *(uint32_t*)&b1;
    ((uint2*)(g_xnb + ((size_t)g * NROWP + node) * CC))[lane] = pk;
}

// ---------------- sim: A tile resident, loop over column tiles ----------------
// grid (47 bx, 21 pairs). Per block: load A (128 rows, full K=128, 32KB) once;
// for each by, stream B in 4 K=32 chunks (128x80B padded rows), mma, bin.
__global__ void __launch_bounds__(256, 2) k_sim() {
    __shared__ __nv_bfloat16 sA[2][128 * 64];  // two SW128 K=64 chunks (32KB)
    __shared__ __nv_bfloat16 sB[128 * 40];     // K=32 chunk, rows padded to 80B
    __shared__ float s_bnd[22];
    __shared__ unsigned s_part[8];

    int p = blockIdx.y;
    int i1 = cP1[p], i2 = cP2[p];
    int bx = blockIdx.x;
    bool diag = (i1 == i2);
    int byStart = diag ? bx : 0;

    int tid = threadIdx.x;
    int lane = tid & 31, wid = tid >> 5;
    int wm = wid & 3, wn = wid >> 2;           // warp tile: rows wm*32, cols wn*64
    if (tid < 22) s_bnd[tid] = c_bnd[tid];

    int row0 = bx * 128;
    const __nv_bfloat16* A = g_xnb + (size_t)i1 * NROWP * CC;
    const __nv_bfloat16* B = g_xnb + (size_t)i2 * NROWP * CC;
    uint32_t baseA = smem_u32(sA), baseB = smem_u32(sB);

    // load resident A: 2048 uint4 slots
#pragma unroll
    for (int it = 0; it < 8; it++) {
        int idx = it * 256 + tid;
        int kc = idx >> 10, rem = idx & 1023;
        int r = rem >> 3, q = rem & 7;
        uint32_t sw = (uint32_t)(kc * 16384) + SWZ128((uint32_t)(r * 128 + q * 16));
        *(uint4*)((uint8_t*)sA + sw) =
            *(const uint4*)(A + (size_t)(row0 + r) * CC + kc * 64 + q * 8);
    }

    unsigned total = 0;
    for (int by = byStart; by < 47; by++) {
        unsigned wgt = (diag && by > bx) ? 2u : 1u;
        int col0 = by * 128;
        float acc[2][8][4];
#pragma unroll
        for (int mt = 0; mt < 2; mt++)
#pragma unroll
            for (int nt = 0; nt < 8; nt++) {
                acc[mt][nt][0] = 0.f; acc[mt][nt][1] = 0.f;
                acc[mt][nt][2] = 0.f; acc[mt][nt][3] = 0.f;
            }
#pragma unroll
        for (int bc = 0; bc < 4; bc++) {
            __syncthreads();                   // prior reads done before overwrite
#pragma unroll
            for (int it = 0; it < 2; it++) {
                int idx = it * 256 + tid;      // 512 uint4 slots
                int r = idx >> 2, q = idx & 3;
                *(uint4*)((uint8_t*)sB + r * 80 + q * 16) =
                    *(const uint4*)(B + (size_t)(col0 + r) * CC + bc * 32 + q * 8);
            }
            __syncthreads();
#pragma unroll
            for (int ks = 0; ks < 2; ks++) {
                int kg = bc * 32 + ks * 16;
                int akc = kg >> 6, akb = (kg & 63) * 2;
                uint32_t a[2][4];
#pragma unroll
                for (int mt = 0; mt < 2; mt++) {
                    int r = wm * 32 + mt * 16 + (lane & 15);
                    uint32_t ad = baseA + akc * 16384 +
                        SWZ128((uint32_t)(r * 128 + akb + (lane >> 4) * 16));
                    asm volatile("ldmatrix.sync.aligned.m8n8.x4.shared.b16 {%0,%1,%2,%3}, [%4];"
                        : "=r"(a[mt][0]), "=r"(a[mt][1]), "=r"(a[mt][2]), "=r"(a[mt][3])
                        : "r"(ad));
                }
                uint32_t b[4][4];
#pragma unroll
                for (int np = 0; np < 4; np++) {
                    int r = wn * 64 + np * 16 + (lane & 7) + ((lane >> 4) << 3);
                    uint32_t bd = baseB + (uint32_t)(r * 80 + ks * 32 + ((lane >> 3) & 1) * 16);
                    asm volatile("ldmatrix.sync.aligned.m8n8.x4.shared.b16 {%0,%1,%2,%3}, [%4];"
                        : "=r"(b[np][0]), "=r"(b[np][1]), "=r"(b[np][2]), "=r"(b[np][3])
                        : "r"(bd));
                }
#pragma unroll
                for (int mt = 0; mt < 2; mt++)
#pragma unroll
                    for (int nt = 0; nt < 8; nt++) {
                        asm volatile(
                            "mma.sync.aligned.m16n8k16.row.col.f32.bf16.bf16.f32 "
                            "{%0,%1,%2,%3}, {%4,%5,%6,%7}, {%8,%9}, {%0,%1,%2,%3};"
                            : "+f"(acc[mt][nt][0]), "+f"(acc[mt][nt][1]),
                              "+f"(acc[mt][nt][2]), "+f"(acc[mt][nt][3])
                            : "r"(a[mt][0]), "r"(a[mt][1]), "r"(a[mt][2]), "r"(a[mt][3]),
                              "r"(b[nt >> 1][(nt & 1) * 2]), "r"(b[nt >> 1][(nt & 1) * 2 + 1]));
                    }
            }
        }
        // bin accumulators (position-independent)
        int sum = 0;
#pragma unroll
        for (int mt = 0; mt < 2; mt++)
#pragma unroll
            for (int nt = 0; nt < 8; nt++)
#pragma unroll
                for (int v = 0; v < 4; v++) {
                    float s = acc[mt][nt][v];
                    float t;
                    asm("tanh.approx.f32 %0, %1;" : "=f"(t) : "f"(s));
                    int idx = __float2int_rd(fmaf(t, 10.5f, 10.5f));
                    idx = max(0, min(20, idx));
                    idx += (s >= s_bnd[idx + 1]) ? 1 : 0;
                    idx -= (s <  s_bnd[idx]) ? 1 : 0;
                    sum += idx;
                }
        total += wgt * (unsigned)sum;
    }
#pragma unroll
    for (int o = 16; o; o >>= 1) total += __shfl_xor_sync(0xffffffffu, total, o);
    if (lane == 0) s_part[wid] = total;
    __syncthreads();
    if (tid == 0) {
        unsigned tot = 0;
#pragma unroll
        for (int i = 0; i < 8; i++) tot += s_part[i];
        atomicAdd(&g_cnt[p], tot);
    }
}

// ---------------- finalize ----------------
__global__ void k_final(float* __restrict__ out) {
    int p = threadIdx.x;
    if (p < NPAIR) {
        // pads: 6016^2 - 6000^2 = 192256 zero-dots, each binned at idx=10
        double cnt = (double)g_cnt[p] - 10.0 * 192256.0;
        double v = -1.0 + 0.1 * cnt / ((double)NN * (double)NN);
        out[NGG * CC + cP1[p] * NGG + cP2[p]] = (float)v;
        out[NGG * CC + cP2[p] * NGG + cP1[p]] = (float)v;
    }
}

// ---------------- launch ----------------
extern "C" void kernel_launch(void* const* d_in, const int* in_sizes, int n_in,
                              void* d_out, int out_size) {
    const float* x   = (const float*)d_in[0];
    const int* ei    = (const int*)d_in[1];
    const float* ea  = (const float*)d_in[2];
    const float* gW  = (const float*)d_in[3];
    const float* gb  = (const float*)d_in[4];
    const float* Wsm = (const float*)d_in[5];
    float* out = (float*)d_out;

    k_setup<<<(NGI * NN + 255) / 256, 256>>>();
    k_deg<<<(NGG * EE + 255) / 256, 256>>>(ei, ea);
    k_dis<<<(NGI * NN + 255) / 256, 256>>>();
    k_scan<<<NGG, 256>>>();
    k_fill<<<(NGG * EE + 255) / 256, 256>>>(ei, ea);
    k_gather<<<(NGG * NN + 7) / 8, 256>>>(x);
    k_gemm_O<<<dim3(94, NGI), dim3(32, 8)>>>(gW);
    k_feats<<<dim3(94, NGG), dim3(32, 8)>>>(Wsm, gb);
    k_gmatrix<<<NGG, 128>>>(out);
    k_norm<<<(NGG * NN) / 8, 256>>>();
    k_sim<<<dim3(47, NPAIR), 256>>>();
    k_final<<<1, 32>>>(out);
}

// round 8
// speedup vs baseline: 5.3945x; 1.1803x over previous
#include <cuda_runtime.h>
#include <cuda_bf16.h>
#include <cstdint>

#define NGG 6
#define NN 6000
#define EE 96000
#define CC 128
#define NGI 24       // NGG * 4 layers
#define NPAIR 21
#define NROWP 6016   // NN padded to multiple of 128

// ---------------- device scratch ----------------
__device__ float g_deg[NGI * NN];                 // weighted deg -> dis (in place)
__device__ int   g_cntn[NGG * NN];                // in-edge count per node
__device__ int   g_off[NGG * NN];                 // CSR start offsets
__device__ int   g_cur[NGG * NN];                 // fill cursors
__device__ int   g_csr[NGG * EE];                 // source node per CSR slot
__device__ float g_enorm[(size_t)NGG * EE * 4];   // per-edge per-layer norm coeff
__device__ float g_Z[(size_t)NGI * NN * CC];      // gathered x (pre-GEMM), per (g,l)
__device__ float g_O[(size_t)NGI * NN * CC];      // Z @ W per (g,l)
__device__ float g_feats[(size_t)NGG * NN * CC];
__device__ float g_gm[NGG * 4 * CC];              // g_matrix partial sums
__device__ __nv_bfloat16 g_xnb[(size_t)NGG * NROWP * CC];
__device__ unsigned int g_cnt[NPAIR];

__constant__ int cP1[NPAIR] = {0,0,0,0,0,0, 1,1,1,1,1, 2,2,2,2, 3,3,3, 4,4, 5};
__constant__ int cP2[NPAIR] = {0,1,2,3,4,5, 1,2,3,4,5, 2,3,4,5, 3,4,5, 4,5, 5};

// s-space bin boundaries: bnd[k] = atanh(k/10.5 - 1), k=1..20; sentinels at ends
__constant__ float c_bnd[22] = {
    -3e38f,
    -1.49786614f, -1.12564590f, -0.89587974f, -0.72345949f, -0.58157540f,
    -0.45814537f, -0.34657359f, -0.24275391f, -0.14384104f, -0.04765509f,
     0.04765509f,  0.14384104f,  0.24275391f,  0.34657359f,  0.45814537f,
     0.58157540f,  0.72345949f,  0.89587974f,  1.12564590f,  1.49786614f,
     3e38f };

__device__ __forceinline__ uint32_t smem_u32(const void* p) {
    uint32_t a;
    asm("{ .reg .u64 t; cvta.to.shared.u64 t, %1; cvt.u32.u64 %0, t; }"
        : "=r"(a) : "l"(p));
    return a;
}
#define SWZ128(off) ((off) ^ (((off) >> 3) & 0x70))

// ---------------- setup ----------------
__global__ void k_setup() {
    int i = blockIdx.x * blockDim.x + threadIdx.x;
    if (i < NGI * NN) g_deg[i] = 1.0f;          // self-loop weight
    if (i < NGG * NN) g_cntn[i] = 0;
    if (i < NPAIR) g_cnt[i] = 0u;
    if (i < NGG * 16 * CC) {
        int g = i / (16 * CC), rem = i - g * (16 * CC);
        g_xnb[((size_t)g * NROWP + NN) * CC + rem] = __float2bfloat16(0.f);
    }
}

// ---------------- per-node in-degree count + weighted degree ----------------
__global__ void k_deg(const int* __restrict__ ei, const float* __restrict__ ea) {
    int i = blockIdx.x * blockDim.x + threadIdx.x;
    if (i >= NGG * EE) return;
    int g = i / EE, e = i - g * EE;
    int c = ei[(size_t)g * 2 * EE + EE + e];
    const float* w = ea + ((size_t)g * EE + e) * 6;
    atomicAdd(&g_cntn[g * NN + c], 1);
#pragma unroll
    for (int l = 0; l < 4; l++)
        atomicAdd(&g_deg[(g * 4 + l) * NN + c], w[2 + l]);
}

__global__ void k_dis() {
    int i = blockIdx.x * blockDim.x + threadIdx.x;
    if (i < NGI * NN) g_deg[i] = rsqrtf(g_deg[i]);
}

// ---------------- CSR offsets: block per graph, scan 6000 counts ----------------
__global__ void __launch_bounds__(256) k_scan() {
    __shared__ int ps[256];
    int g = blockIdx.x, t = threadIdx.x;
    const int PT = 24;                    // 250 threads * 24 = 6000
    int loc[PT];
    int s = 0;
    if (t < 250) {
        int base = g * NN + t * PT;
#pragma unroll
        for (int i = 0; i < PT; i++) { loc[i] = g_cntn[base + i]; s += loc[i]; }
    }
    ps[t] = s;
    __syncthreads();
    for (int o = 1; o < 256; o <<= 1) {
        int v = (t >= o) ? ps[t - o] : 0;
        __syncthreads();
        ps[t] += v;
        __syncthreads();
    }
    if (t < 250) {
        int run = ps[t] - s;              // exclusive prefix
        int base = g * NN + t * PT;
#pragma unroll
        for (int i = 0; i < PT; i++) {
            g_off[base + i] = run;
            g_cur[base + i] = run;
            run += loc[i];
        }
    }
}

// ---------------- CSR fill + per-edge norm coefficients ----------------
__global__ void k_fill(const int* __restrict__ ei, const float* __restrict__ ea) {
    int i = blockIdx.x * blockDim.x + threadIdx.x;
    if (i >= NGG * EE) return;
    int g = i / EE, e = i - g * EE;
    int r = ei[(size_t)g * 2 * EE + e];
    int c = ei[(size_t)g * 2 * EE + EE + e];
    int pos = atomicAdd(&g_cur[g * NN + c], 1);
    g_csr[g * EE + pos] = r;
    const float* w = ea + ((size_t)g * EE + e) * 6;
    float4 nm;
    nm.x = g_deg[(g * 4 + 0) * NN + r] * w[2] * g_deg[(g * 4 + 0) * NN + c];
    nm.y = g_deg[(g * 4 + 1) * NN + r] * w[3] * g_deg[(g * 4 + 1) * NN + c];
    nm.z = g_deg[(g * 4 + 2) * NN + r] * w[4] * g_deg[(g * 4 + 2) * NN + c];
    nm.w = g_deg[(g * 4 + 3) * NN + r] * w[5] * g_deg[(g * 4 + 3) * NN + c];
    *(float4*)&g_enorm[((size_t)g * EE + pos) * 4] = nm;
}

// ---------------- gather raw x:  Z_l[c] = dis_l[c]^2 x[c] + sum_in nrm_l x[r] --
__global__ void __launch_bounds__(256) k_gather(const float* __restrict__ x) {
    int w = (blockIdx.x * 256 + threadIdx.x) >> 5;
    int lane = threadIdx.x & 31;
    if (w >= NGG * NN) return;
    int g = w / NN, c = w - g * NN;
    const float4* Xg = (const float4*)(x + (size_t)g * NN * CC);

    float4 xc = Xg[(size_t)c * 32 + lane];
    float4 acc[4];
#pragma unroll
    for (int l = 0; l < 4; l++) {
        float d = g_deg[(g * 4 + l) * NN + c];
        float s = d * d;
        acc[l] = make_float4(xc.x * s, xc.y * s, xc.z * s, xc.w * s);
    }
    int start = g_off[g * NN + c];
    int cnt = g_cntn[g * NN + c];
    const int* csr = g_csr + (size_t)g * EE;
    const float4* en = (const float4*)(g_enorm + (size_t)g * EE * 4);
#pragma unroll 4
    for (int j = 0; j < cnt; j++) {
        int r = __ldg(&csr[start + j]);
        float4 nm = __ldg(&en[start + j]);
        float4 h = Xg[(size_t)r * 32 + lane];
        acc[0].x += nm.x * h.x; acc[0].y += nm.x * h.y; acc[0].z += nm.x * h.z; acc[0].w += nm.x * h.w;
        acc[1].x += nm.y * h.x; acc[1].y += nm.y * h.y; acc[1].z += nm.y * h.z; acc[1].w += nm.y * h.w;
        acc[2].x += nm.z * h.x; acc[2].y += nm.z * h.y; acc[2].z += nm.z * h.z; acc[2].w += nm.z * h.w;
        acc[3].x += nm.w * h.x; acc[3].y += nm.w * h.y; acc[3].z += nm.w * h.z; acc[3].w += nm.w * h.w;
    }
#pragma unroll
    for (int l = 0; l < 4; l++)
        ((float4*)(g_Z + ((size_t)(g * 4 + l) * NN + c) * CC))[lane] = acc[l];
}

// ---------------- O[gi] = Z[gi] @ gcn_W[layer] ----------------
__global__ void __launch_bounds__(256) k_gemm_O(const float* __restrict__ gW) {
    __shared__ float sA[64 * 32];
    __shared__ float sB[32 * 128];
    int gi = blockIdx.y, l = gi & 3;
    int row0 = blockIdx.x * 64;
    int tx = threadIdx.x, ty = threadIdx.y;
    int tid = ty * 32 + tx;
    const float4* Av = (const float4*)(g_Z + (size_t)gi * NN * CC);
    const float4* Bv = (const float4*)(gW + (size_t)l * CC * CC);
    float acc[8][4];
#pragma unroll
    for (int j = 0; j < 8; j++) { acc[j][0]=0;acc[j][1]=0;acc[j][2]=0;acc[j][3]=0; }
    for (int kc = 0; kc < 4; kc++) {
        __syncthreads();
#pragma unroll
        for (int it = 0; it < 4; it++)
            ((float4*)sB)[it * 256 + tid] = Bv[kc * 1024 + it * 256 + tid];
#pragma unroll
        for (int it = 0; it < 2; it++) {
            int idx = it * 256 + tid;
            int m = idx >> 3, kq = idx & 7;
            int gm = row0 + m;
            float4 v = make_float4(0.f, 0.f, 0.f, 0.f);
            if (gm < NN) v = Av[(size_t)gm * 32 + kc * 8 + kq];
            ((float4*)sA)[idx] = v;
        }
        __syncthreads();
#pragma unroll
        for (int k = 0; k < 32; k++) {
            float4 b = ((float4*)sB)[k * 32 + tx];
#pragma unroll
            for (int j = 0; j < 8; j++) {
                float a = sA[(ty * 8 + j) * 32 + k];
                acc[j][0] += a * b.x; acc[j][1] += a * b.y;
                acc[j][2] += a * b.z; acc[j][3] += a * b.w;
            }
        }
    }
#pragma unroll
    for (int j = 0; j < 8; j++) {
        int gm = row0 + ty * 8 + j;
        if (gm < NN)
            ((float4*)(g_O + ((size_t)gi * NN + gm) * CC))[tx] =
                make_float4(acc[j][0], acc[j][1], acc[j][2], acc[j][3]);
    }
}

// ---------------- feats[g] = sum_l relu(O[g,l]+b[l]) @ Ws[l] ----------------
__global__ void __launch_bounds__(256) k_feats(const float* __restrict__ Wsm,
                                               const float* __restrict__ gb) {
    __shared__ float sA[64 * 32];
    __shared__ float sB[32 * 128];
    int g = blockIdx.y;
    int row0 = blockIdx.x * 64;
    int tx = threadIdx.x, ty = threadIdx.y;
    int tid = ty * 32 + tx;
    float acc[8][4];
#pragma unroll
    for (int j = 0; j < 8; j++) { acc[j][0]=0;acc[j][1]=0;acc[j][2]=0;acc[j][3]=0; }
    for (int l = 0; l < 4; l++) {
        const float4* Bv = (const float4*)(Wsm + (size_t)l * CC * CC);
        const float4* bb = (const float4*)(gb + l * CC);
        const float4* Ov = (const float4*)(g_O + (size_t)(g * 4 + l) * NN * CC);
        for (int kc = 0; kc < 4; kc++) {
            __syncthreads();
#pragma unroll
            for (int it = 0; it < 4; it++)
                ((float4*)sB)[it * 256 + tid] = Bv[kc * 1024 + it * 256 + tid];
#pragma unroll
            for (int it = 0; it < 2; it++) {
                int idx = it * 256 + tid;
                int m = idx >> 3, kq = idx & 7;
                int gm = row0 + m;
                float4 v = make_float4(0.f, 0.f, 0.f, 0.f);
                if (gm < NN) {
                    float4 o = Ov[(size_t)gm * 32 + kc * 8 + kq];
                    float4 b = bb[kc * 8 + kq];
                    v = make_float4(fmaxf(o.x + b.x, 0.f), fmaxf(o.y + b.y, 0.f),
                                    fmaxf(o.z + b.z, 0.f), fmaxf(o.w + b.w, 0.f));
                }
                ((float4*)sA)[idx] = v;
            }
            __syncthreads();
#pragma unroll
            for (int k = 0; k < 32; k++) {
                float4 b = ((float4*)sB)[k * 32 + tx];
#pragma unroll
                for (int j = 0; j < 8; j++) {
                    float a = sA[(ty * 8 + j) * 32 + k];
                    acc[j][0] += a * b.x; acc[j][1] += a * b.y;
                    acc[j][2] += a * b.z; acc[j][3] += a * b.w;
                }
            }
        }
    }
#pragma unroll
    for (int j = 0; j < 8; j++) {
        int gm = row0 + ty * 8 + j;
        if (gm < NN)
            ((float4*)(g_feats + ((size_t)g * NN + gm) * CC))[tx] =
                make_float4(acc[j][0], acc[j][1], acc[j][2], acc[j][3]);
    }
}

// ---------------- g_matrix partial sums: grid (NGG, 4) ----------------
__global__ void k_gmpart() {
    int g = blockIdx.x, q = blockIdx.y, c = threadIdx.x;
    const float* p = g_feats + (size_t)g * NN * CC + (size_t)q * 1500 * CC + c;
    float s0 = 0.f, s1 = 0.f, s2 = 0.f, s3 = 0.f;
    for (int n = 0; n < 1500; n += 4) {
        s0 += p[(size_t)(n + 0) * CC];
        s1 += p[(size_t)(n + 1) * CC];
        s2 += p[(size_t)(n + 2) * CC];
        s3 += p[(size_t)(n + 3) * CC];
    }
    g_gm[(g * 4 + q) * CC + c] = (s0 + s1) + (s2 + s3);
}

// ---------------- normalize rows -> bf16 (padded layout) ----------------
__global__ void k_norm() {
    int w = (blockIdx.x * 256 + threadIdx.x) >> 5;
    int lane = threadIdx.x & 31;
    if (w >= NGG * NN) return;
    int g = w / NN, node = w - g * NN;
    float4 v = ((const float4*)g_feats)[(size_t)w * 32 + lane];
    float ss = v.x * v.x + v.y * v.y + v.z * v.z + v.w * v.w;
#pragma unroll
    for (int o = 16; o; o >>= 1) ss += __shfl_xor_sync(0xffffffffu, ss, o);
    float inv = 1.0f / fmaxf(sqrtf(ss), 1e-12f);
    __nv_bfloat162 b0 = __floats2bfloat162_rn(v.x * inv, v.y * inv);
    __nv_bfloat162 b1 = __floats2bfloat162_rn(v.z * inv, v.w * inv);
    uint2 pk;
    pk.x = *(uint32_t*)&b0;
    pk.y = *(uint32_t*)&b1;
    ((uint2*)(g_xnb + ((size_t)g * NROWP + node) * CC))[lane] = pk;
}

// ---------------- sim: A tile resident, loop over column tiles ----------------
// grid (47 bx, 21 pairs). Per block: load A (128 rows, full K=128, 32KB) once;
// for each by, stream B in 4 K=32 chunks (128x80B padded rows), mma, bin.
__global__ void __launch_bounds__(256, 2) k_sim() {
    __shared__ __nv_bfloat16 sA[2][128 * 64];  // two SW128 K=64 chunks (32KB)
    __shared__ __nv_bfloat16 sB[128 * 40];     // K=32 chunk, rows padded to 80B
    __shared__ float s_bnd[22];
    __shared__ unsigned s_part[8];

    int p = blockIdx.y;
    int i1 = cP1[p], i2 = cP2[p];
    int bx = blockIdx.x;
    bool diag = (i1 == i2);
    int byStart = diag ? bx : 0;

    int tid = threadIdx.x;
    int lane = tid & 31, wid = tid >> 5;
    int wm = wid & 3, wn = wid >> 2;           // warp tile: rows wm*32, cols wn*64
    if (tid < 22) s_bnd[tid] = c_bnd[tid];

    int row0 = bx * 128;
    const __nv_bfloat16* A = g_xnb + (size_t)i1 * NROWP * CC;
    const __nv_bfloat16* B = g_xnb + (size_t)i2 * NROWP * CC;
    uint32_t baseA = smem_u32(sA), baseB = smem_u32(sB);

    // load resident A: 2048 uint4 slots
#pragma unroll
    for (int it = 0; it < 8; it++) {
        int idx = it * 256 + tid;
        int kc = idx >> 10, rem = idx & 1023;
        int r = rem >> 3, q = rem & 7;
        uint32_t sw = (uint32_t)(kc * 16384) + SWZ128((uint32_t)(r * 128 + q * 16));
        *(uint4*)((uint8_t*)sA + sw) =
            *(const uint4*)(A + (size_t)(row0 + r) * CC + kc * 64 + q * 8);
    }

    unsigned total = 0;
    for (int by = byStart; by < 47; by++) {
        unsigned wgt = (diag && by > bx) ? 2u : 1u;
        int col0 = by * 128;
        float acc[2][8][4];
#pragma unroll
        for (int mt = 0; mt < 2; mt++)
#pragma unroll
            for (int nt = 0; nt < 8; nt++) {
                acc[mt][nt][0] = 0.f; acc[mt][nt][1] = 0.f;
                acc[mt][nt][2] = 0.f; acc[mt][nt][3] = 0.f;
            }
#pragma unroll
        for (int bc = 0; bc < 4; bc++) {
            __syncthreads();                   // prior reads done before overwrite
#pragma unroll
            for (int it = 0; it < 2; it++) {
                int idx = it * 256 + tid;      // 512 uint4 slots
                int r = idx >> 2, q = idx & 3;
                *(uint4*)((uint8_t*)sB + r * 80 + q * 16) =
                    *(const uint4*)(B + (size_t)(col0 + r) * CC + bc * 32 + q * 8);
            }
            __syncthreads();
#pragma unroll
            for (int ks = 0; ks < 2; ks++) {
                int kg = bc * 32 + ks * 16;
                int akc = kg >> 6, akb = (kg & 63) * 2;
                uint32_t a[2][4];
#pragma unroll
                for (int mt = 0; mt < 2; mt++) {
                    int r = wm * 32 + mt * 16 + (lane & 15);
                    uint32_t ad = baseA + akc * 16384 +
                        SWZ128((uint32_t)(r * 128 + akb + (lane >> 4) * 16));
                    asm volatile("ldmatrix.sync.aligned.m8n8.x4.shared.b16 {%0,%1,%2,%3}, [%4];"
                        : "=r"(a[mt][0]), "=r"(a[mt][1]), "=r"(a[mt][2]), "=r"(a[mt][3])
                        : "r"(ad));
                }
                uint32_t b[4][4];
#pragma unroll
                for (int np = 0; np < 4; np++) {
                    int r = wn * 64 + np * 16 + (lane & 7) + ((lane >> 4) << 3);
                    uint32_t bd = baseB + (uint32_t)(r * 80 + ks * 32 + ((lane >> 3) & 1) * 16);
                    asm volatile("ldmatrix.sync.aligned.m8n8.x4.shared.b16 {%0,%1,%2,%3}, [%4];"
                        : "=r"(b[np][0]), "=r"(b[np][1]), "=r"(b[np][2]), "=r"(b[np][3])
                        : "r"(bd));
                }
#pragma unroll
                for (int mt = 0; mt < 2; mt++)
#pragma unroll
                    for (int nt = 0; nt < 8; nt++) {
                        asm volatile(
                            "mma.sync.aligned.m16n8k16.row.col.f32.bf16.bf16.f32 "
                            "{%0,%1,%2,%3}, {%4,%5,%6,%7}, {%8,%9}, {%0,%1,%2,%3};"
                            : "+f"(acc[mt][nt][0]), "+f"(acc[mt][nt][1]),
                              "+f"(acc[mt][nt][2]), "+f"(acc[mt][nt][3])
                            : "r"(a[mt][0]), "r"(a[mt][1]), "r"(a[mt][2]), "r"(a[mt][3]),
                              "r"(b[nt >> 1][(nt & 1) * 2]), "r"(b[nt >> 1][(nt & 1) * 2 + 1]));
                    }
            }
        }
        // bin accumulators. idx_true = #{j: s >= bnd[j]}. tanh.approx abs err
        // <= 6.2e-4 -> 10.5*t err <= 0.0065 << 0.07 margin, so
        // idx0 = floor(10.5*t + 10.43) satisfies idx_true in {idx0, idx0+1};
        // one exact compare resolves it. idx0=-1 hits the -3e38 sentinel -> 0.
        int sum = 0;
#pragma unroll
        for (int mt = 0; mt < 2; mt++)
#pragma unroll
            for (int nt = 0; nt < 8; nt++)
#pragma unroll
                for (int v = 0; v < 4; v++) {
                    float s = acc[mt][nt][v];
                    float t;
                    asm("tanh.approx.f32 %0, %1;" : "=f"(t) : "f"(s));
                    int idx = __float2int_rd(fmaf(t, 10.5f, 10.43f));
                    sum += idx + ((s >= s_bnd[idx + 1]) ? 1 : 0);
                }
        total += wgt * (unsigned)sum;
    }
#pragma unroll
    for (int o = 16; o; o >>= 1) total += __shfl_xor_sync(0xffffffffu, total, o);
    if (lane == 0) s_part[wid] = total;
    __syncthreads();
    if (tid == 0) {
        unsigned tot = 0;
#pragma unroll
        for (int i = 0; i < 8; i++) tot += s_part[i];
        atomicAdd(&g_cnt[p], tot);
    }
}

// ---------------- finalize: g_matrix reduce + sim values ----------------
__global__ void k_final(float* __restrict__ out) {
    int t = threadIdx.x;
    if (t < NGG * CC) {
        int g = t / CC, c = t - g * CC;
        float s = (g_gm[(g * 4 + 0) * CC + c] + g_gm[(g * 4 + 1) * CC + c]) +
                  (g_gm[(g * 4 + 2) * CC + c] + g_gm[(g * 4 + 3) * CC + c]);
        out[t] = s / (float)NN;
    }
    if (t < NPAIR) {
        // pads: 6016^2 - 6000^2 = 192256 zero-dots, each binned at idx=10
        double cnt = (double)g_cnt[t] - 10.0 * 192256.0;
        double v = -1.0 + 0.1 * cnt / ((double)NN * (double)NN);
        out[NGG * CC + cP1[t] * NGG + cP2[t]] = (float)v;
        out[NGG * CC + cP2[t] * NGG + cP1[t]] = (float)v;
    }
}

// ---------------- launch ----------------
extern "C" void kernel_launch(void* const* d_in, const int* in_sizes, int n_in,
                              void* d_out, int out_size) {
    const float* x   = (const float*)d_in[0];
    const int* ei    = (const int*)d_in[1];
    const float* ea  = (const float*)d_in[2];
    const float* gW  = (const float*)d_in[3];
    const float* gb  = (const float*)d_in[4];
    const float* Wsm = (const float*)d_in[5];
    float* out = (float*)d_out;

    k_setup<<<(NGI * NN + 255) / 256, 256>>>();
    k_deg<<<(NGG * EE + 255) / 256, 256>>>(ei, ea);
    k_dis<<<(NGI * NN + 255) / 256, 256>>>();
    k_scan<<<NGG, 256>>>();
    k_fill<<<(NGG * EE + 255) / 256, 256>>>(ei, ea);
    k_gather<<<(NGG * NN + 7) / 8, 256>>>(x);
    k_gemm_O<<<dim3(94, NGI), dim3(32, 8)>>>(gW);
    k_feats<<<dim3(94, NGG), dim3(32, 8)>>>(Wsm, gb);
    k_gmpart<<<dim3(NGG, 4), 128>>>();
    k_norm<<<(NGG * NN) / 8, 256>>>();
    k_sim<<<dim3(47, NPAIR), 256>>>();
    k_final<<<1, 768>>>(out);
}

// round 9
// speedup vs baseline: 5.6379x; 1.0451x over previous
#include <cuda_runtime.h>
#include <cuda_bf16.h>
#include <cstdint>

#define NGG 6
#define NN 6000
#define EE 96000
#define CC 128
#define NGI 24       // NGG * 4 layers
#define NPAIR 21
#define NROWP 6016   // NN padded to multiple of 128
#define NBLK 94      // row tiles of 64

// ---------------- device scratch ----------------
__device__ float g_deg[NGI * NN];                 // weighted deg -> dis (in place)
__device__ int   g_cntn[NGG * NN];                // in-edge count per node
__device__ int   g_off[NGG * NN];                 // CSR start offsets
__device__ int   g_cur[NGG * NN];                 // fill cursors
__device__ int   g_csr[NGG * EE];                 // source node per CSR slot
__device__ float g_enorm[(size_t)NGG * EE * 4];   // per-edge per-layer norm coeff
__device__ float g_Z[(size_t)NGI * NN * CC];      // gathered x (pre-GEMM), per (g,l)
__device__ float g_gmp[NGG * NBLK * CC];          // g_matrix per-block partials
__device__ __nv_bfloat16 g_xnb[(size_t)NGG * NROWP * CC];
__device__ unsigned int g_cnt[NPAIR];

__constant__ int cP1[NPAIR] = {0,0,0,0,0,0, 1,1,1,1,1, 2,2,2,2, 3,3,3, 4,4, 5};
__constant__ int cP2[NPAIR] = {0,1,2,3,4,5, 1,2,3,4,5, 2,3,4,5, 3,4,5, 4,5, 5};

// s-space bin boundaries: bnd[k] = atanh(k/10.5 - 1), k=1..20; sentinels at ends
__constant__ float c_bnd[22] = {
    -3e38f,
    -1.49786614f, -1.12564590f, -0.89587974f, -0.72345949f, -0.58157540f,
    -0.45814537f, -0.34657359f, -0.24275391f, -0.14384104f, -0.04765509f,
     0.04765509f,  0.14384104f,  0.24275391f,  0.34657359f,  0.45814537f,
     0.58157540f,  0.72345949f,  0.89587974f,  1.12564590f,  1.49786614f,
     3e38f };

__device__ __forceinline__ uint32_t smem_u32(const void* p) {
    uint32_t a;
    asm("{ .reg .u64 t; cvta.to.shared.u64 t, %1; cvt.u32.u64 %0, t; }"
        : "=r"(a) : "l"(p));
    return a;
}
#define SWZ128(off) ((off) ^ (((off) >> 3) & 0x70))

// ---------------- setup ----------------
__global__ void k_setup() {
    int i = blockIdx.x * blockDim.x + threadIdx.x;
    if (i < NGI * NN) g_deg[i] = 1.0f;          // self-loop weight
    if (i < NGG * NN) g_cntn[i] = 0;
    if (i < NPAIR) g_cnt[i] = 0u;
    if (i < NGG * 16 * CC) {
        int g = i / (16 * CC), rem = i - g * (16 * CC);
        g_xnb[((size_t)g * NROWP + NN) * CC + rem] = __float2bfloat16(0.f);
    }
}

// ---------------- per-node in-degree count + weighted degree ----------------
__global__ void k_deg(const int* __restrict__ ei, const float* __restrict__ ea) {
    int i = blockIdx.x * blockDim.x + threadIdx.x;
    if (i >= NGG * EE) return;
    int g = i / EE, e = i - g * EE;
    int c = ei[(size_t)g * 2 * EE + EE + e];
    const float* w = ea + ((size_t)g * EE + e) * 6;
    atomicAdd(&g_cntn[g * NN + c], 1);
#pragma unroll
    for (int l = 0; l < 4; l++)
        atomicAdd(&g_deg[(g * 4 + l) * NN + c], w[2 + l]);
}

__global__ void k_dis() {
    int i = blockIdx.x * blockDim.x + threadIdx.x;
    if (i < NGI * NN) g_deg[i] = rsqrtf(g_deg[i]);
}

// ---------------- CSR offsets: block per graph, scan 6000 counts ----------------
__global__ void __launch_bounds__(256) k_scan() {
    __shared__ int ps[256];
    int g = blockIdx.x, t = threadIdx.x;
    const int PT = 24;                    // 250 threads * 24 = 6000
    int loc[PT];
    int s = 0;
    if (t < 250) {
        int base = g * NN + t * PT;
#pragma unroll
        for (int i = 0; i < PT; i++) { loc[i] = g_cntn[base + i]; s += loc[i]; }
    }
    ps[t] = s;
    __syncthreads();
    for (int o = 1; o < 256; o <<= 1) {
        int v = (t >= o) ? ps[t - o] : 0;
        __syncthreads();
        ps[t] += v;
        __syncthreads();
    }
    if (t < 250) {
        int run = ps[t] - s;              // exclusive prefix
        int base = g * NN + t * PT;
#pragma unroll
        for (int i = 0; i < PT; i++) {
            g_off[base + i] = run;
            g_cur[base + i] = run;
            run += loc[i];
        }
    }
}

// ---------------- CSR fill + per-edge norm coefficients ----------------
__global__ void k_fill(const int* __restrict__ ei, const float* __restrict__ ea) {
    int i = blockIdx.x * blockDim.x + threadIdx.x;
    if (i >= NGG * EE) return;
    int g = i / EE, e = i - g * EE;
    int r = ei[(size_t)g * 2 * EE + e];
    int c = ei[(size_t)g * 2 * EE + EE + e];
    int pos = atomicAdd(&g_cur[g * NN + c], 1);
    g_csr[g * EE + pos] = r;
    const float* w = ea + ((size_t)g * EE + e) * 6;
    float4 nm;
    nm.x = g_deg[(g * 4 + 0) * NN + r] * w[2] * g_deg[(g * 4 + 0) * NN + c];
    nm.y = g_deg[(g * 4 + 1) * NN + r] * w[3] * g_deg[(g * 4 + 1) * NN + c];
    nm.z = g_deg[(g * 4 + 2) * NN + r] * w[4] * g_deg[(g * 4 + 2) * NN + c];
    nm.w = g_deg[(g * 4 + 3) * NN + r] * w[5] * g_deg[(g * 4 + 3) * NN + c];
    *(float4*)&g_enorm[((size_t)g * EE + pos) * 4] = nm;
}

// ---------------- gather raw x:  Z_l[c] = dis_l[c]^2 x[c] + sum_in nrm_l x[r] --
__global__ void __launch_bounds__(256) k_gather(const float* __restrict__ x) {
    int w = (blockIdx.x * 256 + threadIdx.x) >> 5;
    int lane = threadIdx.x & 31;
    if (w >= NGG * NN) return;
    int g = w / NN, c = w - g * NN;
    const float4* Xg = (const float4*)(x + (size_t)g * NN * CC);

    float4 xc = Xg[(size_t)c * 32 + lane];
    float4 acc[4];
#pragma unroll
    for (int l = 0; l < 4; l++) {
        float d = g_deg[(g * 4 + l) * NN + c];
        float s = d * d;
        acc[l] = make_float4(xc.x * s, xc.y * s, xc.z * s, xc.w * s);
    }
    int start = g_off[g * NN + c];
    int cnt = g_cntn[g * NN + c];
    const int* csr = g_csr + (size_t)g * EE;
    const float4* en = (const float4*)(g_enorm + (size_t)g * EE * 4);
#pragma unroll 4
    for (int j = 0; j < cnt; j++) {
        int r = __ldg(&csr[start + j]);
        float4 nm = __ldg(&en[start + j]);
        float4 h = Xg[(size_t)r * 32 + lane];
        acc[0].x += nm.x * h.x; acc[0].y += nm.x * h.y; acc[0].z += nm.x * h.z; acc[0].w += nm.x * h.w;
        acc[1].x += nm.y * h.x; acc[1].y += nm.y * h.y; acc[1].z += nm.y * h.z; acc[1].w += nm.y * h.w;
        acc[2].x += nm.z * h.x; acc[2].y += nm.z * h.y; acc[2].z += nm.z * h.z; acc[2].w += nm.z * h.w;
        acc[3].x += nm.w * h.x; acc[3].y += nm.w * h.y; acc[3].z += nm.w * h.z; acc[3].w += nm.w * h.w;
    }
#pragma unroll
    for (int l = 0; l < 4; l++)
        ((float4*)(g_Z + ((size_t)(g * 4 + l) * NN + c) * CC))[lane] = acc[l];
}

// ---------------- fused: feats tile + g_matrix partial + norm->bf16 ----------
// grid (94, NGG), block 256 (tx=col float4, ty=row group of 8).
// Per 64-row tile: for each layer l: GEMM1 Z_l@W_l into regs (smem sZ+sW),
// relu+bias -> smem O tile, GEMM2 O@Ws_l accumulating feats regs. Then block
// column sums -> g_gmp, and per-row L2 norm -> bf16 g_xnb.
__global__ void __launch_bounds__(256, 2) k_fused(const float* __restrict__ gW,
                                                  const float* __restrict__ gb,
                                                  const float* __restrict__ Wsm) {
    __shared__ float smem[12288];          // 48KB
    float* sO  = smem;                     // [64][128] 32KB (phase B/C)
    float* sZ  = smem;                     // phase A: [64][32] 8KB
    float* sW  = smem + 2048;              // phase A: [32][128] 16KB
    float* sWs = smem + 8192;              // phase C: [32][128] 16KB
    int g = blockIdx.y;
    int row0 = blockIdx.x * 64;
    int tid = threadIdx.x;
    int tx = tid & 31, ty = tid >> 5;

    float accF[8][4];
#pragma unroll
    for (int j = 0; j < 8; j++) { accF[j][0]=0;accF[j][1]=0;accF[j][2]=0;accF[j][3]=0; }

    for (int l = 0; l < 4; l++) {
        float accO[8][4];
#pragma unroll
        for (int j = 0; j < 8; j++) { accO[j][0]=0;accO[j][1]=0;accO[j][2]=0;accO[j][3]=0; }
        const float4* Av = (const float4*)(g_Z + (size_t)(g * 4 + l) * NN * CC);
        const float4* Bv = (const float4*)(gW + (size_t)l * CC * CC);
        for (int kc = 0; kc < 4; kc++) {
            __syncthreads();               // protects prior phase-C reads of sO
#pragma unroll
            for (int it = 0; it < 4; it++)
                ((float4*)sW)[it * 256 + tid] = Bv[kc * 1024 + it * 256 + tid];
#pragma unroll
            for (int it = 0; it < 2; it++) {
                int idx = it * 256 + tid;
                int m = idx >> 3, kq = idx & 7;
                int gm = row0 + m;
                float4 v = make_float4(0.f, 0.f, 0.f, 0.f);
                if (gm < NN) v = Av[(size_t)gm * 32 + kc * 8 + kq];
                ((float4*)sZ)[idx] = v;
            }
            __syncthreads();
#pragma unroll
            for (int k = 0; k < 32; k++) {
                float4 b = ((float4*)sW)[k * 32 + tx];
#pragma unroll
                for (int j = 0; j < 8; j++) {
                    float a = sZ[(ty * 8 + j) * 32 + k];
                    accO[j][0] += a * b.x; accO[j][1] += a * b.y;
                    accO[j][2] += a * b.z; accO[j][3] += a * b.w;
                }
            }
        }
        // phase B: relu(O + b) -> sO (overwrites sZ/sW region)
        __syncthreads();
        float4 bb = ((const float4*)(gb + l * CC))[tx];
#pragma unroll
        for (int j = 0; j < 8; j++) {
            float4 v = make_float4(fmaxf(accO[j][0] + bb.x, 0.f),
                                   fmaxf(accO[j][1] + bb.y, 0.f),
                                   fmaxf(accO[j][2] + bb.z, 0.f),
                                   fmaxf(accO[j][3] + bb.w, 0.f));
            ((float4*)sO)[(ty * 8 + j) * 32 + tx] = v;
        }
        __syncthreads();
        // phase C: feats += relu(O) @ Ws_l
        const float4* Cv = (const float4*)(Wsm + (size_t)l * CC * CC);
        for (int kc2 = 0; kc2 < 4; kc2++) {
            if (kc2) __syncthreads();
#pragma unroll
            for (int it = 0; it < 4; it++)
                ((float4*)sWs)[it * 256 + tid] = Cv[kc2 * 1024 + it * 256 + tid];
            __syncthreads();
#pragma unroll
            for (int k = 0; k < 32; k++) {
                float4 b = ((float4*)sWs)[k * 32 + tx];
#pragma unroll
                for (int j = 0; j < 8; j++) {
                    float a = sO[(ty * 8 + j) * 128 + kc2 * 32 + k];
                    accF[j][0] += a * b.x; accF[j][1] += a * b.y;
                    accF[j][2] += a * b.z; accF[j][3] += a * b.w;
                }
            }
        }
    }

    // ---- g_matrix partials: column sums of valid rows ----
    __syncthreads();                       // last phase-C reads of sO done
    float4 cs = make_float4(0.f, 0.f, 0.f, 0.f);
#pragma unroll
    for (int j = 0; j < 8; j++) {
        if (row0 + ty * 8 + j < NN) {
            cs.x += accF[j][0]; cs.y += accF[j][1];
            cs.z += accF[j][2]; cs.w += accF[j][3];
        }
    }
    ((float4*)sO)[ty * 32 + tx] = cs;      // sgm[8][128] in sO region
    __syncthreads();
    if (ty == 0) {
        float4 t = make_float4(0.f, 0.f, 0.f, 0.f);
#pragma unroll
        for (int wv = 0; wv < 8; wv++) {
            float4 v = ((float4*)sO)[wv * 32 + tx];
            t.x += v.x; t.y += v.y; t.z += v.z; t.w += v.w;
        }
        ((float4*)(g_gmp + (size_t)(g * NBLK + blockIdx.x) * CC))[tx] = t;
    }

    // ---- per-row L2 normalize -> bf16 (warp ty owns rows ty*8..+7) ----
#pragma unroll
    for (int j = 0; j < 8; j++) {
        int row = row0 + ty * 8 + j;
        float4 v = make_float4(accF[j][0], accF[j][1], accF[j][2], accF[j][3]);
        float ss = v.x * v.x + v.y * v.y + v.z * v.z + v.w * v.w;
#pragma unroll
        for (int o = 16; o; o >>= 1) ss += __shfl_xor_sync(0xffffffffu, ss, o);
        if (row < NN) {
            float inv = 1.0f / fmaxf(sqrtf(ss), 1e-12f);
            __nv_bfloat162 b0 = __floats2bfloat162_rn(v.x * inv, v.y * inv);
            __nv_bfloat162 b1 = __floats2bfloat162_rn(v.z * inv, v.w * inv);
            uint2 pk;
            pk.x = *(uint32_t*)&b0;
            pk.y = *(uint32_t*)&b1;
            ((uint2*)(g_xnb + ((size_t)g * NROWP + row) * CC))[tx] = pk;
        }
    }
}

// ---------------- sim: A tile resident, loop over column tiles ----------------
__global__ void __launch_bounds__(256, 2) k_sim() {
    __shared__ __nv_bfloat16 sA[2][128 * 64];  // two SW128 K=64 chunks (32KB)
    __shared__ __nv_bfloat16 sB[128 * 40];     // K=32 chunk, rows padded to 80B
    __shared__ float s_bnd[22];
    __shared__ unsigned s_part[8];

    int p = blockIdx.y;
    int i1 = cP1[p], i2 = cP2[p];
    int bx = blockIdx.x;
    bool diag = (i1 == i2);
    int byStart = diag ? bx : 0;

    int tid = threadIdx.x;
    int lane = tid & 31, wid = tid >> 5;
    int wm = wid & 3, wn = wid >> 2;           // warp tile: rows wm*32, cols wn*64
    if (tid < 22) s_bnd[tid] = c_bnd[tid];

    int row0 = bx * 128;
    const __nv_bfloat16* A = g_xnb + (size_t)i1 * NROWP * CC;
    const __nv_bfloat16* B = g_xnb + (size_t)i2 * NROWP * CC;
    uint32_t baseA = smem_u32(sA), baseB = smem_u32(sB);

    // load resident A: 2048 uint4 slots
#pragma unroll
    for (int it = 0; it < 8; it++) {
        int idx = it * 256 + tid;
        int kc = idx >> 10, rem = idx & 1023;
        int r = rem >> 3, q = rem & 7;
        uint32_t sw = (uint32_t)(kc * 16384) + SWZ128((uint32_t)(r * 128 + q * 16));
        *(uint4*)((uint8_t*)sA + sw) =
            *(const uint4*)(A + (size_t)(row0 + r) * CC + kc * 64 + q * 8);
    }

    unsigned total = 0;
    for (int by = byStart; by < 47; by++) {
        unsigned wgt = (diag && by > bx) ? 2u : 1u;
        int col0 = by * 128;
        float acc[2][8][4];
#pragma unroll
        for (int mt = 0; mt < 2; mt++)
#pragma unroll
            for (int nt = 0; nt < 8; nt++) {
                acc[mt][nt][0] = 0.f; acc[mt][nt][1] = 0.f;
                acc[mt][nt][2] = 0.f; acc[mt][nt][3] = 0.f;
            }
#pragma unroll
        for (int bc = 0; bc < 4; bc++) {
            __syncthreads();                   // prior reads done before overwrite
#pragma unroll
            for (int it = 0; it < 2; it++) {
                int idx = it * 256 + tid;      // 512 uint4 slots
                int r = idx >> 2, q = idx & 3;
                *(uint4*)((uint8_t*)sB + r * 80 + q * 16) =
                    *(const uint4*)(B + (size_t)(col0 + r) * CC + bc * 32 + q * 8);
            }
            __syncthreads();
#pragma unroll
            for (int ks = 0; ks < 2; ks++) {
                int kg = bc * 32 + ks * 16;
                int akc = kg >> 6, akb = (kg & 63) * 2;
                uint32_t a[2][4];
#pragma unroll
                for (int mt = 0; mt < 2; mt++) {
                    int r = wm * 32 + mt * 16 + (lane & 15);
                    uint32_t ad = baseA + akc * 16384 +
                        SWZ128((uint32_t)(r * 128 + akb + (lane >> 4) * 16));
                    asm volatile("ldmatrix.sync.aligned.m8n8.x4.shared.b16 {%0,%1,%2,%3}, [%4];"
                        : "=r"(a[mt][0]), "=r"(a[mt][1]), "=r"(a[mt][2]), "=r"(a[mt][3])
                        : "r"(ad));
                }
                uint32_t b[4][4];
#pragma unroll
                for (int np = 0; np < 4; np++) {
                    int r = wn * 64 + np * 16 + (lane & 7) + ((lane >> 4) << 3);
                    uint32_t bd = baseB + (uint32_t)(r * 80 + ks * 32 + ((lane >> 3) & 1) * 16);
                    asm volatile("ldmatrix.sync.aligned.m8n8.x4.shared.b16 {%0,%1,%2,%3}, [%4];"
                        : "=r"(b[np][0]), "=r"(b[np][1]), "=r"(b[np][2]), "=r"(b[np][3])
                        : "r"(bd));
                }
#pragma unroll
                for (int mt = 0; mt < 2; mt++)
#pragma unroll
                    for (int nt = 0; nt < 8; nt++) {
                        asm volatile(
                            "mma.sync.aligned.m16n8k16.row.col.f32.bf16.bf16.f32 "
                            "{%0,%1,%2,%3}, {%4,%5,%6,%7}, {%8,%9}, {%0,%1,%2,%3};"
                            : "+f"(acc[mt][nt][0]), "+f"(acc[mt][nt][1]),
                              "+f"(acc[mt][nt][2]), "+f"(acc[mt][nt][3])
                            : "r"(a[mt][0]), "r"(a[mt][1]), "r"(a[mt][2]), "r"(a[mt][3]),
                              "r"(b[nt >> 1][(nt & 1) * 2]), "r"(b[nt >> 1][(nt & 1) * 2 + 1]));
                    }
            }
        }
        // bin accumulators. idx_true = #{j: s >= bnd[j]}. tanh.approx abs err
        // <= 6.2e-4 -> 10.5*t err <= 0.0065 << 0.07 margin, so
        // idx0 = floor(10.5*t + 10.43) satisfies idx_true in {idx0, idx0+1};
        // one exact compare resolves it. idx0=-1 hits the -3e38 sentinel -> 0.
        int sum = 0;
#pragma unroll
        for (int mt = 0; mt < 2; mt++)
#pragma unroll
            for (int nt = 0; nt < 8; nt++)
#pragma unroll
                for (int v = 0; v < 4; v++) {
                    float s = acc[mt][nt][v];
                    float t;
                    asm("tanh.approx.f32 %0, %1;" : "=f"(t) : "f"(s));
                    int idx = __float2int_rd(fmaf(t, 10.5f, 10.43f));
                    sum += idx + ((s >= s_bnd[idx + 1]) ? 1 : 0);
                }
        total += wgt * (unsigned)sum;
    }
#pragma unroll
    for (int o = 16; o; o >>= 1) total += __shfl_xor_sync(0xffffffffu, total, o);
    if (lane == 0) s_part[wid] = total;
    __syncthreads();
    if (tid == 0) {
        unsigned tot = 0;
#pragma unroll
        for (int i = 0; i < 8; i++) tot += s_part[i];
        atomicAdd(&g_cnt[p], tot);
    }
}

// ---------------- finalize: g_matrix reduce + sim values ----------------
__global__ void k_final(float* __restrict__ out) {
    int t = threadIdx.x;
    if (t < NGG * CC) {
        int g = t / CC, c = t - g * CC;
        float s = 0.f;
        for (int b = 0; b < NBLK; b++)
            s += g_gmp[(size_t)(g * NBLK + b) * CC + c];
        out[t] = s / (float)NN;
    }
    if (t < NPAIR) {
        // pads: 6016^2 - 6000^2 = 192256 zero-dots, each binned at idx=10
        double cnt = (double)g_cnt[t] - 10.0 * 192256.0;
        double v = -1.0 + 0.1 * cnt / ((double)NN * (double)NN);
        out[NGG * CC + cP1[t] * NGG + cP2[t]] = (float)v;
        out[NGG * CC + cP2[t] * NGG + cP1[t]] = (float)v;
    }
}

// ---------------- launch ----------------
extern "C" void kernel_launch(void* const* d_in, const int* in_sizes, int n_in,
                              void* d_out, int out_size) {
    const float* x   = (const float*)d_in[0];
    const int* ei    = (const int*)d_in[1];
    const float* ea  = (const float*)d_in[2];
    const float* gW  = (const float*)d_in[3];
    const float* gb  = (const float*)d_in[4];
    const float* Wsm = (const float*)d_in[5];
    float* out = (float*)d_out;

    k_setup<<<(NGI * NN + 255) / 256, 256>>>();
    k_deg<<<(NGG * EE + 255) / 256, 256>>>(ei, ea);
    k_dis<<<(NGI * NN + 255) / 256, 256>>>();
    k_scan<<<NGG, 256>>>();
    k_fill<<<(NGG * EE + 255) / 256, 256>>>(ei, ea);
    k_gather<<<(NGG * NN + 7) / 8, 256>>>(x);
    k_fused<<<dim3(NBLK, NGG), 256>>>(gW, gb, Wsm);
    k_sim<<<dim3(47, NPAIR), 256>>>();
    k_final<<<1, 768>>>(out);
}

// round 11
// speedup vs baseline: 5.7665x; 1.0228x over previous
#include <cuda_runtime.h>
#include <cuda_bf16.h>
#include <cstdint>

#define NGG 6
#define NN 6000
#define EE 96000
#define CC 128
#define NPAIR 21
#define NROWP 6016   // NN padded to multiple of 128
#define NBLK 94      // row tiles of 64

// ---------------- device scratch ----------------
__device__ float g_deg4[(size_t)NGG * NN * 4];    // weighted deg per layer -> dis
__device__ int   g_cntn[NGG * NN];                // in-edge count per node
__device__ int   g_off[NGG * NN];                 // CSR start offsets
__device__ int   g_cur[NGG * NN];                 // fill cursors
__device__ int   g_csr[NGG * EE];                 // source node per CSR slot
__device__ float g_enorm[(size_t)NGG * EE * 4];   // per-edge per-layer norm coeff
__device__ float g_Z[(size_t)NGG * 4 * NN * CC];  // gathered x (pre-GEMM), per (g,l)
__device__ float g_gmp[NGG * NBLK * CC];          // g_matrix per-block partials
__device__ __nv_bfloat16 g_xnb[(size_t)NGG * NROWP * CC]; // normalized rows, bf16
__device__ unsigned int g_cnt[NPAIR];

__constant__ int cP1[NPAIR] = {0,0,0,0,0,0, 1,1,1,1,1, 2,2,2,2, 3,3,3, 4,4, 5};
__constant__ int cP2[NPAIR] = {0,1,2,3,4,5, 1,2,3,4,5, 2,3,4,5, 3,4,5, 4,5, 5};

// s-space bin boundaries: bnd[k] = atanh(k/10.5 - 1), k=1..20; sentinels at ends
__constant__ float c_bnd[22] = {
    -3e38f,
    -1.49786614f, -1.12564590f, -0.89587974f, -0.72345949f, -0.58157540f,
    -0.45814537f, -0.34657359f, -0.24275391f, -0.14384104f, -0.04765509f,
     0.04765509f,  0.14384104f,  0.24275391f,  0.34657359f,  0.45814537f,
     0.58157540f,  0.72345949f,  0.89587974f,  1.12564590f,  1.49786614f,
     3e38f };

__device__ __forceinline__ uint32_t smem_u32(const void* p) {
    uint32_t a;
    asm("{ .reg .u64 t; cvta.to.shared.u64 t, %1; cvt.u32.u64 %0, t; }"
        : "=r"(a) : "l"(p));
    return a;
}
#define SWZ128(off) ((off) ^ (((off) >> 3) & 0x70))

// ---------------- setup ----------------
__global__ void k_setup() {
    int i = blockIdx.x * blockDim.x + threadIdx.x;
    if (i < NGG * NN * 4) g_deg4[i] = 1.0f;     // self-loop weight
    if (i < NGG * NN) g_cntn[i] = 0;
    if (i < NPAIR) g_cnt[i] = 0u;
    if (i < NGG * 16 * CC) {                    // zero 16 pad rows
        int g = i / (16 * CC), rem = i - g * (16 * CC);
        g_xnb[((size_t)g * NROWP + NN) * CC + rem] = __float2bfloat16(0.f);
    }
}

// ---------------- per-node in-degree count + weighted degree ----------------
__global__ void k_deg(const int* __restrict__ ei, const float* __restrict__ ea) {
    int i = blockIdx.x * blockDim.x + threadIdx.x;
    if (i >= NGG * EE) return;
    int g = i / EE, e = i - g * EE;
    int c = ei[(size_t)g * 2 * EE + EE + e];
    const float* w = ea + ((size_t)g * EE + e) * 6;
    float2 wa = *(const float2*)(w + 2);
    float2 wb = *(const float2*)(w + 4);
    asm volatile("red.global.add.v4.f32 [%0], {%1, %2, %3, %4};"
                 :: "l"(&g_deg4[(size_t)(g * NN + c) * 4]),
                    "f"(wa.x), "f"(wa.y), "f"(wb.x), "f"(wb.y) : "memory");
    atomicAdd(&g_cntn[g * NN + c], 1);
}

__global__ void k_dis() {
    int i = blockIdx.x * blockDim.x + threadIdx.x;
    if (i < NGG * NN * 4) g_deg4[i] = rsqrtf(g_deg4[i]);
}

// ---------------- CSR offsets: block per graph, scan 6000 counts ----------------
__global__ void __launch_bounds__(256) k_scan() {
    __shared__ int ps[256];
    int g = blockIdx.x, t = threadIdx.x;
    const int PT = 24;                    // 250 threads * 24 = 6000
    int loc[PT];
    int s = 0;
    if (t < 250) {
        int base = g * NN + t * PT;
#pragma unroll
        for (int i = 0; i < PT; i++) { loc[i] = g_cntn[base + i]; s += loc[i]; }
    }
    ps[t] = s;
    __syncthreads();
    for (int o = 1; o < 256; o <<= 1) {
        int v = (t >= o) ? ps[t - o] : 0;
        __syncthreads();
        ps[t] += v;
        __syncthreads();
    }
    if (t < 250) {
        int run = ps[t] - s;              // exclusive prefix
        int base = g * NN + t * PT;
#pragma unroll
        for (int i = 0; i < PT; i++) {
            g_off[base + i] = run;
            g_cur[base + i] = run;
            run += loc[i];
        }
    }
}

// ---------------- CSR fill + per-edge norm coefficients ----------------
__global__ void k_fill(const int* __restrict__ ei, const float* __restrict__ ea) {
    int i = blockIdx.x * blockDim.x + threadIdx.x;
    if (i >= NGG * EE) return;
    int g = i / EE, e = i - g * EE;
    int r = ei[(size_t)g * 2 * EE + e];
    int c = ei[(size_t)g * 2 * EE + EE + e];
    int pos = atomicAdd(&g_cur[g * NN + c], 1);
    g_csr[g * EE + pos] = r;
    const float* w = ea + ((size_t)g * EE + e) * 6;
    float2 wa = *(const float2*)(w + 2);
    float2 wb = *(const float2*)(w + 4);
    float4 dr = *(const float4*)&g_deg4[(size_t)(g * NN + r) * 4];
    float4 dc = *(const float4*)&g_deg4[(size_t)(g * NN + c) * 4];
    float4 nm;
    nm.x = dr.x * wa.x * dc.x;
    nm.y = dr.y * wa.y * dc.y;
    nm.z = dr.z * wb.x * dc.z;
    nm.w = dr.w * wb.y * dc.w;
    *(float4*)&g_enorm[((size_t)g * EE + pos) * 4] = nm;
}

// ---------------- gather raw x:  Z_l[c] = dis_l[c]^2 x[c] + sum_in nrm_l x[r] --
__global__ void __launch_bounds__(256) k_gather(const float* __restrict__ x) {
    int w = (blockIdx.x * 256 + threadIdx.x) >> 5;
    int lane = threadIdx.x & 31;
    if (w >= NGG * NN) return;
    int g = w / NN, c = w - g * NN;
    const float4* Xg = (const float4*)(x + (size_t)g * NN * CC);

    float4 xc = Xg[(size_t)c * 32 + lane];
    float4 d4 = *(const float4*)&g_deg4[(size_t)(g * NN + c) * 4];
    float sc[4] = {d4.x * d4.x, d4.y * d4.y, d4.z * d4.z, d4.w * d4.w};
    float4 acc[4];
#pragma unroll
    for (int l = 0; l < 4; l++)
        acc[l] = make_float4(xc.x * sc[l], xc.y * sc[l], xc.z * sc[l], xc.w * sc[l]);
    int start = g_off[g * NN + c];
    int cnt = g_cntn[g * NN + c];
    const int* csr = g_csr + (size_t)g * EE;
    const float4* en = (const float4*)(g_enorm + (size_t)g * EE * 4);
#pragma unroll 4
    for (int j = 0; j < cnt; j++) {
        int r = __ldg(&csr[start + j]);
        float4 nm = __ldg(&en[start + j]);
        float4 h = Xg[(size_t)r * 32 + lane];
        acc[0].x += nm.x * h.x; acc[0].y += nm.x * h.y; acc[0].z += nm.x * h.z; acc[0].w += nm.x * h.w;
        acc[1].x += nm.y * h.x; acc[1].y += nm.y * h.y; acc[1].z += nm.y * h.z; acc[1].w += nm.y * h.w;
        acc[2].x += nm.z * h.x; acc[2].y += nm.z * h.y; acc[2].z += nm.z * h.z; acc[2].w += nm.z * h.w;
        acc[3].x += nm.w * h.x; acc[3].y += nm.w * h.y; acc[3].z += nm.w * h.z; acc[3].w += nm.w * h.w;
    }
#pragma unroll
    for (int l = 0; l < 4; l++)
        ((float4*)(g_Z + ((size_t)(g * 4 + l) * NN + c) * CC))[lane] = acc[l];
}

// ---------------- fused: feats tile + g_matrix partial + norm->bf16 ----------
__global__ void __launch_bounds__(256, 2) k_fused(const float* __restrict__ gW,
                                                  const float* __restrict__ gb,
                                                  const float* __restrict__ Wsm) {
    __shared__ float smem[12288];          // 48KB
    float* sO  = smem;                     // [64][128] 32KB (phase B/C)
    float* sZ  = smem;                     // phase A: [64][32] 8KB
    float* sW  = smem + 2048;              // phase A: [32][128] 16KB
    float* sWs = smem + 8192;              // phase C: [32][128] 16KB
    int g = blockIdx.y;
    int row0 = blockIdx.x * 64;
    int tid = threadIdx.x;
    int tx = tid & 31, ty = tid >> 5;

    float accF[8][4];
#pragma unroll
    for (int j = 0; j < 8; j++) { accF[j][0]=0;accF[j][1]=0;accF[j][2]=0;accF[j][3]=0; }

    for (int l = 0; l < 4; l++) {
        float accO[8][4];
#pragma unroll
        for (int j = 0; j < 8; j++) { accO[j][0]=0;accO[j][1]=0;accO[j][2]=0;accO[j][3]=0; }
        const float4* Av = (const float4*)(g_Z + (size_t)(g * 4 + l) * NN * CC);
        const float4* Bv = (const float4*)(gW + (size_t)l * CC * CC);
        for (int kc = 0; kc < 4; kc++) {
            __syncthreads();               // protects prior phase-C reads of sO
#pragma unroll
            for (int it = 0; it < 4; it++)
                ((float4*)sW)[it * 256 + tid] = Bv[kc * 1024 + it * 256 + tid];
#pragma unroll
            for (int it = 0; it < 2; it++) {
                int idx = it * 256 + tid;
                int m = idx >> 3, kq = idx & 7;
                int gm = row0 + m;
                float4 v = make_float4(0.f, 0.f, 0.f, 0.f);
                if (gm < NN) v = Av[(size_t)gm * 32 + kc * 8 + kq];
                ((float4*)sZ)[idx] = v;
            }
            __syncthreads();
#pragma unroll
            for (int k = 0; k < 32; k++) {
                float4 b = ((float4*)sW)[k * 32 + tx];
#pragma unroll
                for (int j = 0; j < 8; j++) {
                    float a = sZ[(ty * 8 + j) * 32 + k];
                    accO[j][0] += a * b.x; accO[j][1] += a * b.y;
                    accO[j][2] += a * b.z; accO[j][3] += a * b.w;
                }
            }
        }
        // phase B: relu(O + b) -> sO
        __syncthreads();
        float4 bb = ((const float4*)(gb + l * CC))[tx];
#pragma unroll
        for (int j = 0; j < 8; j++) {
            float4 v = make_float4(fmaxf(accO[j][0] + bb.x, 0.f),
                                   fmaxf(accO[j][1] + bb.y, 0.f),
                                   fmaxf(accO[j][2] + bb.z, 0.f),
                                   fmaxf(accO[j][3] + bb.w, 0.f));
            ((float4*)sO)[(ty * 8 + j) * 32 + tx] = v;
        }
        __syncthreads();
        // phase C: feats += relu(O) @ Ws_l
        const float4* Cv = (const float4*)(Wsm + (size_t)l * CC * CC);
        for (int kc2 = 0; kc2 < 4; kc2++) {
            if (kc2) __syncthreads();
#pragma unroll
            for (int it = 0; it < 4; it++)
                ((float4*)sWs)[it * 256 + tid] = Cv[kc2 * 1024 + it * 256 + tid];
            __syncthreads();
#pragma unroll
            for (int k = 0; k < 32; k++) {
                float4 b = ((float4*)sWs)[k * 32 + tx];
#pragma unroll
                for (int j = 0; j < 8; j++) {
                    float a = sO[(ty * 8 + j) * 128 + kc2 * 32 + k];
                    accF[j][0] += a * b.x; accF[j][1] += a * b.y;
                    accF[j][2] += a * b.z; accF[j][3] += a * b.w;
                }
            }
        }
    }

    // ---- g_matrix partials: column sums of valid rows ----
    __syncthreads();
    float4 cs = make_float4(0.f, 0.f, 0.f, 0.f);
#pragma unroll
    for (int j = 0; j < 8; j++) {
        if (row0 + ty * 8 + j < NN) {
            cs.x += accF[j][0]; cs.y += accF[j][1];
            cs.z += accF[j][2]; cs.w += accF[j][3];
        }
    }
    ((float4*)sO)[ty * 32 + tx] = cs;
    __syncthreads();
    if (ty == 0) {
        float4 t = make_float4(0.f, 0.f, 0.f, 0.f);
#pragma unroll
        for (int wv = 0; wv < 8; wv++) {
            float4 v = ((float4*)sO)[wv * 32 + tx];
            t.x += v.x; t.y += v.y; t.z += v.z; t.w += v.w;
        }
        ((float4*)(g_gmp + (size_t)(g * NBLK + blockIdx.x) * CC))[tx] = t;
    }

    // ---- per-row L2 normalize -> bf16 ----
#pragma unroll
    for (int j = 0; j < 8; j++) {
        int row = row0 + ty * 8 + j;
        float4 v = make_float4(accF[j][0], accF[j][1], accF[j][2], accF[j][3]);
        float ss = v.x * v.x + v.y * v.y + v.z * v.z + v.w * v.w;
#pragma unroll
        for (int o = 16; o; o >>= 1) ss += __shfl_xor_sync(0xffffffffu, ss, o);
        if (row < NN) {
            float inv = 1.0f / fmaxf(sqrtf(ss), 1e-12f);
            __nv_bfloat162 b0 = __floats2bfloat162_rn(v.x * inv, v.y * inv);
            __nv_bfloat162 b1 = __floats2bfloat162_rn(v.z * inv, v.w * inv);
            uint2 pk;
            pk.x = *(uint32_t*)&b0;
            pk.y = *(uint32_t*)&b1;
            ((uint2*)(g_xnb + ((size_t)g * NROWP + row) * CC))[tx] = pk;
        }
    }
}

// ---------------- sim: bf16 mma, A tile resident, loop over column tiles ------
__global__ void __launch_bounds__(256, 2) k_sim() {
    __shared__ __nv_bfloat16 sA[2][128 * 64];  // two SW128 K=64 chunks (32KB)
    __shared__ __nv_bfloat16 sB[128 * 40];     // K=32 chunk, rows padded to 80B
    __shared__ float s_bnd[22];
    __shared__ unsigned s_part[8];

    int p = blockIdx.y;
    int i1 = cP1[p], i2 = cP2[p];
    int bx = blockIdx.x;
    bool diag = (i1 == i2);
    int byStart = diag ? bx : 0;

    int tid = threadIdx.x;
    int lane = tid & 31, wid = tid >> 5;
    int wm = wid & 3, wn = wid >> 2;           // warp tile: rows wm*32, cols wn*64
    if (tid < 22) s_bnd[tid] = c_bnd[tid];

    int row0 = bx * 128;
    const __nv_bfloat16* A = g_xnb + (size_t)i1 * NROWP * CC;
    const __nv_bfloat16* B = g_xnb + (size_t)i2 * NROWP * CC;
    uint32_t baseA = smem_u32(sA), baseB = smem_u32(sB);

    // load resident A: 2048 uint4 slots
#pragma unroll
    for (int it = 0; it < 8; it++) {
        int idx = it * 256 + tid;
        int kc = idx >> 10, rem = idx & 1023;
        int r = rem >> 3, q = rem & 7;
        uint32_t sw = (uint32_t)(kc * 16384) + SWZ128((uint32_t)(r * 128 + q * 16));
        *(uint4*)((uint8_t*)sA + sw) =
            *(const uint4*)(A + (size_t)(row0 + r) * CC + kc * 64 + q * 8);
    }

    unsigned total = 0;
    for (int by = byStart; by < 47; by++) {
        unsigned wgt = (diag && by > bx) ? 2u : 1u;
        int col0 = by * 128;
        float acc[2][8][4];
#pragma unroll
        for (int mt = 0; mt < 2; mt++)
#pragma unroll
            for (int nt = 0; nt < 8; nt++) {
                acc[mt][nt][0] = 0.f; acc[mt][nt][1] = 0.f;
                acc[mt][nt][2] = 0.f; acc[mt][nt][3] = 0.f;
            }
#pragma unroll
        for (int bc = 0; bc < 4; bc++) {
            __syncthreads();                   // prior reads done before overwrite
#pragma unroll
            for (int it = 0; it < 2; it++) {
                int idx = it * 256 + tid;      // 512 uint4 slots
                int r = idx >> 2, q = idx & 3;
                *(uint4*)((uint8_t*)sB + r * 80 + q * 16) =
                    *(const uint4*)(B + (size_t)(col0 + r) * CC + bc * 32 + q * 8);
            }
            __syncthreads();
#pragma unroll
            for (int ks = 0; ks < 2; ks++) {
                int kg = bc * 32 + ks * 16;
                int akc = kg >> 6, akb = (kg & 63) * 2;
                uint32_t a[2][4];
#pragma unroll
                for (int mt = 0; mt < 2; mt++) {
                    int r = wm * 32 + mt * 16 + (lane & 15);
                    uint32_t ad = baseA + akc * 16384 +
                        SWZ128((uint32_t)(r * 128 + akb + (lane >> 4) * 16));
                    asm volatile("ldmatrix.sync.aligned.m8n8.x4.shared.b16 {%0,%1,%2,%3}, [%4];"
                        : "=r"(a[mt][0]), "=r"(a[mt][1]), "=r"(a[mt][2]), "=r"(a[mt][3])
                        : "r"(ad));
                }
                uint32_t b[4][4];
#pragma unroll
                for (int np = 0; np < 4; np++) {
                    int r = wn * 64 + np * 16 + (lane & 7) + ((lane >> 4) << 3);
                    uint32_t bd = baseB + (uint32_t)(r * 80 + ks * 32 + ((lane >> 3) & 1) * 16);
                    asm volatile("ldmatrix.sync.aligned.m8n8.x4.shared.b16 {%0,%1,%2,%3}, [%4];"
                        : "=r"(b[np][0]), "=r"(b[np][1]), "=r"(b[np][2]), "=r"(b[np][3])
                        : "r"(bd));
                }
#pragma unroll
                for (int mt = 0; mt < 2; mt++)
#pragma unroll
                    for (int nt = 0; nt < 8; nt++) {
                        asm volatile(
                            "mma.sync.aligned.m16n8k16.row.col.f32.bf16.bf16.f32 "
                            "{%0,%1,%2,%3}, {%4,%5,%6,%7}, {%8,%9}, {%0,%1,%2,%3};"
                            : "+f"(acc[mt][nt][0]), "+f"(acc[mt][nt][1]),
                              "+f"(acc[mt][nt][2]), "+f"(acc[mt][nt][3])
                            : "r"(a[mt][0]), "r"(a[mt][1]), "r"(a[mt][2]), "r"(a[mt][3]),
                              "r"(b[nt >> 1][(nt & 1) * 2]), "r"(b[nt >> 1][(nt & 1) * 2 + 1]));
                    }
            }
        }
        // bin accumulators. idx_true = #{j: s >= bnd[j]}; tanh.approx err
        // (<=6.2e-4 in t, so <=0.0065 after x10.5) << 0.07 down-bias margin:
        // idx0 = floor(10.5*t + 10.43) gives idx_true in {idx0, idx0+1},
        // resolved by ONE exact boundary compare. idx0=-1 hits -3e38 sentinel.
        int sum = 0;
#pragma unroll
        for (int mt = 0; mt < 2; mt++)
#pragma unroll
            for (int nt = 0; nt < 8; nt++)
#pragma unroll
                for (int v = 0; v < 4; v++) {
                    float s = acc[mt][nt][v];
                    float t;
                    asm("tanh.approx.f32 %0, %1;" : "=f"(t) : "f"(s));
                    int idx = __float2int_rd(fmaf(t, 10.5f, 10.43f));
                    sum += idx + ((s >= s_bnd[idx + 1]) ? 1 : 0);
                }
        total += wgt * (unsigned)sum;
    }
#pragma unroll
    for (int o = 16; o; o >>= 1) total += __shfl_xor_sync(0xffffffffu, total, o);
    if (lane == 0) s_part[wid] = total;
    __syncthreads();
    if (tid == 0) {
        unsigned tot = 0;
#pragma unroll
        for (int i = 0; i < 8; i++) tot += s_part[i];
        atomicAdd(&g_cnt[p], tot);
    }
}

// ---------------- finalize: g_matrix reduce + sim values ----------------
__global__ void k_final(float* __restrict__ out) {
    int t = threadIdx.x;
    if (t < NGG * CC) {
        int g = t / CC, c = t - g * CC;
        float s = 0.f;
        for (int b = 0; b < NBLK; b++)
            s += g_gmp[(size_t)(g * NBLK + b) * CC + c];
        out[t] = s / (float)NN;
    }
    if (t < NPAIR) {
        // pads: 6016^2 - 6000^2 = 192256 zero-dots, each binned at idx=10
        double cnt = (double)g_cnt[t] - 10.0 * 192256.0;
        double v = -1.0 + 0.1 * cnt / ((double)NN * (double)NN);
        out[NGG * CC + cP1[t] * NGG + cP2[t]] = (float)v;
        out[NGG * CC + cP2[t] * NGG + cP1[t]] = (float)v;
    }
}

// ---------------- launch ----------------
extern "C" void kernel_launch(void* const* d_in, const int* in_sizes, int n_in,
                              void* d_out, int out_size) {
    const float* x   = (const float*)d_in[0];
    const int* ei    = (const int*)d_in[1];
    const float* ea  = (const float*)d_in[2];
    const float* gW  = (const float*)d_in[3];
    const float* gb  = (const float*)d_in[4];
    const float* Wsm = (const float*)d_in[5];
    float* out = (float*)d_out;

    k_setup<<<(NGG * NN * 4 + 255) / 256, 256>>>();
    k_deg<<<(NGG * EE + 255) / 256, 256>>>(ei, ea);
    k_dis<<<(NGG * NN * 4 + 255) / 256, 256>>>();
    k_scan<<<NGG, 256>>>();
    k_fill<<<(NGG * EE + 255) / 256, 256>>>(ei, ea);
    k_gather<<<(NGG * NN + 7) / 8, 256>>>(x);
    k_fused<<<dim3(NBLK, NGG), 256>>>(gW, gb, Wsm);
    k_sim<<<dim3(47, NPAIR), 256>>>();
    k_final<<<1, 768>>>(out);
}

// round 12
// speedup vs baseline: 6.2476x; 1.0834x over previous
#include <cuda_runtime.h>
#include <cuda_bf16.h>
#include <cstdint>

#define NGG 6
#define NN 6000
#define EE 96000
#define CC 128
#define NPAIR 21
#define NROWP 6016   // NN padded to multiple of 128
#define NBLK 47      // row tiles of 128 (fused + gmp)

// ---------------- device scratch ----------------
__device__ float g_deg4[(size_t)NGG * NN * 4];    // weighted deg per layer -> dis
__device__ int   g_cntn[NGG * NN];                // in-edge count per node
__device__ int   g_off[NGG * NN];                 // CSR start offsets
__device__ int   g_cur[NGG * NN];                 // fill cursors
__device__ int   g_csr[NGG * EE];                 // source node per CSR slot
__device__ float g_enorm[(size_t)NGG * EE * 4];   // per-edge per-layer norm coeff
__device__ __nv_bfloat16 g_Zb[(size_t)NGG * 4 * NN * CC]; // gathered x, bf16
__device__ float g_gmp[NGG * NBLK * CC];          // g_matrix per-block partials
__device__ __nv_bfloat16 g_xnb[(size_t)NGG * NROWP * CC]; // normalized rows, bf16
__device__ unsigned int g_cnt[NPAIR];

__constant__ int cP1[NPAIR] = {0,0,0,0,0,0, 1,1,1,1,1, 2,2,2,2, 3,3,3, 4,4, 5};
__constant__ int cP2[NPAIR] = {0,1,2,3,4,5, 1,2,3,4,5, 2,3,4,5, 3,4,5, 4,5, 5};

// s-space bin boundaries: bnd[k] = atanh(k/10.5 - 1), k=1..20; sentinels at ends
__constant__ float c_bnd[22] = {
    -3e38f,
    -1.49786614f, -1.12564590f, -0.89587974f, -0.72345949f, -0.58157540f,
    -0.45814537f, -0.34657359f, -0.24275391f, -0.14384104f, -0.04765509f,
     0.04765509f,  0.14384104f,  0.24275391f,  0.34657359f,  0.45814537f,
     0.58157540f,  0.72345949f,  0.89587974f,  1.12564590f,  1.49786614f,
     3e38f };

__device__ __forceinline__ uint32_t smem_u32(const void* p) {
    uint32_t a;
    asm("{ .reg .u64 t; cvta.to.shared.u64 t, %1; cvt.u32.u64 %0, t; }"
        : "=r"(a) : "l"(p));
    return a;
}
#define SWZ128(off) ((off) ^ (((off) >> 3) & 0x70))

__device__ __forceinline__ uint32_t pk_bf16(float a, float b) {
    __nv_bfloat162 t = __floats2bfloat162_rn(a, b);
    return *(uint32_t*)&t;
}
#define LDSM4(r0, r1, r2, r3, addr) \
    asm volatile("ldmatrix.sync.aligned.m8n8.x4.shared.b16 {%0,%1,%2,%3}, [%4];" \
        : "=r"(r0), "=r"(r1), "=r"(r2), "=r"(r3) : "r"(addr))
#define MMA_BF16(acc, a, b0, b1) \
    asm volatile("mma.sync.aligned.m16n8k16.row.col.f32.bf16.bf16.f32 " \
        "{%0,%1,%2,%3}, {%4,%5,%6,%7}, {%8,%9}, {%0,%1,%2,%3};" \
        : "+f"((acc)[0]), "+f"((acc)[1]), "+f"((acc)[2]), "+f"((acc)[3]) \
        : "r"((a)[0]), "r"((a)[1]), "r"((a)[2]), "r"((a)[3]), "r"(b0), "r"(b1))

// ---------------- setup ----------------
__global__ void k_setup() {
    int i = blockIdx.x * blockDim.x + threadIdx.x;
    if (i < NGG * NN * 4) g_deg4[i] = 1.0f;     // self-loop weight
    if (i < NGG * NN) g_cntn[i] = 0;
    if (i < NPAIR) g_cnt[i] = 0u;
    if (i < NGG * 16 * CC) {                    // zero 16 pad rows
        int g = i / (16 * CC), rem = i - g * (16 * CC);
        g_xnb[((size_t)g * NROWP + NN) * CC + rem] = __float2bfloat16(0.f);
    }
}

// ---------------- per-node in-degree count + weighted degree ----------------
__global__ void k_deg(const int* __restrict__ ei, const float* __restrict__ ea) {
    int i = blockIdx.x * blockDim.x + threadIdx.x;
    if (i >= NGG * EE) return;
    int g = i / EE, e = i - g * EE;
    int c = ei[(size_t)g * 2 * EE + EE + e];
    const float* w = ea + ((size_t)g * EE + e) * 6;
    float2 wa = *(const float2*)(w + 2);
    float2 wb = *(const float2*)(w + 4);
    asm volatile("red.global.add.v4.f32 [%0], {%1, %2, %3, %4};"
                 :: "l"(&g_deg4[(size_t)(g * NN + c) * 4]),
                    "f"(wa.x), "f"(wa.y), "f"(wb.x), "f"(wb.y) : "memory");
    atomicAdd(&g_cntn[g * NN + c], 1);
}

__global__ void k_dis() {
    int i = blockIdx.x * blockDim.x + threadIdx.x;
    if (i < NGG * NN * 4) g_deg4[i] = rsqrtf(g_deg4[i]);
}

// ---------------- CSR offsets ----------------
__global__ void __launch_bounds__(256) k_scan() {
    __shared__ int ps[256];
    int g = blockIdx.x, t = threadIdx.x;
    const int PT = 24;
    int loc[PT];
    int s = 0;
    if (t < 250) {
        int base = g * NN + t * PT;
#pragma unroll
        for (int i = 0; i < PT; i++) { loc[i] = g_cntn[base + i]; s += loc[i]; }
    }
    ps[t] = s;
    __syncthreads();
    for (int o = 1; o < 256; o <<= 1) {
        int v = (t >= o) ? ps[t - o] : 0;
        __syncthreads();
        ps[t] += v;
        __syncthreads();
    }
    if (t < 250) {
        int run = ps[t] - s;
        int base = g * NN + t * PT;
#pragma unroll
        for (int i = 0; i < PT; i++) {
            g_off[base + i] = run;
            g_cur[base + i] = run;
            run += loc[i];
        }
    }
}

// ---------------- CSR fill + per-edge norm coefficients ----------------
__global__ void k_fill(const int* __restrict__ ei, const float* __restrict__ ea) {
    int i = blockIdx.x * blockDim.x + threadIdx.x;
    if (i >= NGG * EE) return;
    int g = i / EE, e = i - g * EE;
    int r = ei[(size_t)g * 2 * EE + e];
    int c = ei[(size_t)g * 2 * EE + EE + e];
    int pos = atomicAdd(&g_cur[g * NN + c], 1);
    g_csr[g * EE + pos] = r;
    const float* w = ea + ((size_t)g * EE + e) * 6;
    float2 wa = *(const float2*)(w + 2);
    float2 wb = *(const float2*)(w + 4);
    float4 dr = *(const float4*)&g_deg4[(size_t)(g * NN + r) * 4];
    float4 dc = *(const float4*)&g_deg4[(size_t)(g * NN + c) * 4];
    float4 nm;
    nm.x = dr.x * wa.x * dc.x;
    nm.y = dr.y * wa.y * dc.y;
    nm.z = dr.z * wb.x * dc.z;
    nm.w = dr.w * wb.y * dc.w;
    *(float4*)&g_enorm[((size_t)g * EE + pos) * 4] = nm;
}

// ---------------- gather raw x -> bf16 Z ----------------
__global__ void __launch_bounds__(256) k_gather(const float* __restrict__ x) {
    int w = (blockIdx.x * 256 + threadIdx.x) >> 5;
    int lane = threadIdx.x & 31;
    if (w >= NGG * NN) return;
    int g = w / NN, c = w - g * NN;
    const float4* Xg = (const float4*)(x + (size_t)g * NN * CC);

    float4 xc = Xg[(size_t)c * 32 + lane];
    float4 d4 = *(const float4*)&g_deg4[(size_t)(g * NN + c) * 4];
    float sc[4] = {d4.x * d4.x, d4.y * d4.y, d4.z * d4.z, d4.w * d4.w};
    float4 acc[4];
#pragma unroll
    for (int l = 0; l < 4; l++)
        acc[l] = make_float4(xc.x * sc[l], xc.y * sc[l], xc.z * sc[l], xc.w * sc[l]);
    int start = g_off[g * NN + c];
    int cnt = g_cntn[g * NN + c];
    const int* csr = g_csr + (size_t)g * EE;
    const float4* en = (const float4*)(g_enorm + (size_t)g * EE * 4);
#pragma unroll 4
    for (int j = 0; j < cnt; j++) {
        int r = __ldg(&csr[start + j]);
        float4 nm = __ldg(&en[start + j]);
        float4 h = Xg[(size_t)r * 32 + lane];
        acc[0].x += nm.x * h.x; acc[0].y += nm.x * h.y; acc[0].z += nm.x * h.z; acc[0].w += nm.x * h.w;
        acc[1].x += nm.y * h.x; acc[1].y += nm.y * h.y; acc[1].z += nm.y * h.z; acc[1].w += nm.y * h.w;
        acc[2].x += nm.z * h.x; acc[2].y += nm.z * h.y; acc[2].z += nm.z * h.z; acc[2].w += nm.z * h.w;
        acc[3].x += nm.w * h.x; acc[3].y += nm.w * h.y; acc[3].z += nm.w * h.z; acc[3].w += nm.w * h.w;
    }
#pragma unroll
    for (int l = 0; l < 4; l++) {
        uint2 pk;
        pk.x = pk_bf16(acc[l].x, acc[l].y);
        pk.y = pk_bf16(acc[l].z, acc[l].w);
        ((uint2*)(g_Zb + ((size_t)(g * 4 + l) * NN + c) * CC))[lane] = pk;
    }
}

// ---------------- fused tensor-core feats + g_matrix + norm ----------------
// grid (47, NGG), 256 threads / 8 warps. Warp (wm,wn): output rows wm*32, cols wn*64.
// GEMM1: accO = Zb @ (W_hi + W_lo); GEMM2: accF += relu(accO+b) @ (Ws_hi + Ws_lo).
__global__ void __launch_bounds__(256) k_fused(const float* __restrict__ gW,
                                               const float* __restrict__ gb,
                                               const float* __restrict__ Wsm) {
    __shared__ uint8_t smem[36864];
    uint8_t* sZ  = smem;              // 16KB [128 rows][128B] SW128 bf16, K=64 chunk (also sO)
    uint8_t* sBh = smem + 16384;      // 10KB [128 n][80B] bf16 hi, K=32 chunk
    uint8_t* sBl = smem + 26624;      // 10KB lo
    __shared__ float sgm[128];
    __shared__ float sns[128];

    int g = blockIdx.y;
    int row0 = blockIdx.x * 128;
    int tid = threadIdx.x;
    int lane = tid & 31, wid = tid >> 5;
    int wm = wid & 3, wn = wid >> 2;
    uint32_t baseZ = smem_u32(sZ), baseBh = smem_u32(sBh), baseBl = smem_u32(sBl);

    float accF[2][8][4];
#pragma unroll
    for (int mt = 0; mt < 2; mt++)
#pragma unroll
        for (int nt = 0; nt < 8; nt++) {
            accF[mt][nt][0]=0.f; accF[mt][nt][1]=0.f; accF[mt][nt][2]=0.f; accF[mt][nt][3]=0.f;
        }

    for (int l = 0; l < 4; l++) {
        float accO[2][8][4];
#pragma unroll
        for (int mt = 0; mt < 2; mt++)
#pragma unroll
            for (int nt = 0; nt < 8; nt++) {
                accO[mt][nt][0]=0.f; accO[mt][nt][1]=0.f; accO[mt][nt][2]=0.f; accO[mt][nt][3]=0.f;
            }
        const uint4* Zb4 = (const uint4*)(g_Zb + (size_t)(g * 4 + l) * NN * CC);
        const float* Wl = gW + (size_t)l * CC * CC;

        // ======== GEMM1 ========
        for (int kc64 = 0; kc64 < 2; kc64++) {
            __syncthreads();
            // load sZ: rows row0..row0+127, k = kc64*64..+63 (SW128 bf16)
#pragma unroll
            for (int it = 0; it < 4; it++) {
                int idx = it * 256 + tid;           // 1024 uint4 slots
                int r = idx >> 3, q = idx & 7;
                uint4 v = make_uint4(0u, 0u, 0u, 0u);
                if (row0 + r < NN) v = Zb4[(size_t)(row0 + r) * 16 + kc64 * 8 + q];
                *(uint4*)(sZ + SWZ128((uint32_t)(r * 128 + q * 16))) = v;
            }
            for (int kc32 = 0; kc32 < 2; kc32++) {
                __syncthreads();
                // load W chunk [32 k][128 n] -> transposed hi/lo [n][80B rows]
                int k0 = kc64 * 64 + kc32 * 32;
#pragma unroll
                for (int it = 0; it < 16; it++) {
                    int idx = it * 256 + tid;       // 4096 elems
                    int k = idx >> 7, n = idx & 127;
                    float wv = Wl[(size_t)(k0 + k) * CC + n];
                    __nv_bfloat16 hb = __float2bfloat16(wv);
                    float lres = wv - __bfloat162float(hb);
                    __nv_bfloat16 lb = __float2bfloat16(lres);
                    *(uint16_t*)(sBh + n * 80 + k * 2) = *(uint16_t*)&hb;
                    *(uint16_t*)(sBl + n * 80 + k * 2) = *(uint16_t*)&lb;
                }
                __syncthreads();
#pragma unroll
                for (int ks = 0; ks < 2; ks++) {
                    int kin = kc32 * 32 + ks * 16;  // within k64 chunk
                    uint32_t a[2][4];
#pragma unroll
                    for (int mt = 0; mt < 2; mt++) {
                        int r = wm * 32 + mt * 16 + (lane & 15);
                        uint32_t ad = baseZ + SWZ128((uint32_t)(r * 128 + kin * 2 + (lane >> 4) * 16));
                        LDSM4(a[mt][0], a[mt][1], a[mt][2], a[mt][3], ad);
                    }
                    uint32_t bh[4][4], bl[4][4];
#pragma unroll
                    for (int np = 0; np < 4; np++) {
                        int r = wn * 64 + np * 16 + (lane & 7) + ((lane >> 4) << 3);
                        uint32_t off = (uint32_t)(r * 80 + ks * 32 + ((lane >> 3) & 1) * 16);
                        LDSM4(bh[np][0], bh[np][1], bh[np][2], bh[np][3], baseBh + off);
                        LDSM4(bl[np][0], bl[np][1], bl[np][2], bl[np][3], baseBl + off);
                    }
#pragma unroll
                    for (int mt = 0; mt < 2; mt++)
#pragma unroll
                        for (int nt = 0; nt < 8; nt++) {
                            MMA_BF16(accO[mt][nt], a[mt],
                                     bh[nt >> 1][(nt & 1) * 2], bh[nt >> 1][(nt & 1) * 2 + 1]);
                            MMA_BF16(accO[mt][nt], a[mt],
                                     bl[nt >> 1][(nt & 1) * 2], bl[nt >> 1][(nt & 1) * 2 + 1]);
                        }
                }
            }
        }

        // ======== GEMM2 ========
        const float* Wsl = Wsm + (size_t)l * CC * CC;
        for (int kc64 = 0; kc64 < 2; kc64++) {
            __syncthreads();                        // prior sZ/sO reads done
            if (wn == kc64) {
                // repack relu(accO + bias) -> sO rows (bf16, SW128); this warp's
                // cols wn*64..+63 are exactly chunk kc64's k-range.
#pragma unroll
                for (int nt = 0; nt < 8; nt++) {
                    int colb = wn * 64 + nt * 8 + 2 * (lane & 3);
                    float2 bb = *(const float2*)&gb[l * CC + colb];
                    int kloc = nt * 8 + 2 * (lane & 3);   // col within chunk
#pragma unroll
                    for (int mt = 0; mt < 2; mt++) {
                        int r = wm * 32 + mt * 16 + (lane >> 2);
                        uint32_t p0 = pk_bf16(fmaxf(accO[mt][nt][0] + bb.x, 0.f),
                                              fmaxf(accO[mt][nt][1] + bb.y, 0.f));
                        uint32_t p1 = pk_bf16(fmaxf(accO[mt][nt][2] + bb.x, 0.f),
                                              fmaxf(accO[mt][nt][3] + bb.y, 0.f));
                        *(uint32_t*)(sZ + SWZ128((uint32_t)(r * 128 + kloc * 2))) = p0;
                        *(uint32_t*)(sZ + SWZ128((uint32_t)((r + 8) * 128 + kloc * 2))) = p1;
                    }
                }
            }
            for (int kc32 = 0; kc32 < 2; kc32++) {
                __syncthreads();
                int k0 = kc64 * 64 + kc32 * 32;
#pragma unroll
                for (int it = 0; it < 16; it++) {
                    int idx = it * 256 + tid;
                    int k = idx >> 7, n = idx & 127;
                    float wv = Wsl[(size_t)(k0 + k) * CC + n];
                    __nv_bfloat16 hb = __float2bfloat16(wv);
                    float lres = wv - __bfloat162float(hb);
                    __nv_bfloat16 lb = __float2bfloat16(lres);
                    *(uint16_t*)(sBh + n * 80 + k * 2) = *(uint16_t*)&hb;
                    *(uint16_t*)(sBl + n * 80 + k * 2) = *(uint16_t*)&lb;
                }
                __syncthreads();
#pragma unroll
                for (int ks = 0; ks < 2; ks++) {
                    int kin = kc32 * 32 + ks * 16;
                    uint32_t a[2][4];
#pragma unroll
                    for (int mt = 0; mt < 2; mt++) {
                        int r = wm * 32 + mt * 16 + (lane & 15);
                        uint32_t ad = baseZ + SWZ128((uint32_t)(r * 128 + kin * 2 + (lane >> 4) * 16));
                        LDSM4(a[mt][0], a[mt][1], a[mt][2], a[mt][3], ad);
                    }
                    uint32_t bh[4][4], bl[4][4];
#pragma unroll
                    for (int np = 0; np < 4; np++) {
                        int r = wn * 64 + np * 16 + (lane & 7) + ((lane >> 4) << 3);
                        uint32_t off = (uint32_t)(r * 80 + ks * 32 + ((lane >> 3) & 1) * 16);
                        LDSM4(bh[np][0], bh[np][1], bh[np][2], bh[np][3], baseBh + off);
                        LDSM4(bl[np][0], bl[np][1], bl[np][2], bl[np][3], baseBl + off);
                    }
#pragma unroll
                    for (int mt = 0; mt < 2; mt++)
#pragma unroll
                        for (int nt = 0; nt < 8; nt++) {
                            MMA_BF16(accF[mt][nt], a[mt],
                                     bh[nt >> 1][(nt & 1) * 2], bh[nt >> 1][(nt & 1) * 2 + 1]);
                            MMA_BF16(accF[mt][nt], a[mt],
                                     bl[nt >> 1][(nt & 1) * 2], bl[nt >> 1][(nt & 1) * 2 + 1]);
                        }
                }
            }
        }
    }

    // ======== epilogue: g_matrix partials + row norms + bf16 xn ========
    __syncthreads();
    if (tid < 128) { sgm[tid] = 0.f; sns[tid] = 0.f; }
    __syncthreads();
    // column sums (mask invalid rows)
#pragma unroll
    for (int nt = 0; nt < 8; nt++) {
        float se = 0.f, so = 0.f;
#pragma unroll
        for (int mt = 0; mt < 2; mt++) {
            int r = wm * 32 + mt * 16 + (lane >> 2);
            if (row0 + r < NN)     { se += accF[mt][nt][0]; so += accF[mt][nt][1]; }
            if (row0 + r + 8 < NN) { se += accF[mt][nt][2]; so += accF[mt][nt][3]; }
        }
        int col = wn * 64 + nt * 8 + 2 * (lane & 3);
        atomicAdd(&sgm[col], se);
        atomicAdd(&sgm[col + 1], so);
    }
    // row sum-of-squares (half-row per warp; combine wn halves via shared)
#pragma unroll
    for (int mt = 0; mt < 2; mt++) {
        float s0 = 0.f, s1 = 0.f;
#pragma unroll
        for (int nt = 0; nt < 8; nt++) {
            s0 += accF[mt][nt][0] * accF[mt][nt][0] + accF[mt][nt][1] * accF[mt][nt][1];
            s1 += accF[mt][nt][2] * accF[mt][nt][2] + accF[mt][nt][3] * accF[mt][nt][3];
        }
        s0 += __shfl_xor_sync(0xffffffffu, s0, 1);
        s0 += __shfl_xor_sync(0xffffffffu, s0, 2);
        s1 += __shfl_xor_sync(0xffffffffu, s1, 1);
        s1 += __shfl_xor_sync(0xffffffffu, s1, 2);
        if ((lane & 3) == 0) {
            int r = wm * 32 + mt * 16 + (lane >> 2);
            atomicAdd(&sns[r], s0);
            atomicAdd(&sns[r + 8], s1);
        }
    }
    __syncthreads();
    if (tid < 32)
        ((float4*)(g_gmp + (size_t)(g * NBLK + blockIdx.x) * CC))[tid] =
            ((const float4*)sgm)[tid];
    // normalized bf16 store
#pragma unroll
    for (int mt = 0; mt < 2; mt++) {
        int r = wm * 32 + mt * 16 + (lane >> 2);
        float inv0 = 1.0f / fmaxf(sqrtf(sns[r]), 1e-12f);
        float inv1 = 1.0f / fmaxf(sqrtf(sns[r + 8]), 1e-12f);
        bool v0 = (row0 + r < NN), v1 = (row0 + r + 8 < NN);
#pragma unroll
        for (int nt = 0; nt < 8; nt++) {
            int col = wn * 64 + nt * 8 + 2 * (lane & 3);
            if (v0)
                *(uint32_t*)(g_xnb + ((size_t)g * NROWP + row0 + r) * CC + col) =
                    pk_bf16(accF[mt][nt][0] * inv0, accF[mt][nt][1] * inv0);
            if (v1)
                *(uint32_t*)(g_xnb + ((size_t)g * NROWP + row0 + r + 8) * CC + col) =
                    pk_bf16(accF[mt][nt][2] * inv1, accF[mt][nt][3] * inv1);
        }
    }
}

// ---------------- sim: bf16 mma, A tile resident, loop over column tiles ------
__global__ void __launch_bounds__(256, 2) k_sim() {
    __shared__ __nv_bfloat16 sA[2][128 * 64];  // two SW128 K=64 chunks (32KB)
    __shared__ __nv_bfloat16 sB[128 * 40];     // K=32 chunk, rows padded to 80B
    __shared__ float s_bnd[22];
    __shared__ unsigned s_part[8];

    int p = blockIdx.y;
    int i1 = cP1[p], i2 = cP2[p];
    int bx = blockIdx.x;
    bool diag = (i1 == i2);
    int byStart = diag ? bx : 0;

    int tid = threadIdx.x;
    int lane = tid & 31, wid = tid >> 5;
    int wm = wid & 3, wn = wid >> 2;
    if (tid < 22) s_bnd[tid] = c_bnd[tid];

    int row0 = bx * 128;
    const __nv_bfloat16* A = g_xnb + (size_t)i1 * NROWP * CC;
    const __nv_bfloat16* B = g_xnb + (size_t)i2 * NROWP * CC;
    uint32_t baseA = smem_u32(sA), baseB = smem_u32(sB);

#pragma unroll
    for (int it = 0; it < 8; it++) {
        int idx = it * 256 + tid;
        int kc = idx >> 10, rem = idx & 1023;
        int r = rem >> 3, q = rem & 7;
        uint32_t sw = (uint32_t)(kc * 16384) + SWZ128((uint32_t)(r * 128 + q * 16));
        *(uint4*)((uint8_t*)sA + sw) =
            *(const uint4*)(A + (size_t)(row0 + r) * CC + kc * 64 + q * 8);
    }

    unsigned total = 0;
    for (int by = byStart; by < 47; by++) {
        unsigned wgt = (diag && by > bx) ? 2u : 1u;
        int col0 = by * 128;
        float acc[2][8][4];
#pragma unroll
        for (int mt = 0; mt < 2; mt++)
#pragma unroll
            for (int nt = 0; nt < 8; nt++) {
                acc[mt][nt][0] = 0.f; acc[mt][nt][1] = 0.f;
                acc[mt][nt][2] = 0.f; acc[mt][nt][3] = 0.f;
            }
#pragma unroll
        for (int bc = 0; bc < 4; bc++) {
            __syncthreads();
#pragma unroll
            for (int it = 0; it < 2; it++) {
                int idx = it * 256 + tid;
                int r = idx >> 2, q = idx & 3;
                *(uint4*)((uint8_t*)sB + r * 80 + q * 16) =
                    *(const uint4*)(B + (size_t)(col0 + r) * CC + bc * 32 + q * 8);
            }
            __syncthreads();
#pragma unroll
            for (int ks = 0; ks < 2; ks++) {
                int kg = bc * 32 + ks * 16;
                int akc = kg >> 6, akb = (kg & 63) * 2;
                uint32_t a[2][4];
#pragma unroll
                for (int mt = 0; mt < 2; mt++) {
                    int r = wm * 32 + mt * 16 + (lane & 15);
                    uint32_t ad = baseA + akc * 16384 +
                        SWZ128((uint32_t)(r * 128 + akb + (lane >> 4) * 16));
                    LDSM4(a[mt][0], a[mt][1], a[mt][2], a[mt][3], ad);
                }
                uint32_t b[4][4];
#pragma unroll
                for (int np = 0; np < 4; np++) {
                    int r = wn * 64 + np * 16 + (lane & 7) + ((lane >> 4) << 3);
                    uint32_t bd = baseB + (uint32_t)(r * 80 + ks * 32 + ((lane >> 3) & 1) * 16);
                    LDSM4(b[np][0], b[np][1], b[np][2], b[np][3], bd);
                }
#pragma unroll
                for (int mt = 0; mt < 2; mt++)
#pragma unroll
                    for (int nt = 0; nt < 8; nt++)
                        MMA_BF16(acc[mt][nt], a[mt],
                                 b[nt >> 1][(nt & 1) * 2], b[nt >> 1][(nt & 1) * 2 + 1]);
            }
        }
        int sum = 0;
#pragma unroll
        for (int mt = 0; mt < 2; mt++)
#pragma unroll
            for (int nt = 0; nt < 8; nt++)
#pragma unroll
                for (int v = 0; v < 4; v++) {
                    float s = acc[mt][nt][v];
                    float t;
                    asm("tanh.approx.f32 %0, %1;" : "=f"(t) : "f"(s));
                    int idx = __float2int_rd(fmaf(t, 10.5f, 10.43f));
                    sum += idx + ((s >= s_bnd[idx + 1]) ? 1 : 0);
                }
        total += wgt * (unsigned)sum;
    }
#pragma unroll
    for (int o = 16; o; o >>= 1) total += __shfl_xor_sync(0xffffffffu, total, o);
    if (lane == 0) s_part[wid] = total;
    __syncthreads();
    if (tid == 0) {
        unsigned tot = 0;
#pragma unroll
        for (int i = 0; i < 8; i++) tot += s_part[i];
        atomicAdd(&g_cnt[p], tot);
    }
}

// ---------------- finalize: g_matrix reduce + sim values ----------------
__global__ void k_final(float* __restrict__ out) {
    int t = threadIdx.x;
    if (t < NGG * CC) {
        int g = t / CC, c = t - g * CC;
        float s = 0.f;
        for (int b = 0; b < NBLK; b++)
            s += g_gmp[(size_t)(g * NBLK + b) * CC + c];
        out[t] = s / (float)NN;
    }
    if (t < NPAIR) {
        double cnt = (double)g_cnt[t] - 10.0 * 192256.0;
        double v = -1.0 + 0.1 * cnt / ((double)NN * (double)NN);
        out[NGG * CC + cP1[t] * NGG + cP2[t]] = (float)v;
        out[NGG * CC + cP2[t] * NGG + cP1[t]] = (float)v;
    }
}

// ---------------- launch ----------------
extern "C" void kernel_launch(void* const* d_in, const int* in_sizes, int n_in,
                              void* d_out, int out_size) {
    const float* x   = (const float*)d_in[0];
    const int* ei    = (const int*)d_in[1];
    const float* ea  = (const float*)d_in[2];
    const float* gW  = (const float*)d_in[3];
    const float* gb  = (const float*)d_in[4];
    const float* Wsm = (const float*)d_in[5];
    float* out = (float*)d_out;

    k_setup<<<(NGG * NN * 4 + 255) / 256, 256>>>();
    k_deg<<<(NGG * EE + 255) / 256, 256>>>(ei, ea);
    k_dis<<<(NGG * NN * 4 + 255) / 256, 256>>>();
    k_scan<<<NGG, 256>>>();
    k_fill<<<(NGG * EE + 255) / 256, 256>>>(ei, ea);
    k_gather<<<(NGG * NN + 7) / 8, 256>>>(x);
    k_fused<<<dim3(NBLK, NGG), 256>>>(gW, gb, Wsm);
    k_sim<<<dim3(47, NPAIR), 256>>>();
    k_final<<<1, 768>>>(out);
}

// round 13
// speedup vs baseline: 6.8203x; 1.0917x over previous
#include <cuda_runtime.h>
#include <cuda_bf16.h>
#include <cstdint>

#define NGG 6
#define NN 6000
#define EE 96000
#define CC 128
#define NPAIR 21
#define NROWP 6016   // NN padded to multiple of 128
#define NBLK 47      // row tiles of 128 (fused + gmp)

// ---------------- device scratch ----------------
__device__ float g_deg4[(size_t)NGG * NN * 4];    // weighted deg per layer -> dis
__device__ int   g_cntn[NGG * NN];                // in-edge count per node
__device__ int   g_off[NGG * NN];                 // CSR start offsets
__device__ int   g_cur[NGG * NN];                 // fill cursors
__device__ int   g_csr[NGG * EE];                 // source node per CSR slot
__device__ float g_enorm[(size_t)NGG * EE * 4];   // per-edge per-layer norm coeff
__device__ __nv_bfloat16 g_Zb[(size_t)NGG * 4 * NN * CC]; // gathered x, bf16
__device__ float g_gmp[NGG * NBLK * CC];          // g_matrix per-block partials
__device__ __nv_bfloat16 g_xnb[(size_t)NGG * NROWP * CC]; // normalized rows, bf16
__device__ __nv_bfloat16 g_Wh[2 * 4 * 4 * 4096];  // weights hi (transposed chunks)
__device__ __nv_bfloat16 g_Wl[2 * 4 * 4 * 4096];  // weights lo
__device__ unsigned int g_cnt[NPAIR];

__constant__ int cP1[NPAIR] = {0,0,0,0,0,0, 1,1,1,1,1, 2,2,2,2, 3,3,3, 4,4, 5};
__constant__ int cP2[NPAIR] = {0,1,2,3,4,5, 1,2,3,4,5, 2,3,4,5, 3,4,5, 4,5, 5};

// s-space bin boundaries: bnd[k] = atanh(k/10.5 - 1), k=1..20; sentinels at ends
__constant__ float c_bnd[22] = {
    -3e38f,
    -1.49786614f, -1.12564590f, -0.89587974f, -0.72345949f, -0.58157540f,
    -0.45814537f, -0.34657359f, -0.24275391f, -0.14384104f, -0.04765509f,
     0.04765509f,  0.14384104f,  0.24275391f,  0.34657359f,  0.45814537f,
     0.58157540f,  0.72345949f,  0.89587974f,  1.12564590f,  1.49786614f,
     3e38f };

__device__ __forceinline__ uint32_t smem_u32(const void* p) {
    uint32_t a;
    asm("{ .reg .u64 t; cvta.to.shared.u64 t, %1; cvt.u32.u64 %0, t; }"
        : "=r"(a) : "l"(p));
    return a;
}
#define SWZ128(off) ((off) ^ (((off) >> 3) & 0x70))

__device__ __forceinline__ uint32_t pk_bf16(float a, float b) {
    __nv_bfloat162 t = __floats2bfloat162_rn(a, b);
    return *(uint32_t*)&t;
}
#define LDSM4(r0, r1, r2, r3, addr) \
    asm volatile("ldmatrix.sync.aligned.m8n8.x4.shared.b16 {%0,%1,%2,%3}, [%4];" \
        : "=r"(r0), "=r"(r1), "=r"(r2), "=r"(r3) : "r"(addr))
#define MMA_BF16(acc, a, b0, b1) \
    asm volatile("mma.sync.aligned.m16n8k16.row.col.f32.bf16.bf16.f32 " \
        "{%0,%1,%2,%3}, {%4,%5,%6,%7}, {%8,%9}, {%0,%1,%2,%3};" \
        : "+f"((acc)[0]), "+f"((acc)[1]), "+f"((acc)[2]), "+f"((acc)[3]) \
        : "r"((a)[0]), "r"((a)[1]), "r"((a)[2]), "r"((a)[3]), "r"(b0), "r"(b1))

// ---------------- setup ----------------
__global__ void k_setup() {
    int i = blockIdx.x * blockDim.x + threadIdx.x;
    if (i < NGG * NN * 4) g_deg4[i] = 1.0f;     // self-loop weight
    if (i < NGG * NN) g_cntn[i] = 0;
    if (i < NPAIR) g_cnt[i] = 0u;
    if (i < NGG * 16 * CC) {                    // zero 16 pad rows
        int g = i / (16 * CC), rem = i - g * (16 * CC);
        g_xnb[((size_t)g * NROWP + NN) * CC + rem] = __float2bfloat16(0.f);
    }
}

// ---------------- one-shot weight hi/lo split, transposed chunk layout --------
// index i = ((mat*4 + layer)*4 + chunk)*4096 + n*32 + k ; source [layer][k][n]
__global__ void k_wconv(const float* __restrict__ gW, const float* __restrict__ Wsm) {
    int i = blockIdx.x * 256 + threadIdx.x;
    if (i >= 2 * 4 * 4 * 4096) return;
    int mat = i >> 16;
    int layer = (i >> 14) & 3;
    int chunk = (i >> 12) & 3;
    int n = (i >> 5) & 127;
    int k = i & 31;
    const float* src = mat ? Wsm : gW;
    float wv = src[((size_t)layer * 128 + chunk * 32 + k) * 128 + n];
    __nv_bfloat16 hb = __float2bfloat16(wv);
    float lres = wv - __bfloat162float(hb);
    g_Wh[i] = hb;
    g_Wl[i] = __float2bfloat16(lres);
}

// ---------------- per-node in-degree count + weighted degree ----------------
__global__ void k_deg(const int* __restrict__ ei, const float* __restrict__ ea) {
    int i = blockIdx.x * blockDim.x + threadIdx.x;
    if (i >= NGG * EE) return;
    int g = i / EE, e = i - g * EE;
    int c = ei[(size_t)g * 2 * EE + EE + e];
    const float* w = ea + ((size_t)g * EE + e) * 6;
    float2 wa = *(const float2*)(w + 2);
    float2 wb = *(const float2*)(w + 4);
    asm volatile("red.global.add.v4.f32 [%0], {%1, %2, %3, %4};"
                 :: "l"(&g_deg4[(size_t)(g * NN + c) * 4]),
                    "f"(wa.x), "f"(wa.y), "f"(wb.x), "f"(wb.y) : "memory");
    atomicAdd(&g_cntn[g * NN + c], 1);
}

__global__ void k_dis() {
    int i = blockIdx.x * blockDim.x + threadIdx.x;
    if (i < NGG * NN * 4) g_deg4[i] = rsqrtf(g_deg4[i]);
}

// ---------------- CSR offsets ----------------
__global__ void __launch_bounds__(256) k_scan() {
    __shared__ int ps[256];
    int g = blockIdx.x, t = threadIdx.x;
    const int PT = 24;
    int loc[PT];
    int s = 0;
    if (t < 250) {
        int base = g * NN + t * PT;
#pragma unroll
        for (int i = 0; i < PT; i++) { loc[i] = g_cntn[base + i]; s += loc[i]; }
    }
    ps[t] = s;
    __syncthreads();
    for (int o = 1; o < 256; o <<= 1) {
        int v = (t >= o) ? ps[t - o] : 0;
        __syncthreads();
        ps[t] += v;
        __syncthreads();
    }
    if (t < 250) {
        int run = ps[t] - s;
        int base = g * NN + t * PT;
#pragma unroll
        for (int i = 0; i < PT; i++) {
            g_off[base + i] = run;
            g_cur[base + i] = run;
            run += loc[i];
        }
    }
}

// ---------------- CSR fill + per-edge norm coefficients ----------------
__global__ void k_fill(const int* __restrict__ ei, const float* __restrict__ ea) {
    int i = blockIdx.x * blockDim.x + threadIdx.x;
    if (i >= NGG * EE) return;
    int g = i / EE, e = i - g * EE;
    int r = ei[(size_t)g * 2 * EE + e];
    int c = ei[(size_t)g * 2 * EE + EE + e];
    int pos = atomicAdd(&g_cur[g * NN + c], 1);
    g_csr[g * EE + pos] = r;
    const float* w = ea + ((size_t)g * EE + e) * 6;
    float2 wa = *(const float2*)(w + 2);
    float2 wb = *(const float2*)(w + 4);
    float4 dr = *(const float4*)&g_deg4[(size_t)(g * NN + r) * 4];
    float4 dc = *(const float4*)&g_deg4[(size_t)(g * NN + c) * 4];
    float4 nm;
    nm.x = dr.x * wa.x * dc.x;
    nm.y = dr.y * wa.y * dc.y;
    nm.z = dr.z * wb.x * dc.z;
    nm.w = dr.w * wb.y * dc.w;
    *(float4*)&g_enorm[((size_t)g * EE + pos) * 4] = nm;
}

// ---------------- gather raw x -> bf16 Z ----------------
__global__ void __launch_bounds__(256) k_gather(const float* __restrict__ x) {
    int w = (blockIdx.x * 256 + threadIdx.x) >> 5;
    int lane = threadIdx.x & 31;
    if (w >= NGG * NN) return;
    int g = w / NN, c = w - g * NN;
    const float4* Xg = (const float4*)(x + (size_t)g * NN * CC);

    float4 xc = Xg[(size_t)c * 32 + lane];
    float4 d4 = *(const float4*)&g_deg4[(size_t)(g * NN + c) * 4];
    float sc[4] = {d4.x * d4.x, d4.y * d4.y, d4.z * d4.z, d4.w * d4.w};
    float4 acc[4];
#pragma unroll
    for (int l = 0; l < 4; l++)
        acc[l] = make_float4(xc.x * sc[l], xc.y * sc[l], xc.z * sc[l], xc.w * sc[l]);
    int start = g_off[g * NN + c];
    int cnt = g_cntn[g * NN + c];
    const int* csr = g_csr + (size_t)g * EE;
    const float4* en = (const float4*)(g_enorm + (size_t)g * EE * 4);
#pragma unroll 4
    for (int j = 0; j < cnt; j++) {
        int r = __ldg(&csr[start + j]);
        float4 nm = __ldg(&en[start + j]);
        float4 h = Xg[(size_t)r * 32 + lane];
        acc[0].x += nm.x * h.x; acc[0].y += nm.x * h.y; acc[0].z += nm.x * h.z; acc[0].w += nm.x * h.w;
        acc[1].x += nm.y * h.x; acc[1].y += nm.y * h.y; acc[1].z += nm.y * h.z; acc[1].w += nm.y * h.w;
        acc[2].x += nm.z * h.x; acc[2].y += nm.z * h.y; acc[2].z += nm.z * h.z; acc[2].w += nm.z * h.w;
        acc[3].x += nm.w * h.x; acc[3].y += nm.w * h.y; acc[3].z += nm.w * h.z; acc[3].w += nm.w * h.w;
    }
#pragma unroll
    for (int l = 0; l < 4; l++) {
        uint2 pk;
        pk.x = pk_bf16(acc[l].x, acc[l].y);
        pk.y = pk_bf16(acc[l].z, acc[l].w);
        ((uint2*)(g_Zb + ((size_t)(g * 4 + l) * NN + c) * CC))[lane] = pk;
    }
}

// ---------------- fused tensor-core feats + g_matrix + norm ----------------
__global__ void __launch_bounds__(256) k_fused(const float* __restrict__ gb) {
    __shared__ uint8_t smem[36864];
    uint8_t* sZ  = smem;              // 16KB [128 rows][128B] SW128 bf16 (also sO)
    uint8_t* sBh = smem + 16384;      // 10KB [128 n][80B] bf16 hi, K=32 chunk
    uint8_t* sBl = smem + 26624;      // 10KB lo
    __shared__ float sgm[128];
    __shared__ float sns[128];

    int g = blockIdx.y;
    int row0 = blockIdx.x * 128;
    int tid = threadIdx.x;
    int lane = tid & 31, wid = tid >> 5;
    int wm = wid & 3, wn = wid >> 2;
    uint32_t baseZ = smem_u32(sZ), baseBh = smem_u32(sBh), baseBl = smem_u32(sBl);

    float accF[2][8][4];
#pragma unroll
    for (int mt = 0; mt < 2; mt++)
#pragma unroll
        for (int nt = 0; nt < 8; nt++) {
            accF[mt][nt][0]=0.f; accF[mt][nt][1]=0.f; accF[mt][nt][2]=0.f; accF[mt][nt][3]=0.f;
        }

    for (int l = 0; l < 4; l++) {
        float accO[2][8][4];
#pragma unroll
        for (int mt = 0; mt < 2; mt++)
#pragma unroll
            for (int nt = 0; nt < 8; nt++) {
                accO[mt][nt][0]=0.f; accO[mt][nt][1]=0.f; accO[mt][nt][2]=0.f; accO[mt][nt][3]=0.f;
            }
        const uint4* Zb4 = (const uint4*)(g_Zb + (size_t)(g * 4 + l) * NN * CC);

        // ======== GEMM1 ========
        for (int kc64 = 0; kc64 < 2; kc64++) {
            __syncthreads();
#pragma unroll
            for (int it = 0; it < 4; it++) {
                int idx = it * 256 + tid;           // 1024 uint4 slots
                int r = idx >> 3, q = idx & 7;
                uint4 v = make_uint4(0u, 0u, 0u, 0u);
                if (row0 + r < NN) v = Zb4[(size_t)(row0 + r) * 16 + kc64 * 8 + q];
                *(uint4*)(sZ + SWZ128((uint32_t)(r * 128 + q * 16))) = v;
            }
            for (int kc32 = 0; kc32 < 2; kc32++) {
                __syncthreads();
                int chunk = kc64 * 2 + kc32;
                const uint4* srcH = (const uint4*)(g_Wh + (size_t)((0 * 4 + l) * 4 + chunk) * 4096);
                const uint4* srcL = (const uint4*)(g_Wl + (size_t)((0 * 4 + l) * 4 + chunk) * 4096);
#pragma unroll
                for (int it = 0; it < 2; it++) {
                    int idx = it * 256 + tid;       // 512 uint4
                    int n = idx >> 2, q = idx & 3;
                    *(uint4*)(sBh + n * 80 + q * 16) = srcH[idx];
                    *(uint4*)(sBl + n * 80 + q * 16) = srcL[idx];
                }
                __syncthreads();
#pragma unroll
                for (int ks = 0; ks < 2; ks++) {
                    int kin = kc32 * 32 + ks * 16;  // within k64 chunk
                    uint32_t a[2][4];
#pragma unroll
                    for (int mt = 0; mt < 2; mt++) {
                        int r = wm * 32 + mt * 16 + (lane & 15);
                        uint32_t ad = baseZ + SWZ128((uint32_t)(r * 128 + kin * 2 + (lane >> 4) * 16));
                        LDSM4(a[mt][0], a[mt][1], a[mt][2], a[mt][3], ad);
                    }
                    uint32_t bh[4][4], bl[4][4];
#pragma unroll
                    for (int np = 0; np < 4; np++) {
                        int r = wn * 64 + np * 16 + (lane & 7) + ((lane >> 4) << 3);
                        uint32_t off = (uint32_t)(r * 80 + ks * 32 + ((lane >> 3) & 1) * 16);
                        LDSM4(bh[np][0], bh[np][1], bh[np][2], bh[np][3], baseBh + off);
                        LDSM4(bl[np][0], bl[np][1], bl[np][2], bl[np][3], baseBl + off);
                    }
#pragma unroll
                    for (int mt = 0; mt < 2; mt++)
#pragma unroll
                        for (int nt = 0; nt < 8; nt++) {
                            MMA_BF16(accO[mt][nt], a[mt],
                                     bh[nt >> 1][(nt & 1) * 2], bh[nt >> 1][(nt & 1) * 2 + 1]);
                            MMA_BF16(accO[mt][nt], a[mt],
                                     bl[nt >> 1][(nt & 1) * 2], bl[nt >> 1][(nt & 1) * 2 + 1]);
                        }
                }
            }
        }

        // ======== GEMM2 ========
        for (int kc64 = 0; kc64 < 2; kc64++) {
            __syncthreads();                        // prior sZ/sO reads done
            if (wn == kc64) {
                // repack relu(accO + bias) -> sO rows (bf16, SW128)
#pragma unroll
                for (int nt = 0; nt < 8; nt++) {
                    int colb = wn * 64 + nt * 8 + 2 * (lane & 3);
                    float2 bb = *(const float2*)&gb[l * CC + colb];
                    int kloc = nt * 8 + 2 * (lane & 3);
#pragma unroll
                    for (int mt = 0; mt < 2; mt++) {
                        int r = wm * 32 + mt * 16 + (lane >> 2);
                        uint32_t p0 = pk_bf16(fmaxf(accO[mt][nt][0] + bb.x, 0.f),
                                              fmaxf(accO[mt][nt][1] + bb.y, 0.f));
                        uint32_t p1 = pk_bf16(fmaxf(accO[mt][nt][2] + bb.x, 0.f),
                                              fmaxf(accO[mt][nt][3] + bb.y, 0.f));
                        *(uint32_t*)(sZ + SWZ128((uint32_t)(r * 128 + kloc * 2))) = p0;
                        *(uint32_t*)(sZ + SWZ128((uint32_t)((r + 8) * 128 + kloc * 2))) = p1;
                    }
                }
            }
            for (int kc32 = 0; kc32 < 2; kc32++) {
                __syncthreads();
                int chunk = kc64 * 2 + kc32;
                const uint4* srcH = (const uint4*)(g_Wh + (size_t)((1 * 4 + l) * 4 + chunk) * 4096);
                const uint4* srcL = (const uint4*)(g_Wl + (size_t)((1 * 4 + l) * 4 + chunk) * 4096);
#pragma unroll
                for (int it = 0; it < 2; it++) {
                    int idx = it * 256 + tid;
                    int n = idx >> 2, q = idx & 3;
                    *(uint4*)(sBh + n * 80 + q * 16) = srcH[idx];
                    *(uint4*)(sBl + n * 80 + q * 16) = srcL[idx];
                }
                __syncthreads();
#pragma unroll
                for (int ks = 0; ks < 2; ks++) {
                    int kin = kc32 * 32 + ks * 16;
                    uint32_t a[2][4];
#pragma unroll
                    for (int mt = 0; mt < 2; mt++) {
                        int r = wm * 32 + mt * 16 + (lane & 15);
                        uint32_t ad = baseZ + SWZ128((uint32_t)(r * 128 + kin * 2 + (lane >> 4) * 16));
                        LDSM4(a[mt][0], a[mt][1], a[mt][2], a[mt][3], ad);
                    }
                    uint32_t bh[4][4], bl[4][4];
#pragma unroll
                    for (int np = 0; np < 4; np++) {
                        int r = wn * 64 + np * 16 + (lane & 7) + ((lane >> 4) << 3);
                        uint32_t off = (uint32_t)(r * 80 + ks * 32 + ((lane >> 3) & 1) * 16);
                        LDSM4(bh[np][0], bh[np][1], bh[np][2], bh[np][3], baseBh + off);
                        LDSM4(bl[np][0], bl[np][1], bl[np][2], bl[np][3], baseBl + off);
                    }
#pragma unroll
                    for (int mt = 0; mt < 2; mt++)
#pragma unroll
                        for (int nt = 0; nt < 8; nt++) {
                            MMA_BF16(accF[mt][nt], a[mt],
                                     bh[nt >> 1][(nt & 1) * 2], bh[nt >> 1][(nt & 1) * 2 + 1]);
                            MMA_BF16(accF[mt][nt], a[mt],
                                     bl[nt >> 1][(nt & 1) * 2], bl[nt >> 1][(nt & 1) * 2 + 1]);
                        }
                }
            }
        }
    }

    // ======== epilogue: g_matrix partials + row norms + bf16 xn ========
    __syncthreads();
    if (tid < 128) { sgm[tid] = 0.f; sns[tid] = 0.f; }
    __syncthreads();
#pragma unroll
    for (int nt = 0; nt < 8; nt++) {
        float se = 0.f, so = 0.f;
#pragma unroll
        for (int mt = 0; mt < 2; mt++) {
            int r = wm * 32 + mt * 16 + (lane >> 2);
            if (row0 + r < NN)     { se += accF[mt][nt][0]; so += accF[mt][nt][1]; }
            if (row0 + r + 8 < NN) { se += accF[mt][nt][2]; so += accF[mt][nt][3]; }
        }
        int col = wn * 64 + nt * 8 + 2 * (lane & 3);
        atomicAdd(&sgm[col], se);
        atomicAdd(&sgm[col + 1], so);
    }
#pragma unroll
    for (int mt = 0; mt < 2; mt++) {
        float s0 = 0.f, s1 = 0.f;
#pragma unroll
        for (int nt = 0; nt < 8; nt++) {
            s0 += accF[mt][nt][0] * accF[mt][nt][0] + accF[mt][nt][1] * accF[mt][nt][1];
            s1 += accF[mt][nt][2] * accF[mt][nt][2] + accF[mt][nt][3] * accF[mt][nt][3];
        }
        s0 += __shfl_xor_sync(0xffffffffu, s0, 1);
        s0 += __shfl_xor_sync(0xffffffffu, s0, 2);
        s1 += __shfl_xor_sync(0xffffffffu, s1, 1);
        s1 += __shfl_xor_sync(0xffffffffu, s1, 2);
        if ((lane & 3) == 0) {
            int r = wm * 32 + mt * 16 + (lane >> 2);
            atomicAdd(&sns[r], s0);
            atomicAdd(&sns[r + 8], s1);
        }
    }
    __syncthreads();
    if (tid < 32)
        ((float4*)(g_gmp + (size_t)(g * NBLK + blockIdx.x) * CC))[tid] =
            ((const float4*)sgm)[tid];
#pragma unroll
    for (int mt = 0; mt < 2; mt++) {
        int r = wm * 32 + mt * 16 + (lane >> 2);
        float inv0 = 1.0f / fmaxf(sqrtf(sns[r]), 1e-12f);
        float inv1 = 1.0f / fmaxf(sqrtf(sns[r + 8]), 1e-12f);
        bool v0 = (row0 + r < NN), v1 = (row0 + r + 8 < NN);
#pragma unroll
        for (int nt = 0; nt < 8; nt++) {
            int col = wn * 64 + nt * 8 + 2 * (lane & 3);
            if (v0)
                *(uint32_t*)(g_xnb + ((size_t)g * NROWP + row0 + r) * CC + col) =
                    pk_bf16(accF[mt][nt][0] * inv0, accF[mt][nt][1] * inv0);
            if (v1)
                *(uint32_t*)(g_xnb + ((size_t)g * NROWP + row0 + r + 8) * CC + col) =
                    pk_bf16(accF[mt][nt][2] * inv1, accF[mt][nt][3] * inv1);
        }
    }
}

// ---------------- sim: bf16 mma, diag pairs folded for balance ----------------
// Off-diag pair: block bx handles row bx, all 47 col tiles.
// Diag pair: blocks 0..23 active; block bx handles rows {bx, 46-bx} (48 tiles).
__global__ void __launch_bounds__(256, 2) k_sim() {
    __shared__ __nv_bfloat16 sA[2][128 * 64];  // two SW128 K=64 chunks (32KB)
    __shared__ __nv_bfloat16 sB[128 * 40];     // K=32 chunk, rows padded to 80B
    __shared__ float s_bnd[22];
    __shared__ unsigned s_part[8];

    int p = blockIdx.y;
    int i1 = cP1[p], i2 = cP2[p];
    int bx = blockIdx.x;
    bool diag = (i1 == i2);
    int rows[2];
    int nrows = 1;
    rows[0] = bx;
    if (diag) {
        if (bx >= 24) return;
        rows[1] = 46 - bx;
        nrows = (bx == 23) ? 1 : 2;
    }

    int tid = threadIdx.x;
    int lane = tid & 31, wid = tid >> 5;
    int wm = wid & 3, wn = wid >> 2;
    if (tid < 22) s_bnd[tid] = c_bnd[tid];

    const __nv_bfloat16* A = g_xnb + (size_t)i1 * NROWP * CC;
    const __nv_bfloat16* B = g_xnb + (size_t)i2 * NROWP * CC;
    uint32_t baseA = smem_u32(sA), baseB = smem_u32(sB);

    unsigned total = 0;
    for (int ri = 0; ri < nrows; ri++) {
        int rb = rows[ri];
        int row0 = rb * 128;
        if (ri) __syncthreads();               // prior row's mma reads of sA done
#pragma unroll
        for (int it = 0; it < 8; it++) {
            int idx = it * 256 + tid;
            int kc = idx >> 10, rem = idx & 1023;
            int r = rem >> 3, q = rem & 7;
            uint32_t sw = (uint32_t)(kc * 16384) + SWZ128((uint32_t)(r * 128 + q * 16));
            *(uint4*)((uint8_t*)sA + sw) =
                *(const uint4*)(A + (size_t)(row0 + r) * CC + kc * 64 + q * 8);
        }
        int byStart = diag ? rb : 0;
        for (int by = byStart; by < 47; by++) {
            unsigned wgt = (diag && by > rb) ? 2u : 1u;
            int col0 = by * 128;
            float acc[2][8][4];
#pragma unroll
            for (int mt = 0; mt < 2; mt++)
#pragma unroll
                for (int nt = 0; nt < 8; nt++) {
                    acc[mt][nt][0] = 0.f; acc[mt][nt][1] = 0.f;
                    acc[mt][nt][2] = 0.f; acc[mt][nt][3] = 0.f;
                }
#pragma unroll
            for (int bc = 0; bc < 4; bc++) {
                __syncthreads();
#pragma unroll
                for (int it = 0; it < 2; it++) {
                    int idx = it * 256 + tid;
                    int r = idx >> 2, q = idx & 3;
                    *(uint4*)((uint8_t*)sB + r * 80 + q * 16) =
                        *(const uint4*)(B + (size_t)(col0 + r) * CC + bc * 32 + q * 8);
                }
                __syncthreads();
#pragma unroll
                for (int ks = 0; ks < 2; ks++) {
                    int kg = bc * 32 + ks * 16;
                    int akc = kg >> 6, akb = (kg & 63) * 2;
                    uint32_t a[2][4];
#pragma unroll
                    for (int mt = 0; mt < 2; mt++) {
                        int r = wm * 32 + mt * 16 + (lane & 15);
                        uint32_t ad = baseA + akc * 16384 +
                            SWZ128((uint32_t)(r * 128 + akb + (lane >> 4) * 16));
                        LDSM4(a[mt][0], a[mt][1], a[mt][2], a[mt][3], ad);
                    }
                    uint32_t b[4][4];
#pragma unroll
                    for (int np = 0; np < 4; np++) {
                        int r = wn * 64 + np * 16 + (lane & 7) + ((lane >> 4) << 3);
                        uint32_t bd = baseB + (uint32_t)(r * 80 + ks * 32 + ((lane >> 3) & 1) * 16);
                        LDSM4(b[np][0], b[np][1], b[np][2], b[np][3], bd);
                    }
#pragma unroll
                    for (int mt = 0; mt < 2; mt++)
#pragma unroll
                        for (int nt = 0; nt < 8; nt++)
                            MMA_BF16(acc[mt][nt], a[mt],
                                     b[nt >> 1][(nt & 1) * 2], b[nt >> 1][(nt & 1) * 2 + 1]);
                }
            }
            // bin accumulators (exact w.r.t. fp32 s; see R8 margin proof)
            int sum = 0;
#pragma unroll
            for (int mt = 0; mt < 2; mt++)
#pragma unroll
                for (int nt = 0; nt < 8; nt++)
#pragma unroll
                    for (int v = 0; v < 4; v++) {
                        float s = acc[mt][nt][v];
                        float t;
                        asm("tanh.approx.f32 %0, %1;" : "=f"(t) : "f"(s));
                        int idx = __float2int_rd(fmaf(t, 10.5f, 10.43f));
                        sum += idx + ((s >= s_bnd[idx + 1]) ? 1 : 0);
                    }
            total += wgt * (unsigned)sum;
        }
    }
#pragma unroll
    for (int o = 16; o; o >>= 1) total += __shfl_xor_sync(0xffffffffu, total, o);
    if (lane == 0) s_part[wid] = total;
    __syncthreads();
    if (tid == 0) {
        unsigned tot = 0;
#pragma unroll
        for (int i = 0; i < 8; i++) tot += s_part[i];
        atomicAdd(&g_cnt[p], tot);
    }
}

// ---------------- finalize: g_matrix reduce + sim values ----------------
__global__ void k_final(float* __restrict__ out) {
    int t = threadIdx.x;
    if (t < NGG * CC) {
        int g = t / CC, c = t - g * CC;
        float s = 0.f;
        for (int b = 0; b < NBLK; b++)
            s += g_gmp[(size_t)(g * NBLK + b) * CC + c];
        out[t] = s / (float)NN;
    }
    if (t < NPAIR) {
        double cnt = (double)g_cnt[t] - 10.0 * 192256.0;
        double v = -1.0 + 0.1 * cnt / ((double)NN * (double)NN);
        out[NGG * CC + cP1[t] * NGG + cP2[t]] = (float)v;
        out[NGG * CC + cP2[t] * NGG + cP1[t]] = (float)v;
    }
}

// ---------------- launch ----------------
extern "C" void kernel_launch(void* const* d_in, const int* in_sizes, int n_in,
                              void* d_out, int out_size) {
    const float* x   = (const float*)d_in[0];
    const int* ei    = (const int*)d_in[1];
    const float* ea  = (const float*)d_in[2];
    const float* gW  = (const float*)d_in[3];
    const float* gb  = (const float*)d_in[4];
    const float* Wsm = (const float*)d_in[5];
    float* out = (float*)d_out;

    k_setup<<<(NGG * NN * 4 + 255) / 256, 256>>>();
    k_wconv<<<512, 256>>>(gW, Wsm);
    k_deg<<<(NGG * EE + 255) / 256, 256>>>(ei, ea);
    k_dis<<<(NGG * NN * 4 + 255) / 256, 256>>>();
    k_scan<<<NGG, 256>>>();
    k_fill<<<(NGG * EE + 255) / 256, 256>>>(ei, ea);
    k_gather<<<(NGG * NN + 7) / 8, 256>>>(x);
    k_fused<<<dim3(NBLK, NGG), 256>>>(gb);
    k_sim<<<dim3(47, NPAIR), 256>>>();
    k_final<<<1, 768>>>(out);
}